// round 8
// baseline (speedup 1.0000x reference)
#include <cuda_runtime.h>

#define Bq 2
#define Nq 2048
#define Hq 16
#define DHq 64
#define Dq 1024
#define HDq (Hq * DHq)   // 1024
#define Mq (Bq * Nq)     // 4096

// tf32 hi/lo planes
__device__ float g_xh[Mq * Dq],  g_xl[Mq * Dq];
__device__ float g_wsh[4 * Dq * Dq], g_wsl[4 * Dq * Dq];   // q,k,v,o TRANSPOSED [n][k]
__device__ float g_qh[Mq * HDq], g_ql[Mq * HDq];
__device__ float g_kh[Mq * HDq], g_kl[Mq * HDq];
__device__ float g_vh[Mq * HDq], g_vl[Mq * HDq];
__device__ float g_aoh[Mq * HDq], g_aol[Mq * HDq];

// ---------------------------------------------------------------------------
// helpers
// ---------------------------------------------------------------------------
__device__ __forceinline__ void split_tf32(float x, float& hi, float& lo)
{
    unsigned h;
    asm("cvt.rna.tf32.f32 %0, %1;" : "=r"(h) : "f"(x));
    hi = __uint_as_float(h);
    float r = x - hi;
    unsigned l;
    asm("cvt.rna.tf32.f32 %0, %1;" : "=r"(l) : "f"(r));
    lo = __uint_as_float(l);
}

__device__ __forceinline__ float ex2(float x)
{
    float r;
    asm("ex2.approx.f32 %0, %1;" : "=f"(r) : "f"(x));
    return r;
}

#define MMA_TF32(d, a, b)                                                     \
    asm volatile("mma.sync.aligned.m16n8k8.row.col.f32.tf32.tf32.f32 "        \
                 "{%0,%1,%2,%3}, {%4,%5,%6,%7}, {%8,%9}, {%0,%1,%2,%3};"      \
                 : "+f"(d[0]), "+f"(d[1]), "+f"(d[2]), "+f"(d[3])             \
                 : "r"(a[0]), "r"(a[1]), "r"(a[2]), "r"(a[3]),                \
                   "r"(b[0]), "r"(b[1]))

#define LDSM_X4(r0, r1, r2, r3, addr)                                         \
    asm volatile("ldmatrix.sync.aligned.m8n8.x4.shared.b16 {%0,%1,%2,%3}, [%4];" \
                 : "=r"(r0), "=r"(r1), "=r"(r2), "=r"(r3) : "r"(addr))

#define CP_A16(dst, src) \
    asm volatile("cp.async.cg.shared.global [%0], [%1], 16;" :: "r"(dst), "l"(src))
#define CP_COMMIT() asm volatile("cp.async.commit_group;")
#define CP_WAIT0()  asm volatile("cp.async.wait_group 0;" ::: "memory")
#define CP_WAIT1()  asm volatile("cp.async.wait_group 1;" ::: "memory")

// ---------------------------------------------------------------------------
// split kernels
// ---------------------------------------------------------------------------
__global__ __launch_bounds__(256) void split_x(const float* __restrict__ in)
{
    int i = blockIdx.x * 256 + threadIdx.x;          // over float4
    float4 v = ((const float4*)in)[i];
    float4 h4, l4;
    split_tf32(v.x, h4.x, l4.x); split_tf32(v.y, h4.y, l4.y);
    split_tf32(v.z, h4.z, l4.z); split_tf32(v.w, h4.w, l4.w);
    ((float4*)g_xh)[i] = h4;
    ((float4*)g_xl)[i] = l4;
}

// transpose + split: Wt_h/l[n][k] = split(W[k][n])
__global__ __launch_bounds__(256) void split_wT(const float* __restrict__ W, int w)
{
    int n  = blockIdx.x * 32 + (threadIdx.x & 31);
    int k0 = blockIdx.y * 64 + (threadIdx.x >> 5) * 8;
    float hb[8], lb[8];
#pragma unroll
    for (int j = 0; j < 8; j++) {
        float v = W[(size_t)(k0 + j) * Dq + n];
        split_tf32(v, hb[j], lb[j]);
    }
    float* dh = g_wsh + (size_t)w * Dq * Dq + (size_t)n * Dq + k0;
    float* dl = g_wsl + (size_t)w * Dq * Dq + (size_t)n * Dq + k0;
#pragma unroll
    for (int j = 0; j < 8; j += 4) {
        *(float4*)(dh + j) = make_float4(hb[j], hb[j + 1], hb[j + 2], hb[j + 3]);
        *(float4*)(dl + j) = make_float4(lb[j], lb[j + 1], lb[j + 2], lb[j + 3]);
    }
}

// ---------------------------------------------------------------------------
// Pipelined 3xTF32 GEMM with ldmatrix fragment loads + dependency-free MMA order.
// BM=128 BN=128 BK=16, 2-stage cp.async, 256 thr.
// ---------------------------------------------------------------------------
#define BKp 16
#define TSTR 20
#define PLANE_F (128 * TSTR)                    // 2560 floats per plane
#define STAGE_F (4 * PLANE_F)                   // Ah Al Wh Wl
#define GEMMP_SMEM (2 * STAGE_F * 4)            // 81920 B

__device__ __forceinline__ void gemm_pipe(const float* __restrict__ Ahg,
                                          const float* __restrict__ Alg,
                                          const float* __restrict__ Whg,   // [n][k]
                                          const float* __restrict__ Wlg,
                                          float* __restrict__ Ch,
                                          float* __restrict__ Cl,
                                          const float* __restrict__ bias,
                                          int rowBlk, int colBlk)
{
    extern __shared__ float sm[];
    const unsigned smb = (unsigned)__cvta_generic_to_shared(sm);
    const int tid = threadIdx.x;
    const int wid = tid >> 5, lane = tid & 31;
    const int g = lane >> 2, t = lane & 3;
    const int wm = (wid & 3) * 32, wn = (wid >> 2) * 64;

    const size_t arow = (size_t)rowBlk * 128;
    const int ccol = colBlk * 128;

    const int quad = lane >> 3, lrow = lane & 7;
    const unsigned offA = (unsigned)(((wm + (quad & 1) * 8 + lrow) * TSTR + (quad >> 1) * 4) * 4);
    const unsigned offW = (unsigned)(((wn + (quad >> 1) * 8 + lrow) * TSTR + (quad & 1) * 4) * 4);

    float acc[2][8][4] = {};

#define PREFETCH(st, k0)                                                          \
    {                                                                             \
        unsigned base = smb + (st) * (STAGE_F * 4);                               \
        _Pragma("unroll")                                                         \
        for (int i_ = 0; i_ < 2; i_++) {                                          \
            int idx = tid * 2 + i_;                                               \
            int r = idx >> 2, c = (idx & 3) * 4;                                  \
            CP_A16(base + (unsigned)(r * TSTR + c) * 4,                           \
                   Ahg + (arow + r) * Dq + (k0) + c);                             \
            CP_A16(base + (unsigned)(PLANE_F + r * TSTR + c) * 4,                 \
                   Alg + (arow + r) * Dq + (k0) + c);                             \
            CP_A16(base + (unsigned)(2 * PLANE_F + r * TSTR + c) * 4,             \
                   Whg + (size_t)(ccol + r) * Dq + (k0) + c);                     \
            CP_A16(base + (unsigned)(3 * PLANE_F + r * TSTR + c) * 4,             \
                   Wlg + (size_t)(ccol + r) * Dq + (k0) + c);                     \
        }                                                                         \
    }

    PREFETCH(0, 0);
    CP_COMMIT();

    const int nch = Dq / BKp;   // 64
    for (int chn = 0; chn < nch; chn++) {
        if (chn + 1 < nch) {
            PREFETCH((chn + 1) & 1, (chn + 1) * BKp);
            CP_COMMIT();
            CP_WAIT1();
        } else {
            CP_WAIT0();
        }
        __syncthreads();

        const unsigned stg = smb + (chn & 1) * (STAGE_F * 4);

#pragma unroll
        for (int kk = 0; kk < BKp; kk += 8) {
            unsigned ah[2][4], al[2][4];
#pragma unroll
            for (int mt = 0; mt < 2; mt++) {
                unsigned ao = stg + offA + (unsigned)((mt * 16 * TSTR + kk) * 4);
                LDSM_X4(ah[mt][0], ah[mt][1], ah[mt][2], ah[mt][3], ao);
                LDSM_X4(al[mt][0], al[mt][1], al[mt][2], al[mt][3],
                        ao + PLANE_F * 4);
            }
            unsigned bh[4][4], bl[4][4];
#pragma unroll
            for (int np = 0; np < 4; np++) {
                unsigned wo = stg + 2 * PLANE_F * 4 + offW +
                              (unsigned)((np * 16 * TSTR + kk) * 4);
                LDSM_X4(bh[np][0], bh[np][1], bh[np][2], bh[np][3], wo);
                LDSM_X4(bl[np][0], bl[np][1], bl[np][2], bl[np][3],
                        wo + PLANE_F * 4);
            }
            // pass 1: ah*bh over all 16 independent tiles
#pragma unroll
            for (int mt = 0; mt < 2; mt++)
#pragma unroll
                for (int nt = 0; nt < 8; nt++)
                    MMA_TF32(acc[mt][nt], ah[mt], (&bh[nt >> 1][(nt & 1) * 2]));
            // pass 2: al*bh
#pragma unroll
            for (int mt = 0; mt < 2; mt++)
#pragma unroll
                for (int nt = 0; nt < 8; nt++)
                    MMA_TF32(acc[mt][nt], al[mt], (&bh[nt >> 1][(nt & 1) * 2]));
            // pass 3: ah*bl
#pragma unroll
            for (int mt = 0; mt < 2; mt++)
#pragma unroll
                for (int nt = 0; nt < 8; nt++)
                    MMA_TF32(acc[mt][nt], ah[mt], (&bl[nt >> 1][(nt & 1) * 2]));
        }
        __syncthreads();
    }

    // epilogue
#pragma unroll
    for (int mt = 0; mt < 2; mt++) {
        size_t r0 = arow + wm + mt * 16 + g;
#pragma unroll
        for (int nt = 0; nt < 8; nt++) {
            int c = ccol + wn + nt * 8 + 2 * t;
            if (Cl) {
                float h0, l0, h1, l1;
                split_tf32(acc[mt][nt][0], h0, l0);
                split_tf32(acc[mt][nt][1], h1, l1);
                *(float2*)(Ch + r0 * Dq + c) = make_float2(h0, h1);
                *(float2*)(Cl + r0 * Dq + c) = make_float2(l0, l1);
                split_tf32(acc[mt][nt][2], h0, l0);
                split_tf32(acc[mt][nt][3], h1, l1);
                *(float2*)(Ch + (r0 + 8) * Dq + c) = make_float2(h0, h1);
                *(float2*)(Cl + (r0 + 8) * Dq + c) = make_float2(l0, l1);
            } else {
                float b0 = bias[c], b1 = bias[c + 1];
                *(float2*)(Ch + r0 * Dq + c) =
                    make_float2(acc[mt][nt][0] + b0, acc[mt][nt][1] + b1);
                *(float2*)(Ch + (r0 + 8) * Dq + c) =
                    make_float2(acc[mt][nt][2] + b0, acc[mt][nt][3] + b1);
            }
        }
    }
#undef PREFETCH
}

__global__ __launch_bounds__(256, 2) void qkv_gemm_p()
{
    int w = blockIdx.x >> 3, colBlk = blockIdx.x & 7;
    float* Ch = (w == 0) ? g_qh : (w == 1) ? g_kh : g_vh;
    float* Cl = (w == 0) ? g_ql : (w == 1) ? g_kl : g_vl;
    gemm_pipe(g_xh, g_xl,
              g_wsh + (size_t)w * Dq * Dq, g_wsl + (size_t)w * Dq * Dq,
              Ch, Cl, nullptr, blockIdx.y, colBlk);
}

__global__ __launch_bounds__(256, 2) void out_proj_p(const float* __restrict__ bo,
                                                     float* __restrict__ out)
{
    gemm_pipe(g_aoh, g_aol,
              g_wsh + (size_t)3 * Dq * Dq, g_wsl + (size_t)3 * Dq * Dq,
              out, nullptr, bo, blockIdx.y, blockIdx.x);
}

// ---------------------------------------------------------------------------
// Tensor-core flash attention (3xTF32), ALiBi + causal — MMA passes reordered.
// ---------------------------------------------------------------------------
#define QSTR 68
#define KSTR 68
#define VSTR 72
#define PSTR 136
#define OFF_QH 0
#define OFF_QL (128 * QSTR)
#define OFF_KH (2 * 128 * QSTR)
#define OFF_KL (OFF_KH + 64 * KSTR)
#define OFF_VH (OFF_KL + 64 * KSTR)
#define OFF_VL (OFF_VH + 64 * VSTR)
#define OFF_PT (OFF_VL + 64 * VSTR)
#define OFF_MP (OFF_PT + 64 * PSTR)
#define OFF_LP (OFF_MP + 256)
#define FLTC_SMEM ((OFF_LP + 256) * 4)

__global__ __launch_bounds__(256, 1) void flash_alibi_tc()
{
    extern __shared__ float sm[];
    const unsigned smb = (unsigned)__cvta_generic_to_shared(sm);
    float* Qh = sm + OFF_QH;
    float* Ql = sm + OFF_QL;
    float* Kh = sm + OFF_KH;
    float* Kl = sm + OFF_KL;
    float* Vh = sm + OFF_VH;
    float* Vl = sm + OFF_VL;
    float* Pt = sm + OFF_PT;
    float* mp = sm + OFF_MP;
    float* lp = sm + OFF_LP;

    const int tid  = threadIdx.x;
    const int lane = tid & 31, wid = tid >> 5;
    const int g = lane >> 2, t = lane & 3;
    const int iw = wid & 3;
    const int ow = wid >> 2;
    const int it = (int)gridDim.x - 1 - (int)blockIdx.x;
    const int i0 = it * 128;
    const int h  = blockIdx.y, b = blockIdx.z;
    const float slope_l2 = exp2f(-0.5f * (float)(h + 1)) * 1.44269504f;
    const float sscale   = 0.125f * 1.44269504f;

    {
        size_t qbase = ((size_t)(b * Nq + i0) * Hq + h) * DHq;
        int i = tid >> 1, d0 = (tid & 1) * 32;
#pragma unroll
        for (int ii = 0; ii < 8; ii++) {
            int d = d0 + ii * 4;
            CP_A16(smb + (unsigned)(OFF_QH + i * QSTR + d) * 4, g_qh + qbase + (size_t)i * HDq + d);
            CP_A16(smb + (unsigned)(OFF_QL + i * QSTR + d) * 4, g_ql + qbase + (size_t)i * HDq + d);
        }
        CP_COMMIT();
    }

    float acc_o[2][4][4] = {};
    float m_s[8], l_s[8];
#pragma unroll
    for (int k8 = 0; k8 < 8; k8++) { m_s[k8] = -1e30f; l_s[k8] = 0.f; }

    const int njt = 2 * (it + 1);
    for (int jt = 0; jt < njt; jt++) {
        const int j0 = jt * 64;
        __syncthreads();

        {
            int jr = tid >> 2, d0 = (tid & 3) * 4;
            size_t base = ((size_t)(b * Nq + j0 + jr) * Hq + h) * DHq;
#pragma unroll
            for (int ii = 0; ii < 4; ii++) {
                int d = d0 + ii * 16;
                CP_A16(smb + (unsigned)(OFF_KH + jr * KSTR + d) * 4, g_kh + base + d);
                CP_A16(smb + (unsigned)(OFF_KL + jr * KSTR + d) * 4, g_kl + base + d);
                CP_A16(smb + (unsigned)(OFF_VH + jr * VSTR + d) * 4, g_vh + base + d);
                CP_A16(smb + (unsigned)(OFF_VL + jr * VSTR + d) * 4, g_vl + base + d);
            }
            CP_COMMIT();
            CP_WAIT0();
        }
        __syncthreads();

        float s[2][4][4] = {};
#pragma unroll
        for (int kt = 0; kt < 8; kt++) {
            int kk = kt * 8;
            unsigned ah[2][4], al[2][4];
#pragma unroll
            for (int mt = 0; mt < 2; mt++) {
                int r = ow * 32 + mt * 16 + g;
                ah[mt][0] = __float_as_uint(Kh[(r    ) * KSTR + kk + t    ]);
                ah[mt][1] = __float_as_uint(Kh[(r + 8) * KSTR + kk + t    ]);
                ah[mt][2] = __float_as_uint(Kh[(r    ) * KSTR + kk + t + 4]);
                ah[mt][3] = __float_as_uint(Kh[(r + 8) * KSTR + kk + t + 4]);
                al[mt][0] = __float_as_uint(Kl[(r    ) * KSTR + kk + t    ]);
                al[mt][1] = __float_as_uint(Kl[(r + 8) * KSTR + kk + t    ]);
                al[mt][2] = __float_as_uint(Kl[(r    ) * KSTR + kk + t + 4]);
                al[mt][3] = __float_as_uint(Kl[(r + 8) * KSTR + kk + t + 4]);
            }
            unsigned bh[4][2], bl[4][2];
#pragma unroll
            for (int nt = 0; nt < 4; nt++) {
                int c = iw * 32 + nt * 8 + g;
                bh[nt][0] = __float_as_uint(Qh[c * QSTR + kk + t    ]);
                bh[nt][1] = __float_as_uint(Qh[c * QSTR + kk + t + 4]);
                bl[nt][0] = __float_as_uint(Ql[c * QSTR + kk + t    ]);
                bl[nt][1] = __float_as_uint(Ql[c * QSTR + kk + t + 4]);
            }
#pragma unroll
            for (int mt = 0; mt < 2; mt++)
#pragma unroll
                for (int nt = 0; nt < 4; nt++)
                    MMA_TF32(s[mt][nt], ah[mt], bh[nt]);
#pragma unroll
            for (int mt = 0; mt < 2; mt++)
#pragma unroll
                for (int nt = 0; nt < 4; nt++)
                    MMA_TF32(s[mt][nt], al[mt], bh[nt]);
#pragma unroll
            for (int mt = 0; mt < 2; mt++)
#pragma unroll
                for (int nt = 0; nt < 4; nt++)
                    MMA_TF32(s[mt][nt], ah[mt], bl[nt]);
        }

        float colmax[8];
#pragma unroll
        for (int k8 = 0; k8 < 8; k8++) colmax[k8] = -1e30f;
#pragma unroll
        for (int mt = 0; mt < 2; mt++)
#pragma unroll
            for (int nt = 0; nt < 4; nt++)
#pragma unroll
                for (int e = 0; e < 4; e++) {
                    int jg = j0 + ow * 32 + mt * 16 + g + ((e & 2) ? 8 : 0);
                    int ig = i0 + iw * 32 + nt * 8 + 2 * t + (e & 1);
                    float v = s[mt][nt][e] * sscale + slope_l2 * (float)(ig - jg);
                    if (jg > ig) v = -1e30f;
                    s[mt][nt][e] = v;
                    int c8 = nt * 2 + (e & 1);
                    colmax[c8] = fmaxf(colmax[c8], v);
                }
#pragma unroll
        for (int k8 = 0; k8 < 8; k8++) {
            colmax[k8] = fmaxf(colmax[k8], __shfl_xor_sync(0xffffffffu, colmax[k8], 4));
            colmax[k8] = fmaxf(colmax[k8], __shfl_xor_sync(0xffffffffu, colmax[k8], 8));
            colmax[k8] = fmaxf(colmax[k8], __shfl_xor_sync(0xffffffffu, colmax[k8], 16));
        }
        if (g == 0) {
#pragma unroll
            for (int k8 = 0; k8 < 8; k8++)
                mp[ow * 128 + iw * 32 + (k8 >> 1) * 8 + 2 * t + (k8 & 1)] = colmax[k8];
        }
        __syncthreads();

        float f[8], mnew[8];
#pragma unroll
        for (int k8 = 0; k8 < 8; k8++) {
            int irel = iw * 32 + (k8 >> 1) * 8 + 2 * t + (k8 & 1);
            float mt2 = fmaxf(mp[irel], mp[128 + irel]);
            mnew[k8] = fmaxf(m_s[k8], mt2);
            f[k8] = ex2(m_s[k8] - mnew[k8]);
            m_s[k8] = mnew[k8];
        }

        float csum[8];
#pragma unroll
        for (int k8 = 0; k8 < 8; k8++) csum[k8] = 0.f;
#pragma unroll
        for (int mt = 0; mt < 2; mt++)
#pragma unroll
            for (int nt = 0; nt < 4; nt++)
#pragma unroll
                for (int e = 0; e < 4; e++) {
                    int c8 = nt * 2 + (e & 1);
                    float p = ex2(s[mt][nt][e] - mnew[c8]);
                    s[mt][nt][e] = p;
                    csum[c8] += p;
                }
#pragma unroll
        for (int k8 = 0; k8 < 8; k8++) {
            csum[k8] += __shfl_xor_sync(0xffffffffu, csum[k8], 4);
            csum[k8] += __shfl_xor_sync(0xffffffffu, csum[k8], 8);
            csum[k8] += __shfl_xor_sync(0xffffffffu, csum[k8], 16);
        }
        if (g == 0) {
#pragma unroll
            for (int k8 = 0; k8 < 8; k8++)
                lp[ow * 128 + iw * 32 + (k8 >> 1) * 8 + 2 * t + (k8 & 1)] = csum[k8];
        }
#pragma unroll
        for (int mt = 0; mt < 2; mt++) {
            int row = ow * 32 + mt * 16 + g;
#pragma unroll
            for (int nt = 0; nt < 4; nt++) {
                int col = iw * 32 + nt * 8 + 2 * t;
                *(float2*)(Pt + row * PSTR + col)       = make_float2(s[mt][nt][0], s[mt][nt][1]);
                *(float2*)(Pt + (row + 8) * PSTR + col) = make_float2(s[mt][nt][2], s[mt][nt][3]);
            }
        }
        __syncthreads();

#pragma unroll
        for (int k8 = 0; k8 < 8; k8++) {
            int irel = iw * 32 + (k8 >> 1) * 8 + 2 * t + (k8 & 1);
            l_s[k8] = l_s[k8] * f[k8] + (lp[irel] + lp[128 + irel]);
        }
#pragma unroll
        for (int mt = 0; mt < 2; mt++)
#pragma unroll
            for (int nt = 0; nt < 4; nt++)
#pragma unroll
                for (int e = 0; e < 4; e++)
                    acc_o[mt][nt][e] *= f[nt * 2 + (e & 1)];

#pragma unroll
        for (int kt = 0; kt < 8; kt++) {
            int kk = kt * 8;
            unsigned vh_[2][4], vl_[2][4];
#pragma unroll
            for (int mt = 0; mt < 2; mt++) {
                int dc = ow * 32 + mt * 16 + g;
                vh_[mt][0] = __float_as_uint(Vh[(kk + t    ) * VSTR + dc    ]);
                vh_[mt][1] = __float_as_uint(Vh[(kk + t    ) * VSTR + dc + 8]);
                vh_[mt][2] = __float_as_uint(Vh[(kk + t + 4) * VSTR + dc    ]);
                vh_[mt][3] = __float_as_uint(Vh[(kk + t + 4) * VSTR + dc + 8]);
                vl_[mt][0] = __float_as_uint(Vl[(kk + t    ) * VSTR + dc    ]);
                vl_[mt][1] = __float_as_uint(Vl[(kk + t    ) * VSTR + dc + 8]);
                vl_[mt][2] = __float_as_uint(Vl[(kk + t + 4) * VSTR + dc    ]);
                vl_[mt][3] = __float_as_uint(Vl[(kk + t + 4) * VSTR + dc + 8]);
            }
            unsigned ph[4][2], pl[4][2];
#pragma unroll
            for (int nt = 0; nt < 4; nt++) {
                int ic = iw * 32 + nt * 8 + g;
                float p0 = Pt[(kk + t    ) * PSTR + ic];
                float p1 = Pt[(kk + t + 4) * PSTR + ic];
                float hh, ll;
                split_tf32(p0, hh, ll);
                ph[nt][0] = __float_as_uint(hh); pl[nt][0] = __float_as_uint(ll);
                split_tf32(p1, hh, ll);
                ph[nt][1] = __float_as_uint(hh); pl[nt][1] = __float_as_uint(ll);
            }
#pragma unroll
            for (int mt = 0; mt < 2; mt++)
#pragma unroll
                for (int nt = 0; nt < 4; nt++)
                    MMA_TF32(acc_o[mt][nt], vh_[mt], ph[nt]);
#pragma unroll
            for (int mt = 0; mt < 2; mt++)
#pragma unroll
                for (int nt = 0; nt < 4; nt++)
                    MMA_TF32(acc_o[mt][nt], vl_[mt], ph[nt]);
#pragma unroll
            for (int mt = 0; mt < 2; mt++)
#pragma unroll
                for (int nt = 0; nt < 4; nt++)
                    MMA_TF32(acc_o[mt][nt], vh_[mt], pl[nt]);
        }
    }

    float inv[8];
#pragma unroll
    for (int k8 = 0; k8 < 8; k8++) inv[k8] = 1.f / l_s[k8];
#pragma unroll
    for (int mt = 0; mt < 2; mt++)
#pragma unroll
        for (int nt = 0; nt < 4; nt++)
#pragma unroll
            for (int e = 0; e < 4; e++) {
                int d  = ow * 32 + mt * 16 + g + ((e & 2) ? 8 : 0);
                int ig = i0 + iw * 32 + nt * 8 + 2 * t + (e & 1);
                size_t idx = ((size_t)(b * Nq + ig) * Hq + h) * DHq + d;
                float hh, ll;
                split_tf32(acc_o[mt][nt][e] * inv[nt * 2 + (e & 1)], hh, ll);
                g_aoh[idx] = hh;
                g_aol[idx] = ll;
            }
}

// ---------------------------------------------------------------------------
extern "C" void kernel_launch(void* const* d_in, const int* in_sizes, int n_in,
                              void* d_out, int out_size)
{
    (void)in_sizes; (void)n_in; (void)out_size;
    const float* x  = (const float*)d_in[0];
    const float* Wq = (const float*)d_in[1];
    const float* Wk = (const float*)d_in[2];
    const float* Wv = (const float*)d_in[3];
    const float* Wo = (const float*)d_in[4];
    const float* bo = (const float*)d_in[5];
    float* out = (float*)d_out;

    cudaFuncSetAttribute(qkv_gemm_p, cudaFuncAttributeMaxDynamicSharedMemorySize, GEMMP_SMEM);
    cudaFuncSetAttribute(out_proj_p, cudaFuncAttributeMaxDynamicSharedMemorySize, GEMMP_SMEM);
    cudaFuncSetAttribute(flash_alibi_tc, cudaFuncAttributeMaxDynamicSharedMemorySize, FLTC_SMEM);

    split_x<<<Mq * Dq / 4 / 256, 256>>>(x);
    split_wT<<<dim3(32, 16), 256>>>(Wq, 0);
    split_wT<<<dim3(32, 16), 256>>>(Wk, 1);
    split_wT<<<dim3(32, 16), 256>>>(Wv, 2);
    split_wT<<<dim3(32, 16), 256>>>(Wo, 3);

    qkv_gemm_p<<<dim3(24, 32), 256, GEMMP_SMEM>>>();
    flash_alibi_tc<<<dim3(16, Hq, Bq), 256, FLTC_SMEM>>>();
    out_proj_p<<<dim3(8, 32), 256, GEMMP_SMEM>>>(bo, out);
}

// round 9
// speedup vs baseline: 1.2627x; 1.2627x over previous
#include <cuda_runtime.h>
#include <cuda_bf16.h>

#define Bq 2
#define Nq 2048
#define Hq 16
#define DHq 64
#define Dq 1024
#define HDq (Hq * DHq)   // 1024
#define Mq (Bq * Nq)     // 4096

#define PLX ((size_t)Mq * Dq)
#define PLW ((size_t)Dq * Dq)
#define PLA ((size_t)Mq * HDq)

// bf16 split planes (GEMM inputs)
__device__ __nv_bfloat16 g_xb0[PLX], g_xb1[PLX];
__device__ __nv_bfloat16 g_wtb[8 * PLW];          // 4 weights x 2 planes, transposed [n][k]
__device__ __nv_bfloat16 g_ab0[PLA], g_ab1[PLA];  // attention out planes
// tf32 hi/lo planes for flash
__device__ float g_qh[PLA], g_ql[PLA];
__device__ float g_kh[PLA], g_kl[PLA];
__device__ float g_vh[PLA], g_vl[PLA];

// ---------------------------------------------------------------------------
// helpers
// ---------------------------------------------------------------------------
__device__ __forceinline__ void split_tf32(float x, float& hi, float& lo)
{
    unsigned h;
    asm("cvt.rna.tf32.f32 %0, %1;" : "=r"(h) : "f"(x));
    hi = __uint_as_float(h);
    float r = x - hi;
    unsigned l;
    asm("cvt.rna.tf32.f32 %0, %1;" : "=r"(l) : "f"(r));
    lo = __uint_as_float(l);
}

__device__ __forceinline__ void split_bf16(float x, __nv_bfloat16& b0, __nv_bfloat16& b1)
{
    b0 = __float2bfloat16(x);
    b1 = __float2bfloat16(x - __bfloat162float(b0));
}

__device__ __forceinline__ float ex2(float x)
{
    float r;
    asm("ex2.approx.f32 %0, %1;" : "=f"(r) : "f"(x));
    return r;
}

#define MMA_TF32(d, a, b)                                                     \
    asm volatile("mma.sync.aligned.m16n8k8.row.col.f32.tf32.tf32.f32 "        \
                 "{%0,%1,%2,%3}, {%4,%5,%6,%7}, {%8,%9}, {%0,%1,%2,%3};"      \
                 : "+f"(d[0]), "+f"(d[1]), "+f"(d[2]), "+f"(d[3])             \
                 : "r"(a[0]), "r"(a[1]), "r"(a[2]), "r"(a[3]),                \
                   "r"(b[0]), "r"(b[1]))

#define MMA_BF16(d, a, b0_, b1_)                                              \
    asm volatile("mma.sync.aligned.m16n8k16.row.col.f32.bf16.bf16.f32 "       \
                 "{%0,%1,%2,%3}, {%4,%5,%6,%7}, {%8,%9}, {%0,%1,%2,%3};"      \
                 : "+f"(d[0]), "+f"(d[1]), "+f"(d[2]), "+f"(d[3])             \
                 : "r"(a[0]), "r"(a[1]), "r"(a[2]), "r"(a[3]),                \
                   "r"(b0_), "r"(b1_))

#define LDSM_X4(r0, r1, r2, r3, addr)                                         \
    asm volatile("ldmatrix.sync.aligned.m8n8.x4.shared.b16 {%0,%1,%2,%3}, [%4];" \
                 : "=r"(r0), "=r"(r1), "=r"(r2), "=r"(r3) : "r"(addr))

#define CP_A16(dst, src) \
    asm volatile("cp.async.cg.shared.global [%0], [%1], 16;" :: "r"(dst), "l"(src))
#define CP_COMMIT() asm volatile("cp.async.commit_group;")
#define CP_WAIT0()  asm volatile("cp.async.wait_group 0;" ::: "memory")
#define CP_WAIT1()  asm volatile("cp.async.wait_group 1;" ::: "memory")

// ---------------------------------------------------------------------------
// split kernels
// ---------------------------------------------------------------------------
__global__ __launch_bounds__(256) void split_x_b(const float* __restrict__ in)
{
    size_t i = (size_t)blockIdx.x * 256 + threadIdx.x;   // over float4
    float4 v = ((const float4*)in)[i];
    __nv_bfloat16 a0, a1, b0, b1, c0, c1, d0, d1;
    split_bf16(v.x, a0, a1); split_bf16(v.y, b0, b1);
    split_bf16(v.z, c0, c1); split_bf16(v.w, d0, d1);
    __nv_bfloat162 p;
    p.x = a0; p.y = b0; *(__nv_bfloat162*)(g_xb0 + i * 4)     = p;
    p.x = c0; p.y = d0; *(__nv_bfloat162*)(g_xb0 + i * 4 + 2) = p;
    p.x = a1; p.y = b1; *(__nv_bfloat162*)(g_xb1 + i * 4)     = p;
    p.x = c1; p.y = d1; *(__nv_bfloat162*)(g_xb1 + i * 4 + 2) = p;
}

// transpose + split: Wt_p[n][k] = split(W[k][n])
__global__ __launch_bounds__(256) void split_wT_b(const float* __restrict__ W, int w)
{
    int n  = blockIdx.x * 32 + (threadIdx.x & 31);
    int k0 = blockIdx.y * 64 + (threadIdx.x >> 5) * 8;
    __nv_bfloat16 b0[8], b1[8];
#pragma unroll
    for (int j = 0; j < 8; j++) {
        float v = W[(size_t)(k0 + j) * Dq + n];
        split_bf16(v, b0[j], b1[j]);
    }
    __nv_bfloat16* d0 = g_wtb + (size_t)(w * 2 + 0) * PLW + (size_t)n * Dq + k0;
    __nv_bfloat16* d1 = g_wtb + (size_t)(w * 2 + 1) * PLW + (size_t)n * Dq + k0;
#pragma unroll
    for (int j = 0; j < 8; j += 2) {
        __nv_bfloat162 p;
        p.x = b0[j]; p.y = b0[j + 1]; *(__nv_bfloat162*)(d0 + j) = p;
        p.x = b1[j]; p.y = b1[j + 1]; *(__nv_bfloat162*)(d1 + j) = p;
    }
}

// ---------------------------------------------------------------------------
// bf16x3 m16n8k16 GEMM: C[128,128] = A[128,1024] @ W^T (W stored [n][k]).
// BK=16, 2-stage cp.async, 256 thr. smem tiles [128][16] bf16, row stride 48 B
// (ldmatrix phase offsets {0,48,96,16,64,112,32,80} mod 128 -> conflict-free).
// planes per stage: Ab0 Ab1 Wb0 Wb1, 6144 B each; stage 24576 B.
// ---------------------------------------------------------------------------
#define TPL 6144
#define STAGE_B 24576
#define GEMMP_SMEM (2 * STAGE_B)   // 49152

__device__ __forceinline__ void gemm_pipe_bf(const __nv_bfloat16* __restrict__ Ab0,
                                             const __nv_bfloat16* __restrict__ Ab1,
                                             const __nv_bfloat16* __restrict__ Wb0,
                                             const __nv_bfloat16* __restrict__ Wb1,
                                             float* __restrict__ Ch,
                                             float* __restrict__ Cl,
                                             const float* __restrict__ bias,
                                             int rowBlk, int colBlk)
{
    extern __shared__ float sm[];
    const unsigned smb = (unsigned)__cvta_generic_to_shared(sm);
    const int tid = threadIdx.x;
    const int wid = tid >> 5, lane = tid & 31;
    const int g = lane >> 2, t = lane & 3;
    const int wm = (wid & 3) * 32, wn = (wid >> 2) * 64;

    const size_t arow = (size_t)rowBlk * 128;
    const int ccol = colBlk * 128;

    const int quad = lane >> 3, lrow = lane & 7;
    // per-lane offset inside a [*,16]-bf16 tile with 48 B row stride
    const unsigned lmoff = (unsigned)(((quad & 1) * 8 + lrow) * 48 + (quad >> 1) * 16);

    float acc[2][8][4] = {};

#define PREFB(st, k0)                                                          \
    {                                                                          \
        unsigned base = smb + (st) * STAGE_B;                                  \
        int r = tid >> 1, c = tid & 1;                                         \
        unsigned so = (unsigned)(r * 48 + c * 16);                             \
        CP_A16(base + 0 * TPL + so, Ab0 + (arow + r) * Dq + (k0) + c * 8);     \
        CP_A16(base + 1 * TPL + so, Ab1 + (arow + r) * Dq + (k0) + c * 8);     \
        CP_A16(base + 2 * TPL + so, Wb0 + (size_t)(ccol + r) * Dq + (k0) + c * 8); \
        CP_A16(base + 3 * TPL + so, Wb1 + (size_t)(ccol + r) * Dq + (k0) + c * 8); \
    }

    PREFB(0, 0);
    CP_COMMIT();

    const int nch = Dq / 16;   // 64
    for (int chn = 0; chn < nch; chn++) {
        if (chn + 1 < nch) {
            PREFB((chn + 1) & 1, (chn + 1) * 16);
            CP_COMMIT();
            CP_WAIT1();
        } else {
            CP_WAIT0();
        }
        __syncthreads();

        const unsigned stg = smb + (chn & 1) * STAGE_B;

        unsigned af0[2][4], af1[2][4];
#pragma unroll
        for (int mt = 0; mt < 2; mt++) {
            unsigned ao = stg + (unsigned)((wm + mt * 16) * 48) + lmoff;
            LDSM_X4(af0[mt][0], af0[mt][1], af0[mt][2], af0[mt][3], ao);
            LDSM_X4(af1[mt][0], af1[mt][1], af1[mt][2], af1[mt][3], ao + TPL);
        }
        unsigned bf0[4][4], bf1[4][4];
#pragma unroll
        for (int np = 0; np < 4; np++) {
            unsigned wo = stg + 2 * TPL + (unsigned)((wn + np * 16) * 48) + lmoff;
            LDSM_X4(bf0[np][0], bf0[np][1], bf0[np][2], bf0[np][3], wo);
            LDSM_X4(bf1[np][0], bf1[np][1], bf1[np][2], bf1[np][3], wo + TPL);
        }
        // rows ldsm-major: with this quad mapping, r0=rows0-7/k0-7, r1=rows8-15/k0-7,
        // r2=rows0-7/k8-15, r3=rows8-15/k8-15.
        // A frag = {r0,r1,r2,r3}. W frag nt-even = {r0,r2}, nt-odd = {r1,r3}.
        // pass 1: a0*b0 over all 16 independent tiles
#pragma unroll
        for (int mt = 0; mt < 2; mt++)
#pragma unroll
            for (int nt = 0; nt < 8; nt++)
                MMA_BF16(acc[mt][nt], af0[mt], bf0[nt >> 1][nt & 1], bf0[nt >> 1][(nt & 1) + 2]);
        // pass 2: a1*b0
#pragma unroll
        for (int mt = 0; mt < 2; mt++)
#pragma unroll
            for (int nt = 0; nt < 8; nt++)
                MMA_BF16(acc[mt][nt], af1[mt], bf0[nt >> 1][nt & 1], bf0[nt >> 1][(nt & 1) + 2]);
        // pass 3: a0*b1
#pragma unroll
        for (int mt = 0; mt < 2; mt++)
#pragma unroll
            for (int nt = 0; nt < 8; nt++)
                MMA_BF16(acc[mt][nt], af0[mt], bf1[nt >> 1][nt & 1], bf1[nt >> 1][(nt & 1) + 2]);
        __syncthreads();
    }

    // epilogue: A-frag row mapping identical to k8 tf32 version
#pragma unroll
    for (int mt = 0; mt < 2; mt++) {
        size_t r0 = arow + wm + mt * 16 + g;
#pragma unroll
        for (int nt = 0; nt < 8; nt++) {
            int c = ccol + wn + nt * 8 + 2 * t;
            if (Cl) {
                float h0, l0, h1, l1;
                split_tf32(acc[mt][nt][0], h0, l0);
                split_tf32(acc[mt][nt][1], h1, l1);
                *(float2*)(Ch + r0 * Dq + c) = make_float2(h0, h1);
                *(float2*)(Cl + r0 * Dq + c) = make_float2(l0, l1);
                split_tf32(acc[mt][nt][2], h0, l0);
                split_tf32(acc[mt][nt][3], h1, l1);
                *(float2*)(Ch + (r0 + 8) * Dq + c) = make_float2(h0, h1);
                *(float2*)(Cl + (r0 + 8) * Dq + c) = make_float2(l0, l1);
            } else {
                float b0 = bias[c], b1 = bias[c + 1];
                *(float2*)(Ch + r0 * Dq + c) =
                    make_float2(acc[mt][nt][0] + b0, acc[mt][nt][1] + b1);
                *(float2*)(Ch + (r0 + 8) * Dq + c) =
                    make_float2(acc[mt][nt][2] + b0, acc[mt][nt][3] + b1);
            }
        }
    }
#undef PREFB
}

__global__ __launch_bounds__(256, 2) void qkv_gemm_p()
{
    int w = blockIdx.x >> 3, colBlk = blockIdx.x & 7;
    float* Ch = (w == 0) ? g_qh : (w == 1) ? g_kh : g_vh;
    float* Cl = (w == 0) ? g_ql : (w == 1) ? g_kl : g_vl;
    gemm_pipe_bf(g_xb0, g_xb1,
                 g_wtb + (size_t)(w * 2) * PLW, g_wtb + (size_t)(w * 2 + 1) * PLW,
                 Ch, Cl, nullptr, blockIdx.y, colBlk);
}

__global__ __launch_bounds__(256, 2) void out_proj_p(const float* __restrict__ bo,
                                                     float* __restrict__ out)
{
    gemm_pipe_bf(g_ab0, g_ab1,
                 g_wtb + (size_t)6 * PLW, g_wtb + (size_t)7 * PLW,
                 out, nullptr, bo, blockIdx.y, blockIdx.x);
}

// ---------------------------------------------------------------------------
// Tensor-core flash attention (3xTF32), ALiBi + causal — unchanged mainloop.
// Epilogue writes bf16 split planes for out_proj.
// ---------------------------------------------------------------------------
#define QSTR 68
#define KSTR 68
#define VSTR 72
#define PSTR 136
#define OFF_QH 0
#define OFF_QL (128 * QSTR)
#define OFF_KH (2 * 128 * QSTR)
#define OFF_KL (OFF_KH + 64 * KSTR)
#define OFF_VH (OFF_KL + 64 * KSTR)
#define OFF_VL (OFF_VH + 64 * VSTR)
#define OFF_PT (OFF_VL + 64 * VSTR)
#define OFF_MP (OFF_PT + 64 * PSTR)
#define OFF_LP (OFF_MP + 256)
#define FLTC_SMEM ((OFF_LP + 256) * 4)

__global__ __launch_bounds__(256, 1) void flash_alibi_tc()
{
    extern __shared__ float sm[];
    const unsigned smb = (unsigned)__cvta_generic_to_shared(sm);
    float* Qh = sm + OFF_QH;
    float* Ql = sm + OFF_QL;
    float* Kh = sm + OFF_KH;
    float* Kl = sm + OFF_KL;
    float* Vh = sm + OFF_VH;
    float* Vl = sm + OFF_VL;
    float* Pt = sm + OFF_PT;
    float* mp = sm + OFF_MP;
    float* lp = sm + OFF_LP;

    const int tid  = threadIdx.x;
    const int lane = tid & 31, wid = tid >> 5;
    const int g = lane >> 2, t = lane & 3;
    const int iw = wid & 3;
    const int ow = wid >> 2;
    const int it = (int)gridDim.x - 1 - (int)blockIdx.x;
    const int i0 = it * 128;
    const int h  = blockIdx.y, b = blockIdx.z;
    const float slope_l2 = exp2f(-0.5f * (float)(h + 1)) * 1.44269504f;
    const float sscale   = 0.125f * 1.44269504f;

    {
        size_t qbase = ((size_t)(b * Nq + i0) * Hq + h) * DHq;
        int i = tid >> 1, d0 = (tid & 1) * 32;
#pragma unroll
        for (int ii = 0; ii < 8; ii++) {
            int d = d0 + ii * 4;
            CP_A16(smb + (unsigned)(OFF_QH + i * QSTR + d) * 4, g_qh + qbase + (size_t)i * HDq + d);
            CP_A16(smb + (unsigned)(OFF_QL + i * QSTR + d) * 4, g_ql + qbase + (size_t)i * HDq + d);
        }
        CP_COMMIT();
    }

    float acc_o[2][4][4] = {};
    float m_s[8], l_s[8];
#pragma unroll
    for (int k8 = 0; k8 < 8; k8++) { m_s[k8] = -1e30f; l_s[k8] = 0.f; }

    const int njt = 2 * (it + 1);
    for (int jt = 0; jt < njt; jt++) {
        const int j0 = jt * 64;
        __syncthreads();

        {
            int jr = tid >> 2, d0 = (tid & 3) * 4;
            size_t base = ((size_t)(b * Nq + j0 + jr) * Hq + h) * DHq;
#pragma unroll
            for (int ii = 0; ii < 4; ii++) {
                int d = d0 + ii * 16;
                CP_A16(smb + (unsigned)(OFF_KH + jr * KSTR + d) * 4, g_kh + base + d);
                CP_A16(smb + (unsigned)(OFF_KL + jr * KSTR + d) * 4, g_kl + base + d);
                CP_A16(smb + (unsigned)(OFF_VH + jr * VSTR + d) * 4, g_vh + base + d);
                CP_A16(smb + (unsigned)(OFF_VL + jr * VSTR + d) * 4, g_vl + base + d);
            }
            CP_COMMIT();
            CP_WAIT0();
        }
        __syncthreads();

        float s[2][4][4] = {};
#pragma unroll
        for (int kt = 0; kt < 8; kt++) {
            int kk = kt * 8;
            unsigned ah[2][4], al[2][4];
#pragma unroll
            for (int mt = 0; mt < 2; mt++) {
                int r = ow * 32 + mt * 16 + g;
                ah[mt][0] = __float_as_uint(Kh[(r    ) * KSTR + kk + t    ]);
                ah[mt][1] = __float_as_uint(Kh[(r + 8) * KSTR + kk + t    ]);
                ah[mt][2] = __float_as_uint(Kh[(r    ) * KSTR + kk + t + 4]);
                ah[mt][3] = __float_as_uint(Kh[(r + 8) * KSTR + kk + t + 4]);
                al[mt][0] = __float_as_uint(Kl[(r    ) * KSTR + kk + t    ]);
                al[mt][1] = __float_as_uint(Kl[(r + 8) * KSTR + kk + t    ]);
                al[mt][2] = __float_as_uint(Kl[(r    ) * KSTR + kk + t + 4]);
                al[mt][3] = __float_as_uint(Kl[(r + 8) * KSTR + kk + t + 4]);
            }
            unsigned bh[4][2], bl[4][2];
#pragma unroll
            for (int nt = 0; nt < 4; nt++) {
                int c = iw * 32 + nt * 8 + g;
                bh[nt][0] = __float_as_uint(Qh[c * QSTR + kk + t    ]);
                bh[nt][1] = __float_as_uint(Qh[c * QSTR + kk + t + 4]);
                bl[nt][0] = __float_as_uint(Ql[c * QSTR + kk + t    ]);
                bl[nt][1] = __float_as_uint(Ql[c * QSTR + kk + t + 4]);
            }
#pragma unroll
            for (int mt = 0; mt < 2; mt++)
#pragma unroll
                for (int nt = 0; nt < 4; nt++)
                    MMA_TF32(s[mt][nt], ah[mt], bh[nt]);
#pragma unroll
            for (int mt = 0; mt < 2; mt++)
#pragma unroll
                for (int nt = 0; nt < 4; nt++)
                    MMA_TF32(s[mt][nt], al[mt], bh[nt]);
#pragma unroll
            for (int mt = 0; mt < 2; mt++)
#pragma unroll
                for (int nt = 0; nt < 4; nt++)
                    MMA_TF32(s[mt][nt], ah[mt], bl[nt]);
        }

        float colmax[8];
#pragma unroll
        for (int k8 = 0; k8 < 8; k8++) colmax[k8] = -1e30f;
#pragma unroll
        for (int mt = 0; mt < 2; mt++)
#pragma unroll
            for (int nt = 0; nt < 4; nt++)
#pragma unroll
                for (int e = 0; e < 4; e++) {
                    int jg = j0 + ow * 32 + mt * 16 + g + ((e & 2) ? 8 : 0);
                    int ig = i0 + iw * 32 + nt * 8 + 2 * t + (e & 1);
                    float v = s[mt][nt][e] * sscale + slope_l2 * (float)(ig - jg);
                    if (jg > ig) v = -1e30f;
                    s[mt][nt][e] = v;
                    int c8 = nt * 2 + (e & 1);
                    colmax[c8] = fmaxf(colmax[c8], v);
                }
#pragma unroll
        for (int k8 = 0; k8 < 8; k8++) {
            colmax[k8] = fmaxf(colmax[k8], __shfl_xor_sync(0xffffffffu, colmax[k8], 4));
            colmax[k8] = fmaxf(colmax[k8], __shfl_xor_sync(0xffffffffu, colmax[k8], 8));
            colmax[k8] = fmaxf(colmax[k8], __shfl_xor_sync(0xffffffffu, colmax[k8], 16));
        }
        if (g == 0) {
#pragma unroll
            for (int k8 = 0; k8 < 8; k8++)
                mp[ow * 128 + iw * 32 + (k8 >> 1) * 8 + 2 * t + (k8 & 1)] = colmax[k8];
        }
        __syncthreads();

        float f[8], mnew[8];
#pragma unroll
        for (int k8 = 0; k8 < 8; k8++) {
            int irel = iw * 32 + (k8 >> 1) * 8 + 2 * t + (k8 & 1);
            float mt2 = fmaxf(mp[irel], mp[128 + irel]);
            mnew[k8] = fmaxf(m_s[k8], mt2);
            f[k8] = ex2(m_s[k8] - mnew[k8]);
            m_s[k8] = mnew[k8];
        }

        float csum[8];
#pragma unroll
        for (int k8 = 0; k8 < 8; k8++) csum[k8] = 0.f;
#pragma unroll
        for (int mt = 0; mt < 2; mt++)
#pragma unroll
            for (int nt = 0; nt < 4; nt++)
#pragma unroll
                for (int e = 0; e < 4; e++) {
                    int c8 = nt * 2 + (e & 1);
                    float p = ex2(s[mt][nt][e] - mnew[c8]);
                    s[mt][nt][e] = p;
                    csum[c8] += p;
                }
#pragma unroll
        for (int k8 = 0; k8 < 8; k8++) {
            csum[k8] += __shfl_xor_sync(0xffffffffu, csum[k8], 4);
            csum[k8] += __shfl_xor_sync(0xffffffffu, csum[k8], 8);
            csum[k8] += __shfl_xor_sync(0xffffffffu, csum[k8], 16);
        }
        if (g == 0) {
#pragma unroll
            for (int k8 = 0; k8 < 8; k8++)
                lp[ow * 128 + iw * 32 + (k8 >> 1) * 8 + 2 * t + (k8 & 1)] = csum[k8];
        }
#pragma unroll
        for (int mt = 0; mt < 2; mt++) {
            int row = ow * 32 + mt * 16 + g;
#pragma unroll
            for (int nt = 0; nt < 4; nt++) {
                int col = iw * 32 + nt * 8 + 2 * t;
                *(float2*)(Pt + row * PSTR + col)       = make_float2(s[mt][nt][0], s[mt][nt][1]);
                *(float2*)(Pt + (row + 8) * PSTR + col) = make_float2(s[mt][nt][2], s[mt][nt][3]);
            }
        }
        __syncthreads();

#pragma unroll
        for (int k8 = 0; k8 < 8; k8++) {
            int irel = iw * 32 + (k8 >> 1) * 8 + 2 * t + (k8 & 1);
            l_s[k8] = l_s[k8] * f[k8] + (lp[irel] + lp[128 + irel]);
        }
#pragma unroll
        for (int mt = 0; mt < 2; mt++)
#pragma unroll
            for (int nt = 0; nt < 4; nt++)
#pragma unroll
                for (int e = 0; e < 4; e++)
                    acc_o[mt][nt][e] *= f[nt * 2 + (e & 1)];

#pragma unroll
        for (int kt = 0; kt < 8; kt++) {
            int kk = kt * 8;
            unsigned vh_[2][4], vl_[2][4];
#pragma unroll
            for (int mt = 0; mt < 2; mt++) {
                int dc = ow * 32 + mt * 16 + g;
                vh_[mt][0] = __float_as_uint(Vh[(kk + t    ) * VSTR + dc    ]);
                vh_[mt][1] = __float_as_uint(Vh[(kk + t    ) * VSTR + dc + 8]);
                vh_[mt][2] = __float_as_uint(Vh[(kk + t + 4) * VSTR + dc    ]);
                vh_[mt][3] = __float_as_uint(Vh[(kk + t + 4) * VSTR + dc + 8]);
                vl_[mt][0] = __float_as_uint(Vl[(kk + t    ) * VSTR + dc    ]);
                vl_[mt][1] = __float_as_uint(Vl[(kk + t    ) * VSTR + dc + 8]);
                vl_[mt][2] = __float_as_uint(Vl[(kk + t + 4) * VSTR + dc    ]);
                vl_[mt][3] = __float_as_uint(Vl[(kk + t + 4) * VSTR + dc + 8]);
            }
            unsigned ph[4][2], pl[4][2];
#pragma unroll
            for (int nt = 0; nt < 4; nt++) {
                int ic = iw * 32 + nt * 8 + g;
                float p0 = Pt[(kk + t    ) * PSTR + ic];
                float p1 = Pt[(kk + t + 4) * PSTR + ic];
                float hh, ll;
                split_tf32(p0, hh, ll);
                ph[nt][0] = __float_as_uint(hh); pl[nt][0] = __float_as_uint(ll);
                split_tf32(p1, hh, ll);
                ph[nt][1] = __float_as_uint(hh); pl[nt][1] = __float_as_uint(ll);
            }
#pragma unroll
            for (int mt = 0; mt < 2; mt++)
#pragma unroll
                for (int nt = 0; nt < 4; nt++)
                    MMA_TF32(acc_o[mt][nt], vh_[mt], ph[nt]);
#pragma unroll
            for (int mt = 0; mt < 2; mt++)
#pragma unroll
                for (int nt = 0; nt < 4; nt++)
                    MMA_TF32(acc_o[mt][nt], vl_[mt], ph[nt]);
#pragma unroll
            for (int mt = 0; mt < 2; mt++)
#pragma unroll
                for (int nt = 0; nt < 4; nt++)
                    MMA_TF32(acc_o[mt][nt], vh_[mt], pl[nt]);
        }
    }

    float inv[8];
#pragma unroll
    for (int k8 = 0; k8 < 8; k8++) inv[k8] = 1.f / l_s[k8];
#pragma unroll
    for (int mt = 0; mt < 2; mt++)
#pragma unroll
        for (int nt = 0; nt < 4; nt++)
#pragma unroll
            for (int e = 0; e < 4; e++) {
                int d  = ow * 32 + mt * 16 + g + ((e & 2) ? 8 : 0);
                int ig = i0 + iw * 32 + nt * 8 + 2 * t + (e & 1);
                size_t idx = ((size_t)(b * Nq + ig) * Hq + h) * DHq + d;
                float v = acc_o[mt][nt][e] * inv[nt * 2 + (e & 1)];
                __nv_bfloat16 b0, b1;
                split_bf16(v, b0, b1);
                g_ab0[idx] = b0;
                g_ab1[idx] = b1;
            }
}

// ---------------------------------------------------------------------------
extern "C" void kernel_launch(void* const* d_in, const int* in_sizes, int n_in,
                              void* d_out, int out_size)
{
    (void)in_sizes; (void)n_in; (void)out_size;
    const float* x  = (const float*)d_in[0];
    const float* Wq = (const float*)d_in[1];
    const float* Wk = (const float*)d_in[2];
    const float* Wv = (const float*)d_in[3];
    const float* Wo = (const float*)d_in[4];
    const float* bo = (const float*)d_in[5];
    float* out = (float*)d_out;

    cudaFuncSetAttribute(qkv_gemm_p, cudaFuncAttributeMaxDynamicSharedMemorySize, GEMMP_SMEM);
    cudaFuncSetAttribute(out_proj_p, cudaFuncAttributeMaxDynamicSharedMemorySize, GEMMP_SMEM);
    cudaFuncSetAttribute(flash_alibi_tc, cudaFuncAttributeMaxDynamicSharedMemorySize, FLTC_SMEM);

    split_x_b<<<Mq * Dq / 4 / 256, 256>>>(x);
    split_wT_b<<<dim3(32, 16), 256>>>(Wq, 0);
    split_wT_b<<<dim3(32, 16), 256>>>(Wk, 1);
    split_wT_b<<<dim3(32, 16), 256>>>(Wv, 2);
    split_wT_b<<<dim3(32, 16), 256>>>(Wo, 3);

    qkv_gemm_p<<<dim3(24, 32), 256, GEMMP_SMEM>>>();
    flash_alibi_tc<<<dim3(16, Hq, Bq), 256, FLTC_SMEM>>>();
    out_proj_p<<<dim3(8, 32), 256, GEMMP_SMEM>>>(bo, out);
}

// round 10
// speedup vs baseline: 1.6745x; 1.3261x over previous
#include <cuda_runtime.h>
#include <cuda_bf16.h>

#define Bq 2
#define Nq 2048
#define Hq 16
#define DHq 64
#define Dq 1024
#define HDq (Hq * DHq)   // 1024
#define Mq (Bq * Nq)     // 4096

#define PLX ((size_t)Mq * Dq)
#define PLW ((size_t)Dq * Dq)
#define PLA ((size_t)Mq * HDq)

// bf16 split planes
__device__ __nv_bfloat16 g_xb0[PLX], g_xb1[PLX];
__device__ __nv_bfloat16 g_wtb[8 * PLW];          // 4 weights x 2 planes, transposed [n][k]
__device__ __nv_bfloat16 g_qb0[PLA], g_qb1[PLA];
__device__ __nv_bfloat16 g_kb0[PLA], g_kb1[PLA];
__device__ __nv_bfloat16 g_vb0[PLA], g_vb1[PLA];
__device__ __nv_bfloat16 g_ab0[PLA], g_ab1[PLA];

// ---------------------------------------------------------------------------
// helpers
// ---------------------------------------------------------------------------
__device__ __forceinline__ void split_bf16(float x, __nv_bfloat16& b0, __nv_bfloat16& b1)
{
    b0 = __float2bfloat16(x);
    b1 = __float2bfloat16(x - __bfloat162float(b0));
}

__device__ __forceinline__ float bf_round(float x)
{
    return __bfloat162float(__float2bfloat16(x));
}

__device__ __forceinline__ float ex2(float x)
{
    float r;
    asm("ex2.approx.f32 %0, %1;" : "=f"(r) : "f"(x));
    return r;
}

// pack two floats to bf16x2: lo = a, hi = b
#define PK_BF2(d, a, b) \
    asm("cvt.rn.bf16x2.f32 %0, %1, %2;" : "=r"(d) : "f"(b), "f"(a))

#define MMA_BF16(d, a, b0_, b1_)                                              \
    asm volatile("mma.sync.aligned.m16n8k16.row.col.f32.bf16.bf16.f32 "       \
                 "{%0,%1,%2,%3}, {%4,%5,%6,%7}, {%8,%9}, {%0,%1,%2,%3};"      \
                 : "+f"(d[0]), "+f"(d[1]), "+f"(d[2]), "+f"(d[3])             \
                 : "r"(a[0]), "r"(a[1]), "r"(a[2]), "r"(a[3]),                \
                   "r"(b0_), "r"(b1_))

#define LDSM_X4(r0, r1, r2, r3, addr)                                         \
    asm volatile("ldmatrix.sync.aligned.m8n8.x4.shared.b16 {%0,%1,%2,%3}, [%4];" \
                 : "=r"(r0), "=r"(r1), "=r"(r2), "=r"(r3) : "r"(addr))

#define LDSM_T_X4(r0, r1, r2, r3, addr)                                       \
    asm volatile("ldmatrix.sync.aligned.m8n8.x4.trans.shared.b16 {%0,%1,%2,%3}, [%4];" \
                 : "=r"(r0), "=r"(r1), "=r"(r2), "=r"(r3) : "r"(addr))

#define CP_A16(dst, src) \
    asm volatile("cp.async.cg.shared.global [%0], [%1], 16;" :: "r"(dst), "l"(src))
#define CP_COMMIT() asm volatile("cp.async.commit_group;")
#define CP_WAIT0()  asm volatile("cp.async.wait_group 0;" ::: "memory")
#define CP_WAIT1()  asm volatile("cp.async.wait_group 1;" ::: "memory")

// ---------------------------------------------------------------------------
// split kernels
// ---------------------------------------------------------------------------
__global__ __launch_bounds__(256) void split_x_b(const float* __restrict__ in)
{
    size_t i = (size_t)blockIdx.x * 256 + threadIdx.x;   // over float4
    float4 v = ((const float4*)in)[i];
    __nv_bfloat16 a0, a1, b0, b1, c0, c1, d0, d1;
    split_bf16(v.x, a0, a1); split_bf16(v.y, b0, b1);
    split_bf16(v.z, c0, c1); split_bf16(v.w, d0, d1);
    __nv_bfloat162 p;
    p.x = a0; p.y = b0; *(__nv_bfloat162*)(g_xb0 + i * 4)     = p;
    p.x = c0; p.y = d0; *(__nv_bfloat162*)(g_xb0 + i * 4 + 2) = p;
    p.x = a1; p.y = b1; *(__nv_bfloat162*)(g_xb1 + i * 4)     = p;
    p.x = c1; p.y = d1; *(__nv_bfloat162*)(g_xb1 + i * 4 + 2) = p;
}

__global__ __launch_bounds__(256) void split_wT_b(const float* __restrict__ W, int w)
{
    int n  = blockIdx.x * 32 + (threadIdx.x & 31);
    int k0 = blockIdx.y * 64 + (threadIdx.x >> 5) * 8;
    __nv_bfloat16 b0[8], b1[8];
#pragma unroll
    for (int j = 0; j < 8; j++) {
        float v = W[(size_t)(k0 + j) * Dq + n];
        split_bf16(v, b0[j], b1[j]);
    }
    __nv_bfloat16* d0 = g_wtb + (size_t)(w * 2 + 0) * PLW + (size_t)n * Dq + k0;
    __nv_bfloat16* d1 = g_wtb + (size_t)(w * 2 + 1) * PLW + (size_t)n * Dq + k0;
#pragma unroll
    for (int j = 0; j < 8; j += 2) {
        __nv_bfloat162 p;
        p.x = b0[j]; p.y = b0[j + 1]; *(__nv_bfloat162*)(d0 + j) = p;
        p.x = b1[j]; p.y = b1[j + 1]; *(__nv_bfloat162*)(d1 + j) = p;
    }
}

// ---------------------------------------------------------------------------
// bf16x3 m16n8k16 GEMM (R8, proven). Epilogue: bf16 split planes OR fp32+bias.
// ---------------------------------------------------------------------------
#define TPL 6144
#define STAGE_B 24576
#define GEMMP_SMEM (2 * STAGE_B)

__device__ __forceinline__ void gemm_pipe_bf(const __nv_bfloat16* __restrict__ Ab0,
                                             const __nv_bfloat16* __restrict__ Ab1,
                                             const __nv_bfloat16* __restrict__ Wb0,
                                             const __nv_bfloat16* __restrict__ Wb1,
                                             __nv_bfloat16* __restrict__ Cb0,
                                             __nv_bfloat16* __restrict__ Cb1,
                                             float* __restrict__ Cf,
                                             const float* __restrict__ bias,
                                             int rowBlk, int colBlk)
{
    extern __shared__ float sm[];
    const unsigned smb = (unsigned)__cvta_generic_to_shared(sm);
    const int tid = threadIdx.x;
    const int wid = tid >> 5, lane = tid & 31;
    const int g = lane >> 2, t = lane & 3;
    const int wm = (wid & 3) * 32, wn = (wid >> 2) * 64;

    const size_t arow = (size_t)rowBlk * 128;
    const int ccol = colBlk * 128;

    const int quad = lane >> 3, lrow = lane & 7;
    const unsigned lmoff = (unsigned)(((quad & 1) * 8 + lrow) * 48 + (quad >> 1) * 16);

    float acc[2][8][4] = {};

#define PREFB(st, k0)                                                          \
    {                                                                          \
        unsigned base = smb + (st) * STAGE_B;                                  \
        int r = tid >> 1, c = tid & 1;                                         \
        unsigned so = (unsigned)(r * 48 + c * 16);                             \
        CP_A16(base + 0 * TPL + so, Ab0 + (arow + r) * Dq + (k0) + c * 8);     \
        CP_A16(base + 1 * TPL + so, Ab1 + (arow + r) * Dq + (k0) + c * 8);     \
        CP_A16(base + 2 * TPL + so, Wb0 + (size_t)(ccol + r) * Dq + (k0) + c * 8); \
        CP_A16(base + 3 * TPL + so, Wb1 + (size_t)(ccol + r) * Dq + (k0) + c * 8); \
    }

    PREFB(0, 0);
    CP_COMMIT();

    const int nch = Dq / 16;
    for (int chn = 0; chn < nch; chn++) {
        if (chn + 1 < nch) {
            PREFB((chn + 1) & 1, (chn + 1) * 16);
            CP_COMMIT();
            CP_WAIT1();
        } else {
            CP_WAIT0();
        }
        __syncthreads();

        const unsigned stg = smb + (chn & 1) * STAGE_B;

        unsigned af0[2][4], af1[2][4];
#pragma unroll
        for (int mt = 0; mt < 2; mt++) {
            unsigned ao = stg + (unsigned)((wm + mt * 16) * 48) + lmoff;
            LDSM_X4(af0[mt][0], af0[mt][1], af0[mt][2], af0[mt][3], ao);
            LDSM_X4(af1[mt][0], af1[mt][1], af1[mt][2], af1[mt][3], ao + TPL);
        }
        unsigned bf0[4][4], bf1[4][4];
#pragma unroll
        for (int np = 0; np < 4; np++) {
            unsigned wo = stg + 2 * TPL + (unsigned)((wn + np * 16) * 48) + lmoff;
            LDSM_X4(bf0[np][0], bf0[np][1], bf0[np][2], bf0[np][3], wo);
            LDSM_X4(bf1[np][0], bf1[np][1], bf1[np][2], bf1[np][3], wo + TPL);
        }
#pragma unroll
        for (int mt = 0; mt < 2; mt++)
#pragma unroll
            for (int nt = 0; nt < 8; nt++)
                MMA_BF16(acc[mt][nt], af0[mt], bf0[nt >> 1][nt & 1], bf0[nt >> 1][(nt & 1) + 2]);
#pragma unroll
        for (int mt = 0; mt < 2; mt++)
#pragma unroll
            for (int nt = 0; nt < 8; nt++)
                MMA_BF16(acc[mt][nt], af1[mt], bf0[nt >> 1][nt & 1], bf0[nt >> 1][(nt & 1) + 2]);
#pragma unroll
        for (int mt = 0; mt < 2; mt++)
#pragma unroll
            for (int nt = 0; nt < 8; nt++)
                MMA_BF16(acc[mt][nt], af0[mt], bf1[nt >> 1][nt & 1], bf1[nt >> 1][(nt & 1) + 2]);
        __syncthreads();
    }

#pragma unroll
    for (int mt = 0; mt < 2; mt++) {
        size_t r0 = arow + wm + mt * 16 + g;
#pragma unroll
        for (int nt = 0; nt < 8; nt++) {
            int c = ccol + wn + nt * 8 + 2 * t;
            if (Cb0) {
                float v0 = acc[mt][nt][0], v1 = acc[mt][nt][1];
                float v2 = acc[mt][nt][2], v3 = acc[mt][nt][3];
                unsigned u;
                PK_BF2(u, v0, v1);                       *(unsigned*)(Cb0 + r0 * Dq + c) = u;
                PK_BF2(u, v0 - bf_round(v0), v1 - bf_round(v1)); *(unsigned*)(Cb1 + r0 * Dq + c) = u;
                PK_BF2(u, v2, v3);                       *(unsigned*)(Cb0 + (r0 + 8) * Dq + c) = u;
                PK_BF2(u, v2 - bf_round(v2), v3 - bf_round(v3)); *(unsigned*)(Cb1 + (r0 + 8) * Dq + c) = u;
            } else {
                float b0 = bias[c], b1 = bias[c + 1];
                *(float2*)(Cf + r0 * Dq + c) =
                    make_float2(acc[mt][nt][0] + b0, acc[mt][nt][1] + b1);
                *(float2*)(Cf + (r0 + 8) * Dq + c) =
                    make_float2(acc[mt][nt][2] + b0, acc[mt][nt][3] + b1);
            }
        }
    }
#undef PREFB
}

__global__ __launch_bounds__(256, 2) void qkv_gemm_p()
{
    int w = blockIdx.x >> 3, colBlk = blockIdx.x & 7;
    __nv_bfloat16* C0 = (w == 0) ? g_qb0 : (w == 1) ? g_kb0 : g_vb0;
    __nv_bfloat16* C1 = (w == 0) ? g_qb1 : (w == 1) ? g_kb1 : g_vb1;
    gemm_pipe_bf(g_xb0, g_xb1,
                 g_wtb + (size_t)(w * 2) * PLW, g_wtb + (size_t)(w * 2 + 1) * PLW,
                 C0, C1, nullptr, nullptr, blockIdx.y, colBlk);
}

__global__ __launch_bounds__(256, 2) void out_proj_p(const float* __restrict__ bo,
                                                     float* __restrict__ out)
{
    gemm_pipe_bf(g_ab0, g_ab1,
                 g_wtb + (size_t)6 * PLW, g_wtb + (size_t)7 * PLW,
                 nullptr, nullptr, out, bo, blockIdx.y, blockIdx.x);
}

// ---------------------------------------------------------------------------
// bf16x3 flash attention (FA2 style): S = Q@K^T, O = P@V, P stays in registers.
// BR=128 (8 warps x 16 rows), BC=64. ALiBi + causal, log2-domain softmax.
// smem: Q0 Q1 [128][64]bf16 (stride 144B), K0 K1 V0 V1 [64][64] (stride 144B).
// ---------------------------------------------------------------------------
#define VRB 144
#define OFF_Q0 0
#define OFF_Q1 18432
#define OFF_K0 36864
#define OFF_K1 46080
#define OFF_V0 55296
#define OFF_V1 64512
#define FL_SMEM 73728

__global__ __launch_bounds__(256) void flash_bf()
{
    extern __shared__ char smc[];
    const unsigned smb = (unsigned)__cvta_generic_to_shared(smc);
    const int tid = threadIdx.x, wid = tid >> 5, lane = tid & 31;
    const int g = lane >> 2, t = lane & 3;
    const int quad = lane >> 3, lrow = lane & 7;
    const int it = (int)gridDim.x - 1 - (int)blockIdx.x;   // heavy tiles first
    const int i0 = it * 128;
    const int h = blockIdx.y, b = blockIdx.z;
    const float slope_l2 = exp2f(-0.5f * (float)(h + 1)) * 1.44269504f;
    const float sscale   = 0.125f * 1.44269504f;

    const unsigned lmoff = (unsigned)(((quad & 1) * 8 + lrow) * VRB + (quad >> 1) * 16);
    const unsigned vrow  = (unsigned)(lane & 15);
    const unsigned vc16  = (unsigned)(lane >> 4) * 16;

    // ---- load Q tile (2 planes) ----
    {
        size_t qb = ((size_t)(b * Nq + i0) * Hq + h) * DHq;
#pragma unroll
        for (int itr = 0; itr < 4; itr++) {
            int idx = itr * 256 + tid;
            int row = idx >> 3, ch = idx & 7;
            size_t src = qb + (size_t)row * HDq + ch * 8;
            CP_A16(smb + OFF_Q0 + (unsigned)(row * VRB + ch * 16), g_qb0 + src);
            CP_A16(smb + OFF_Q1 + (unsigned)(row * VRB + ch * 16), g_qb1 + src);
        }
        CP_COMMIT();
    }

    float o[8][4] = {};
    float m0 = -1e30f, m1 = -1e30f, l0 = 0.f, l1 = 0.f;

    const int njt = 2 * (it + 1);
    for (int jt = 0; jt < njt; jt++) {
        const int j0 = jt * 64;
        __syncthreads();   // protect prior K/V reads

        {
            size_t kb = ((size_t)(b * Nq + j0) * Hq + h) * DHq;
#pragma unroll
            for (int itr = 0; itr < 2; itr++) {
                int idx = itr * 256 + tid;
                int row = idx >> 3, ch = idx & 7;
                size_t src = kb + (size_t)row * HDq + ch * 8;
                unsigned so = (unsigned)(row * VRB + ch * 16);
                CP_A16(smb + OFF_K0 + so, g_kb0 + src);
                CP_A16(smb + OFF_K1 + so, g_kb1 + src);
                CP_A16(smb + OFF_V0 + so, g_vb0 + src);
                CP_A16(smb + OFF_V1 + so, g_vb1 + src);
            }
            CP_COMMIT();
            CP_WAIT0();
        }
        __syncthreads();

        // ---- S = Q @ K^T : warp tile m16 x n64, 4 k16 chunks ----
        float s[8][4] = {};
#pragma unroll
        for (int kt = 0; kt < 4; kt++) {
            unsigned a0[4], a1[4];
            unsigned qo = smb + OFF_Q0 + (unsigned)(wid * 16) * VRB + lmoff + kt * 32;
            LDSM_X4(a0[0], a0[1], a0[2], a0[3], qo);
            LDSM_X4(a1[0], a1[1], a1[2], a1[3], qo + (OFF_Q1 - OFF_Q0));
            unsigned kb0[4][4], kb1[4][4];
#pragma unroll
            for (int grp = 0; grp < 4; grp++) {
                unsigned ko = smb + OFF_K0 + (unsigned)(grp * 16) * VRB + lmoff + kt * 32;
                LDSM_X4(kb0[grp][0], kb0[grp][1], kb0[grp][2], kb0[grp][3], ko);
                LDSM_X4(kb1[grp][0], kb1[grp][1], kb1[grp][2], kb1[grp][3],
                        ko + (OFF_K1 - OFF_K0));
            }
#pragma unroll
            for (int nt = 0; nt < 8; nt++)
                MMA_BF16(s[nt], a0, kb0[nt >> 1][nt & 1], kb0[nt >> 1][(nt & 1) + 2]);
#pragma unroll
            for (int nt = 0; nt < 8; nt++)
                MMA_BF16(s[nt], a1, kb0[nt >> 1][nt & 1], kb0[nt >> 1][(nt & 1) + 2]);
#pragma unroll
            for (int nt = 0; nt < 8; nt++)
                MMA_BF16(s[nt], a0, kb1[nt >> 1][nt & 1], kb1[nt >> 1][(nt & 1) + 2]);
        }

        // ---- scale + ALiBi + causal, row stats (rows g and g+8) ----
        float rmax0 = -1e30f, rmax1 = -1e30f;
        const int ig0 = i0 + wid * 16 + g;
#pragma unroll
        for (int nt = 0; nt < 8; nt++)
#pragma unroll
            for (int e = 0; e < 4; e++) {
                int jg = j0 + nt * 8 + 2 * t + (e & 1);
                int ig = ig0 + ((e & 2) ? 8 : 0);
                float v = s[nt][e] * sscale + slope_l2 * (float)(ig - jg);
                if (jg > ig) v = -1e30f;
                s[nt][e] = v;
                if (e & 2) rmax1 = fmaxf(rmax1, v); else rmax0 = fmaxf(rmax0, v);
            }
        rmax0 = fmaxf(rmax0, __shfl_xor_sync(0xffffffffu, rmax0, 1));
        rmax0 = fmaxf(rmax0, __shfl_xor_sync(0xffffffffu, rmax0, 2));
        rmax1 = fmaxf(rmax1, __shfl_xor_sync(0xffffffffu, rmax1, 1));
        rmax1 = fmaxf(rmax1, __shfl_xor_sync(0xffffffffu, rmax1, 2));
        float mn0 = fmaxf(m0, rmax0), mn1 = fmaxf(m1, rmax1);
        float f0 = ex2(m0 - mn0), f1 = ex2(m1 - mn1);
        m0 = mn0; m1 = mn1;

        float rs0 = 0.f, rs1 = 0.f;
#pragma unroll
        for (int nt = 0; nt < 8; nt++)
#pragma unroll
            for (int e = 0; e < 4; e++) {
                float p = ex2(s[nt][e] - ((e & 2) ? mn1 : mn0));
                s[nt][e] = p;
                if (e & 2) rs1 += p; else rs0 += p;
            }
        rs0 += __shfl_xor_sync(0xffffffffu, rs0, 1);
        rs0 += __shfl_xor_sync(0xffffffffu, rs0, 2);
        rs1 += __shfl_xor_sync(0xffffffffu, rs1, 1);
        rs1 += __shfl_xor_sync(0xffffffffu, rs1, 2);
        l0 = l0 * f0 + rs0;
        l1 = l1 * f1 + rs1;
#pragma unroll
        for (int nt = 0; nt < 8; nt++) {
            o[nt][0] *= f0; o[nt][1] *= f0;
            o[nt][2] *= f1; o[nt][3] *= f1;
        }

        // ---- O += P @ V : P from registers (bf16 split), V via ldmatrix.trans ----
#pragma unroll
        for (int kt = 0; kt < 4; kt++) {
            unsigned p0[4], p1[4];
            {
                float c0 = s[2 * kt][0],     c1 = s[2 * kt][1];
                float c2 = s[2 * kt][2],     c3 = s[2 * kt][3];
                float d0 = s[2 * kt + 1][0], d1 = s[2 * kt + 1][1];
                float d2 = s[2 * kt + 1][2], d3 = s[2 * kt + 1][3];
                PK_BF2(p0[0], c0, c1); PK_BF2(p0[1], c2, c3);
                PK_BF2(p0[2], d0, d1); PK_BF2(p0[3], d2, d3);
                PK_BF2(p1[0], c0 - bf_round(c0), c1 - bf_round(c1));
                PK_BF2(p1[1], c2 - bf_round(c2), c3 - bf_round(c3));
                PK_BF2(p1[2], d0 - bf_round(d0), d1 - bf_round(d1));
                PK_BF2(p1[3], d2 - bf_round(d2), d3 - bf_round(d3));
            }
            unsigned vb0[4][4], vb1[4][4];
#pragma unroll
            for (int dg = 0; dg < 4; dg++) {
                unsigned vo = smb + OFF_V0 +
                              (unsigned)((kt * 16 + vrow) * VRB) + (unsigned)(dg * 32) + vc16;
                LDSM_T_X4(vb0[dg][0], vb0[dg][1], vb0[dg][2], vb0[dg][3], vo);
                LDSM_T_X4(vb1[dg][0], vb1[dg][1], vb1[dg][2], vb1[dg][3],
                          vo + (OFF_V1 - OFF_V0));
            }
#pragma unroll
            for (int nt = 0; nt < 8; nt++)
                MMA_BF16(o[nt], p0, vb0[nt >> 1][(nt & 1) * 2], vb0[nt >> 1][(nt & 1) * 2 + 1]);
#pragma unroll
            for (int nt = 0; nt < 8; nt++)
                MMA_BF16(o[nt], p1, vb0[nt >> 1][(nt & 1) * 2], vb0[nt >> 1][(nt & 1) * 2 + 1]);
#pragma unroll
            for (int nt = 0; nt < 8; nt++)
                MMA_BF16(o[nt], p0, vb1[nt >> 1][(nt & 1) * 2], vb1[nt >> 1][(nt & 1) * 2 + 1]);
        }
    }

    // ---- normalize + write bf16 split planes ----
    float inv0 = 1.f / l0, inv1 = 1.f / l1;
    const int ig0 = i0 + wid * 16 + g;
#pragma unroll
    for (int nt = 0; nt < 8; nt++) {
        int d = nt * 8 + 2 * t;
        size_t idx0 = ((size_t)(b * Nq + ig0) * Hq + h) * DHq + d;
        size_t idx1 = idx0 + (size_t)8 * HDq;
        float v0 = o[nt][0] * inv0, v1 = o[nt][1] * inv0;
        float v2 = o[nt][2] * inv1, v3 = o[nt][3] * inv1;
        unsigned u;
        PK_BF2(u, v0, v1);                               *(unsigned*)(g_ab0 + idx0) = u;
        PK_BF2(u, v0 - bf_round(v0), v1 - bf_round(v1)); *(unsigned*)(g_ab1 + idx0) = u;
        PK_BF2(u, v2, v3);                               *(unsigned*)(g_ab0 + idx1) = u;
        PK_BF2(u, v2 - bf_round(v2), v3 - bf_round(v3)); *(unsigned*)(g_ab1 + idx1) = u;
    }
}

// ---------------------------------------------------------------------------
extern "C" void kernel_launch(void* const* d_in, const int* in_sizes, int n_in,
                              void* d_out, int out_size)
{
    (void)in_sizes; (void)n_in; (void)out_size;
    const float* x  = (const float*)d_in[0];
    const float* Wq = (const float*)d_in[1];
    const float* Wk = (const float*)d_in[2];
    const float* Wv = (const float*)d_in[3];
    const float* Wo = (const float*)d_in[4];
    const float* bo = (const float*)d_in[5];
    float* out = (float*)d_out;

    cudaFuncSetAttribute(qkv_gemm_p, cudaFuncAttributeMaxDynamicSharedMemorySize, GEMMP_SMEM);
    cudaFuncSetAttribute(out_proj_p, cudaFuncAttributeMaxDynamicSharedMemorySize, GEMMP_SMEM);
    cudaFuncSetAttribute(flash_bf,   cudaFuncAttributeMaxDynamicSharedMemorySize, FL_SMEM);

    split_x_b<<<Mq * Dq / 4 / 256, 256>>>(x);
    split_wT_b<<<dim3(32, 16), 256>>>(Wq, 0);
    split_wT_b<<<dim3(32, 16), 256>>>(Wk, 1);
    split_wT_b<<<dim3(32, 16), 256>>>(Wv, 2);
    split_wT_b<<<dim3(32, 16), 256>>>(Wo, 3);

    qkv_gemm_p<<<dim3(24, 32), 256, GEMMP_SMEM>>>();
    flash_bf<<<dim3(16, Hq, Bq), 256, FL_SMEM>>>();
    out_proj_p<<<dim3(8, 32), 256, GEMMP_SMEM>>>(bo, out);
}

// round 11
// speedup vs baseline: 1.7435x; 1.0412x over previous
#include <cuda_runtime.h>
#include <cuda_bf16.h>

#define Bq 2
#define Nq 2048
#define Hq 16
#define DHq 64
#define Dq 1024
#define HDq (Hq * DHq)   // 1024
#define Mq (Bq * Nq)     // 4096

#define PLX ((size_t)Mq * Dq)
#define PLW ((size_t)Dq * Dq)
#define PLA ((size_t)Mq * HDq)

// bf16 split planes
__device__ __nv_bfloat16 g_xb0[PLX], g_xb1[PLX];
__device__ __nv_bfloat16 g_wtb[8 * PLW];          // 4 weights x 2 planes, transposed [n][k]
__device__ __nv_bfloat16 g_qb0[PLA], g_qb1[PLA];
__device__ __nv_bfloat16 g_kb0[PLA], g_kb1[PLA];
__device__ __nv_bfloat16 g_vb0[PLA], g_vb1[PLA];
__device__ __nv_bfloat16 g_ab0[PLA], g_ab1[PLA];

// ---------------------------------------------------------------------------
// helpers
// ---------------------------------------------------------------------------
__device__ __forceinline__ void split_bf16(float x, __nv_bfloat16& b0, __nv_bfloat16& b1)
{
    b0 = __float2bfloat16(x);
    b1 = __float2bfloat16(x - __bfloat162float(b0));
}

__device__ __forceinline__ float bf_round(float x)
{
    return __bfloat162float(__float2bfloat16(x));
}

__device__ __forceinline__ float ex2(float x)
{
    float r;
    asm("ex2.approx.f32 %0, %1;" : "=f"(r) : "f"(x));
    return r;
}

#define PK_BF2(d, a, b) \
    asm("cvt.rn.bf16x2.f32 %0, %1, %2;" : "=r"(d) : "f"(b), "f"(a))

#define MMA_BF16(d, a, b0_, b1_)                                              \
    asm volatile("mma.sync.aligned.m16n8k16.row.col.f32.bf16.bf16.f32 "       \
                 "{%0,%1,%2,%3}, {%4,%5,%6,%7}, {%8,%9}, {%0,%1,%2,%3};"      \
                 : "+f"(d[0]), "+f"(d[1]), "+f"(d[2]), "+f"(d[3])             \
                 : "r"(a[0]), "r"(a[1]), "r"(a[2]), "r"(a[3]),                \
                   "r"(b0_), "r"(b1_))

#define LDSM_X4(r0, r1, r2, r3, addr)                                         \
    asm volatile("ldmatrix.sync.aligned.m8n8.x4.shared.b16 {%0,%1,%2,%3}, [%4];" \
                 : "=r"(r0), "=r"(r1), "=r"(r2), "=r"(r3) : "r"(addr))

#define LDSM_T_X4(r0, r1, r2, r3, addr)                                       \
    asm volatile("ldmatrix.sync.aligned.m8n8.x4.trans.shared.b16 {%0,%1,%2,%3}, [%4];" \
                 : "=r"(r0), "=r"(r1), "=r"(r2), "=r"(r3) : "r"(addr))

#define CP_A16(dst, src) \
    asm volatile("cp.async.cg.shared.global [%0], [%1], 16;" :: "r"(dst), "l"(src))
#define CP_COMMIT() asm volatile("cp.async.commit_group;")
#define CP_WAIT0()  asm volatile("cp.async.wait_group 0;" ::: "memory")
#define CP_WAIT1()  asm volatile("cp.async.wait_group 1;" ::: "memory")

// ---------------------------------------------------------------------------
// split kernels
// ---------------------------------------------------------------------------
__global__ __launch_bounds__(256) void split_x_b(const float* __restrict__ in)
{
    size_t i = (size_t)blockIdx.x * 256 + threadIdx.x;   // over float4
    float4 v = ((const float4*)in)[i];
    __nv_bfloat16 a0, a1, b0, b1, c0, c1, d0, d1;
    split_bf16(v.x, a0, a1); split_bf16(v.y, b0, b1);
    split_bf16(v.z, c0, c1); split_bf16(v.w, d0, d1);
    __nv_bfloat162 p;
    p.x = a0; p.y = b0; *(__nv_bfloat162*)(g_xb0 + i * 4)     = p;
    p.x = c0; p.y = d0; *(__nv_bfloat162*)(g_xb0 + i * 4 + 2) = p;
    p.x = a1; p.y = b1; *(__nv_bfloat162*)(g_xb1 + i * 4)     = p;
    p.x = c1; p.y = d1; *(__nv_bfloat162*)(g_xb1 + i * 4 + 2) = p;
}

__global__ __launch_bounds__(256) void split_wT_b(const float* __restrict__ W, int w)
{
    int n  = blockIdx.x * 32 + (threadIdx.x & 31);
    int k0 = blockIdx.y * 64 + (threadIdx.x >> 5) * 8;
    __nv_bfloat16 b0[8], b1[8];
#pragma unroll
    for (int j = 0; j < 8; j++) {
        float v = W[(size_t)(k0 + j) * Dq + n];
        split_bf16(v, b0[j], b1[j]);
    }
    __nv_bfloat16* d0 = g_wtb + (size_t)(w * 2 + 0) * PLW + (size_t)n * Dq + k0;
    __nv_bfloat16* d1 = g_wtb + (size_t)(w * 2 + 1) * PLW + (size_t)n * Dq + k0;
#pragma unroll
    for (int j = 0; j < 8; j += 2) {
        __nv_bfloat162 p;
        p.x = b0[j]; p.y = b0[j + 1]; *(__nv_bfloat162*)(d0 + j) = p;
        p.x = b1[j]; p.y = b1[j + 1]; *(__nv_bfloat162*)(d1 + j) = p;
    }
}

// ---------------------------------------------------------------------------
// bf16x3 m16n8k16 GEMM, BK=32 (halved barrier count vs R9).
// smem tiles [128][32]bf16 padded to 80 B rows (LDSM conflict-free:
// row addrs mod 128 = {0,80,32,112,64,16,96,48}).
// ---------------------------------------------------------------------------
#define TPL 10240
#define STAGE_B 40960
#define GEMMP_SMEM (2 * STAGE_B)   // 81920

__device__ __forceinline__ void gemm_pipe_bf(const __nv_bfloat16* __restrict__ Ab0,
                                             const __nv_bfloat16* __restrict__ Ab1,
                                             const __nv_bfloat16* __restrict__ Wb0,
                                             const __nv_bfloat16* __restrict__ Wb1,
                                             __nv_bfloat16* __restrict__ Cb0,
                                             __nv_bfloat16* __restrict__ Cb1,
                                             float* __restrict__ Cf,
                                             const float* __restrict__ bias,
                                             int rowBlk, int colBlk)
{
    extern __shared__ float sm[];
    const unsigned smb = (unsigned)__cvta_generic_to_shared(sm);
    const int tid = threadIdx.x;
    const int wid = tid >> 5, lane = tid & 31;
    const int g = lane >> 2, t = lane & 3;
    const int wm = (wid & 3) * 32, wn = (wid >> 2) * 64;

    const size_t arow = (size_t)rowBlk * 128;
    const int ccol = colBlk * 128;

    const int quad = lane >> 3, lrow = lane & 7;
    const unsigned lmoff = (unsigned)(((quad & 1) * 8 + lrow) * 80 + (quad >> 1) * 16);

    float acc[2][8][4] = {};

#define PREFB(st, k0)                                                          \
    {                                                                          \
        unsigned base = smb + (st) * STAGE_B;                                  \
        _Pragma("unroll")                                                      \
        for (int i_ = 0; i_ < 2; i_++) {                                       \
            int idx = tid * 2 + i_;                                            \
            int r = idx >> 2, c4 = idx & 3;                                    \
            unsigned so = (unsigned)(r * 80 + c4 * 16);                        \
            CP_A16(base + 0 * TPL + so, Ab0 + (arow + r) * Dq + (k0) + c4 * 8);\
            CP_A16(base + 1 * TPL + so, Ab1 + (arow + r) * Dq + (k0) + c4 * 8);\
            CP_A16(base + 2 * TPL + so, Wb0 + (size_t)(ccol + r) * Dq + (k0) + c4 * 8); \
            CP_A16(base + 3 * TPL + so, Wb1 + (size_t)(ccol + r) * Dq + (k0) + c4 * 8); \
        }                                                                      \
    }

    PREFB(0, 0);
    CP_COMMIT();

    const int nch = Dq / 32;   // 32
    for (int chn = 0; chn < nch; chn++) {
        if (chn + 1 < nch) {
            PREFB((chn + 1) & 1, (chn + 1) * 32);
            CP_COMMIT();
            CP_WAIT1();
        } else {
            CP_WAIT0();
        }
        __syncthreads();

        const unsigned stg = smb + (chn & 1) * STAGE_B;

#pragma unroll
        for (int half = 0; half < 2; half++) {
            const unsigned co = (unsigned)(half * 32);
            unsigned af0[2][4], af1[2][4];
#pragma unroll
            for (int mt = 0; mt < 2; mt++) {
                unsigned ao = stg + (unsigned)((wm + mt * 16) * 80) + lmoff + co;
                LDSM_X4(af0[mt][0], af0[mt][1], af0[mt][2], af0[mt][3], ao);
                LDSM_X4(af1[mt][0], af1[mt][1], af1[mt][2], af1[mt][3], ao + TPL);
            }
            unsigned bf0[4][4], bf1[4][4];
#pragma unroll
            for (int np = 0; np < 4; np++) {
                unsigned wo = stg + 2 * TPL + (unsigned)((wn + np * 16) * 80) + lmoff + co;
                LDSM_X4(bf0[np][0], bf0[np][1], bf0[np][2], bf0[np][3], wo);
                LDSM_X4(bf1[np][0], bf1[np][1], bf1[np][2], bf1[np][3], wo + TPL);
            }
#pragma unroll
            for (int mt = 0; mt < 2; mt++)
#pragma unroll
                for (int nt = 0; nt < 8; nt++)
                    MMA_BF16(acc[mt][nt], af0[mt], bf0[nt >> 1][nt & 1], bf0[nt >> 1][(nt & 1) + 2]);
#pragma unroll
            for (int mt = 0; mt < 2; mt++)
#pragma unroll
                for (int nt = 0; nt < 8; nt++)
                    MMA_BF16(acc[mt][nt], af1[mt], bf0[nt >> 1][nt & 1], bf0[nt >> 1][(nt & 1) + 2]);
#pragma unroll
            for (int mt = 0; mt < 2; mt++)
#pragma unroll
                for (int nt = 0; nt < 8; nt++)
                    MMA_BF16(acc[mt][nt], af0[mt], bf1[nt >> 1][nt & 1], bf1[nt >> 1][(nt & 1) + 2]);
        }
        __syncthreads();
    }

#pragma unroll
    for (int mt = 0; mt < 2; mt++) {
        size_t r0 = arow + wm + mt * 16 + g;
#pragma unroll
        for (int nt = 0; nt < 8; nt++) {
            int c = ccol + wn + nt * 8 + 2 * t;
            if (Cb0) {
                float v0 = acc[mt][nt][0], v1 = acc[mt][nt][1];
                float v2 = acc[mt][nt][2], v3 = acc[mt][nt][3];
                unsigned u;
                PK_BF2(u, v0, v1);                               *(unsigned*)(Cb0 + r0 * Dq + c) = u;
                PK_BF2(u, v0 - bf_round(v0), v1 - bf_round(v1)); *(unsigned*)(Cb1 + r0 * Dq + c) = u;
                PK_BF2(u, v2, v3);                               *(unsigned*)(Cb0 + (r0 + 8) * Dq + c) = u;
                PK_BF2(u, v2 - bf_round(v2), v3 - bf_round(v3)); *(unsigned*)(Cb1 + (r0 + 8) * Dq + c) = u;
            } else {
                float b0 = bias[c], b1 = bias[c + 1];
                *(float2*)(Cf + r0 * Dq + c) =
                    make_float2(acc[mt][nt][0] + b0, acc[mt][nt][1] + b1);
                *(float2*)(Cf + (r0 + 8) * Dq + c) =
                    make_float2(acc[mt][nt][2] + b0, acc[mt][nt][3] + b1);
            }
        }
    }
#undef PREFB
}

__global__ __launch_bounds__(256, 2) void qkv_gemm_p()
{
    int w = blockIdx.x >> 3, colBlk = blockIdx.x & 7;
    __nv_bfloat16* C0 = (w == 0) ? g_qb0 : (w == 1) ? g_kb0 : g_vb0;
    __nv_bfloat16* C1 = (w == 0) ? g_qb1 : (w == 1) ? g_kb1 : g_vb1;
    gemm_pipe_bf(g_xb0, g_xb1,
                 g_wtb + (size_t)(w * 2) * PLW, g_wtb + (size_t)(w * 2 + 1) * PLW,
                 C0, C1, nullptr, nullptr, blockIdx.y, colBlk);
}

__global__ __launch_bounds__(256, 2) void out_proj_p(const float* __restrict__ bo,
                                                     float* __restrict__ out)
{
    gemm_pipe_bf(g_ab0, g_ab1,
                 g_wtb + (size_t)6 * PLW, g_wtb + (size_t)7 * PLW,
                 nullptr, nullptr, out, bo, blockIdx.y, blockIdx.x);
}

// ---------------------------------------------------------------------------
// bf16x3 flash attention, FA2 style + DOUBLE-BUFFERED K/V (2-stage cp.async).
// BR=128 (8 warps x 16 rows), BC=64. ALiBi + causal, log2-domain softmax.
// smem: Q0 Q1 [128][64]bf16 (144 B rows), 2 stages x {K0 K1 V0 V1}[64][64].
// ---------------------------------------------------------------------------
#define VRB 144
#define OFF_Q0 0
#define OFF_Q1 18432
#define FL_STG0 36864
#define FL_PL 9216            // one 64x64 plane (144 B rows)
#define FL_STG_SZ (4 * FL_PL) // 36864
#define FL_SMEM (FL_STG0 + 2 * FL_STG_SZ)   // 110592

__global__ __launch_bounds__(256) void flash_bf()
{
    extern __shared__ char smc[];
    const unsigned smb = (unsigned)__cvta_generic_to_shared(smc);
    const int tid = threadIdx.x, wid = tid >> 5, lane = tid & 31;
    const int g = lane >> 2, t = lane & 3;
    const int quad = lane >> 3, lrow = lane & 7;
    const int it = (int)gridDim.x - 1 - (int)blockIdx.x;   // heavy tiles first
    const int i0 = it * 128;
    const int h = blockIdx.y, b = blockIdx.z;
    const float slope_l2 = exp2f(-0.5f * (float)(h + 1)) * 1.44269504f;
    const float sscale   = 0.125f * 1.44269504f;

    const unsigned lmoff = (unsigned)(((quad & 1) * 8 + lrow) * VRB + (quad >> 1) * 16);
    const unsigned vrow  = (unsigned)(lane & 15);
    const unsigned vc16  = (unsigned)(lane >> 4) * 16;

#define FL_LOAD_TILE(j0_, sbase_)                                              \
    {                                                                          \
        size_t kb_ = ((size_t)(b * Nq + (j0_)) * Hq + h) * DHq;                \
        _Pragma("unroll")                                                      \
        for (int itr_ = 0; itr_ < 2; itr_++) {                                 \
            int idx_ = itr_ * 256 + tid;                                       \
            int row_ = idx_ >> 3, ch_ = idx_ & 7;                              \
            size_t src_ = kb_ + (size_t)row_ * HDq + ch_ * 8;                  \
            unsigned so_ = (unsigned)(row_ * VRB + ch_ * 16);                  \
            CP_A16((sbase_) + 0 * FL_PL + so_, g_kb0 + src_);                  \
            CP_A16((sbase_) + 1 * FL_PL + so_, g_kb1 + src_);                  \
            CP_A16((sbase_) + 2 * FL_PL + so_, g_vb0 + src_);                  \
            CP_A16((sbase_) + 3 * FL_PL + so_, g_vb1 + src_);                  \
        }                                                                      \
    }

    // ---- prologue: Q + first K/V tile in one commit group ----
    {
        size_t qb = ((size_t)(b * Nq + i0) * Hq + h) * DHq;
#pragma unroll
        for (int itr = 0; itr < 4; itr++) {
            int idx = itr * 256 + tid;
            int row = idx >> 3, ch = idx & 7;
            size_t src = qb + (size_t)row * HDq + ch * 8;
            CP_A16(smb + OFF_Q0 + (unsigned)(row * VRB + ch * 16), g_qb0 + src);
            CP_A16(smb + OFF_Q1 + (unsigned)(row * VRB + ch * 16), g_qb1 + src);
        }
        FL_LOAD_TILE(0, smb + FL_STG0);
        CP_COMMIT();
    }

    float o[8][4] = {};
    float m0 = -1e30f, m1 = -1e30f, l0 = 0.f, l1 = 0.f;

    const int njt = 2 * (it + 1);
    for (int jt = 0; jt < njt; jt++) {
        const int j0 = jt * 64;

        // prefetch next tile into the other stage, then wait on current
        if (jt + 1 < njt) {
            FL_LOAD_TILE(j0 + 64, smb + FL_STG0 + (unsigned)(((jt + 1) & 1) * FL_STG_SZ));
            CP_COMMIT();
            CP_WAIT1();
        } else {
            CP_WAIT0();
        }
        __syncthreads();

        const unsigned kstg = smb + FL_STG0 + (unsigned)((jt & 1) * FL_STG_SZ);

        // ---- S = Q @ K^T : warp tile m16 x n64, 4 k16 chunks ----
        float s[8][4] = {};
#pragma unroll
        for (int kt = 0; kt < 4; kt++) {
            unsigned a0[4], a1[4];
            unsigned qo = smb + OFF_Q0 + (unsigned)(wid * 16) * VRB + lmoff + kt * 32;
            LDSM_X4(a0[0], a0[1], a0[2], a0[3], qo);
            LDSM_X4(a1[0], a1[1], a1[2], a1[3], qo + (OFF_Q1 - OFF_Q0));
            unsigned kb0[4][4], kb1[4][4];
#pragma unroll
            for (int grp = 0; grp < 4; grp++) {
                unsigned ko = kstg + (unsigned)(grp * 16) * VRB + lmoff + kt * 32;
                LDSM_X4(kb0[grp][0], kb0[grp][1], kb0[grp][2], kb0[grp][3], ko);
                LDSM_X4(kb1[grp][0], kb1[grp][1], kb1[grp][2], kb1[grp][3], ko + FL_PL);
            }
#pragma unroll
            for (int nt = 0; nt < 8; nt++)
                MMA_BF16(s[nt], a0, kb0[nt >> 1][nt & 1], kb0[nt >> 1][(nt & 1) + 2]);
#pragma unroll
            for (int nt = 0; nt < 8; nt++)
                MMA_BF16(s[nt], a1, kb0[nt >> 1][nt & 1], kb0[nt >> 1][(nt & 1) + 2]);
#pragma unroll
            for (int nt = 0; nt < 8; nt++)
                MMA_BF16(s[nt], a0, kb1[nt >> 1][nt & 1], kb1[nt >> 1][(nt & 1) + 2]);
        }

        // ---- scale + ALiBi + causal, row stats ----
        float rmax0 = -1e30f, rmax1 = -1e30f;
        const int ig0 = i0 + wid * 16 + g;
#pragma unroll
        for (int nt = 0; nt < 8; nt++)
#pragma unroll
            for (int e = 0; e < 4; e++) {
                int jg = j0 + nt * 8 + 2 * t + (e & 1);
                int ig = ig0 + ((e & 2) ? 8 : 0);
                float v = s[nt][e] * sscale + slope_l2 * (float)(ig - jg);
                if (jg > ig) v = -1e30f;
                s[nt][e] = v;
                if (e & 2) rmax1 = fmaxf(rmax1, v); else rmax0 = fmaxf(rmax0, v);
            }
        rmax0 = fmaxf(rmax0, __shfl_xor_sync(0xffffffffu, rmax0, 1));
        rmax0 = fmaxf(rmax0, __shfl_xor_sync(0xffffffffu, rmax0, 2));
        rmax1 = fmaxf(rmax1, __shfl_xor_sync(0xffffffffu, rmax1, 1));
        rmax1 = fmaxf(rmax1, __shfl_xor_sync(0xffffffffu, rmax1, 2));
        float mn0 = fmaxf(m0, rmax0), mn1 = fmaxf(m1, rmax1);
        float f0 = ex2(m0 - mn0), f1 = ex2(m1 - mn1);
        m0 = mn0; m1 = mn1;

        float rs0 = 0.f, rs1 = 0.f;
#pragma unroll
        for (int nt = 0; nt < 8; nt++)
#pragma unroll
            for (int e = 0; e < 4; e++) {
                float p = ex2(s[nt][e] - ((e & 2) ? mn1 : mn0));
                s[nt][e] = p;
                if (e & 2) rs1 += p; else rs0 += p;
            }
        rs0 += __shfl_xor_sync(0xffffffffu, rs0, 1);
        rs0 += __shfl_xor_sync(0xffffffffu, rs0, 2);
        rs1 += __shfl_xor_sync(0xffffffffu, rs1, 1);
        rs1 += __shfl_xor_sync(0xffffffffu, rs1, 2);
        l0 = l0 * f0 + rs0;
        l1 = l1 * f1 + rs1;
#pragma unroll
        for (int nt = 0; nt < 8; nt++) {
            o[nt][0] *= f0; o[nt][1] *= f0;
            o[nt][2] *= f1; o[nt][3] *= f1;
        }

        // ---- O += P @ V : P in registers (bf16 split), V via ldmatrix.trans ----
#pragma unroll
        for (int kt = 0; kt < 4; kt++) {
            unsigned p0[4], p1[4];
            {
                float c0 = s[2 * kt][0],     c1 = s[2 * kt][1];
                float c2 = s[2 * kt][2],     c3 = s[2 * kt][3];
                float d0 = s[2 * kt + 1][0], d1 = s[2 * kt + 1][1];
                float d2 = s[2 * kt + 1][2], d3 = s[2 * kt + 1][3];
                PK_BF2(p0[0], c0, c1); PK_BF2(p0[1], c2, c3);
                PK_BF2(p0[2], d0, d1); PK_BF2(p0[3], d2, d3);
                PK_BF2(p1[0], c0 - bf_round(c0), c1 - bf_round(c1));
                PK_BF2(p1[1], c2 - bf_round(c2), c3 - bf_round(c3));
                PK_BF2(p1[2], d0 - bf_round(d0), d1 - bf_round(d1));
                PK_BF2(p1[3], d2 - bf_round(d2), d3 - bf_round(d3));
            }
            unsigned vb0[4][4], vb1[4][4];
#pragma unroll
            for (int dg = 0; dg < 4; dg++) {
                unsigned vo = kstg + 2 * FL_PL +
                              (unsigned)((kt * 16 + vrow) * VRB) + (unsigned)(dg * 32) + vc16;
                LDSM_T_X4(vb0[dg][0], vb0[dg][1], vb0[dg][2], vb0[dg][3], vo);
                LDSM_T_X4(vb1[dg][0], vb1[dg][1], vb1[dg][2], vb1[dg][3], vo + FL_PL);
            }
#pragma unroll
            for (int nt = 0; nt < 8; nt++)
                MMA_BF16(o[nt], p0, vb0[nt >> 1][(nt & 1) * 2], vb0[nt >> 1][(nt & 1) * 2 + 1]);
#pragma unroll
            for (int nt = 0; nt < 8; nt++)
                MMA_BF16(o[nt], p1, vb0[nt >> 1][(nt & 1) * 2], vb0[nt >> 1][(nt & 1) * 2 + 1]);
#pragma unroll
            for (int nt = 0; nt < 8; nt++)
                MMA_BF16(o[nt], p0, vb1[nt >> 1][(nt & 1) * 2], vb1[nt >> 1][(nt & 1) * 2 + 1]);
        }
        __syncthreads();   // all reads of stage (jt&1) done before tile jt+2 loads overwrite it
    }

    // ---- normalize + write bf16 split planes ----
    float inv0 = 1.f / l0, inv1 = 1.f / l1;
    const int ig0 = i0 + wid * 16 + g;
#pragma unroll
    for (int nt = 0; nt < 8; nt++) {
        int d = nt * 8 + 2 * t;
        size_t idx0 = ((size_t)(b * Nq + ig0) * Hq + h) * DHq + d;
        size_t idx1 = idx0 + (size_t)8 * HDq;
        float v0 = o[nt][0] * inv0, v1 = o[nt][1] * inv0;
        float v2 = o[nt][2] * inv1, v3 = o[nt][3] * inv1;
        unsigned u;
        PK_BF2(u, v0, v1);                               *(unsigned*)(g_ab0 + idx0) = u;
        PK_BF2(u, v0 - bf_round(v0), v1 - bf_round(v1)); *(unsigned*)(g_ab1 + idx0) = u;
        PK_BF2(u, v2, v3);                               *(unsigned*)(g_ab0 + idx1) = u;
        PK_BF2(u, v2 - bf_round(v2), v3 - bf_round(v3)); *(unsigned*)(g_ab1 + idx1) = u;
    }
#undef FL_LOAD_TILE
}

// ---------------------------------------------------------------------------
extern "C" void kernel_launch(void* const* d_in, const int* in_sizes, int n_in,
                              void* d_out, int out_size)
{
    (void)in_sizes; (void)n_in; (void)out_size;
    const float* x  = (const float*)d_in[0];
    const float* Wq = (const float*)d_in[1];
    const float* Wk = (const float*)d_in[2];
    const float* Wv = (const float*)d_in[3];
    const float* Wo = (const float*)d_in[4];
    const float* bo = (const float*)d_in[5];
    float* out = (float*)d_out;

    cudaFuncSetAttribute(qkv_gemm_p, cudaFuncAttributeMaxDynamicSharedMemorySize, GEMMP_SMEM);
    cudaFuncSetAttribute(out_proj_p, cudaFuncAttributeMaxDynamicSharedMemorySize, GEMMP_SMEM);
    cudaFuncSetAttribute(flash_bf,   cudaFuncAttributeMaxDynamicSharedMemorySize, FL_SMEM);

    split_x_b<<<Mq * Dq / 4 / 256, 256>>>(x);
    split_wT_b<<<dim3(32, 16), 256>>>(Wq, 0);
    split_wT_b<<<dim3(32, 16), 256>>>(Wk, 1);
    split_wT_b<<<dim3(32, 16), 256>>>(Wv, 2);
    split_wT_b<<<dim3(32, 16), 256>>>(Wo, 3);

    qkv_gemm_p<<<dim3(24, 32), 256, GEMMP_SMEM>>>();
    flash_bf<<<dim3(16, Hq, Bq), 256, FL_SMEM>>>();
    out_proj_p<<<dim3(8, 32), 256, GEMMP_SMEM>>>(bo, out);
}

// round 12
// speedup vs baseline: 1.7812x; 1.0216x over previous
#include <cuda_runtime.h>
#include <cuda_bf16.h>

#define Bq 2
#define Nq 2048
#define Hq 16
#define DHq 64
#define Dq 1024
#define HDq (Hq * DHq)   // 1024
#define Mq (Bq * Nq)     // 4096

#define PLX ((size_t)Mq * Dq)
#define PLW ((size_t)Dq * Dq)
#define PLA ((size_t)Mq * HDq)

// bf16 split planes
__device__ __nv_bfloat16 g_xb0[PLX], g_xb1[PLX];
__device__ __nv_bfloat16 g_wtb[8 * PLW];          // 4 weights x 2 planes, transposed [n][k]
__device__ __nv_bfloat16 g_qb0[PLA], g_qb1[PLA];
__device__ __nv_bfloat16 g_kb0[PLA], g_kb1[PLA];
__device__ __nv_bfloat16 g_vb0[PLA], g_vb1[PLA];
__device__ __nv_bfloat16 g_ab0[PLA], g_ab1[PLA];

// ---------------------------------------------------------------------------
// helpers
// ---------------------------------------------------------------------------
__device__ __forceinline__ void split_bf16(float x, __nv_bfloat16& b0, __nv_bfloat16& b1)
{
    b0 = __float2bfloat16(x);
    b1 = __float2bfloat16(x - __bfloat162float(b0));
}

__device__ __forceinline__ float bf_round(float x)
{
    return __bfloat162float(__float2bfloat16(x));
}

__device__ __forceinline__ float ex2(float x)
{
    float r;
    asm("ex2.approx.f32 %0, %1;" : "=f"(r) : "f"(x));
    return r;
}

#define PK_BF2(d, a, b) \
    asm("cvt.rn.bf16x2.f32 %0, %1, %2;" : "=r"(d) : "f"(b), "f"(a))

#define MMA_BF16(d, a, b0_, b1_)                                              \
    asm volatile("mma.sync.aligned.m16n8k16.row.col.f32.bf16.bf16.f32 "       \
                 "{%0,%1,%2,%3}, {%4,%5,%6,%7}, {%8,%9}, {%0,%1,%2,%3};"      \
                 : "+f"(d[0]), "+f"(d[1]), "+f"(d[2]), "+f"(d[3])             \
                 : "r"(a[0]), "r"(a[1]), "r"(a[2]), "r"(a[3]),                \
                   "r"(b0_), "r"(b1_))

#define LDSM_X4(r0, r1, r2, r3, addr)                                         \
    asm volatile("ldmatrix.sync.aligned.m8n8.x4.shared.b16 {%0,%1,%2,%3}, [%4];" \
                 : "=r"(r0), "=r"(r1), "=r"(r2), "=r"(r3) : "r"(addr))

#define LDSM_T_X4(r0, r1, r2, r3, addr)                                       \
    asm volatile("ldmatrix.sync.aligned.m8n8.x4.trans.shared.b16 {%0,%1,%2,%3}, [%4];" \
                 : "=r"(r0), "=r"(r1), "=r"(r2), "=r"(r3) : "r"(addr))

#define CP_A16(dst, src) \
    asm volatile("cp.async.cg.shared.global [%0], [%1], 16;" :: "r"(dst), "l"(src))
#define CP_COMMIT() asm volatile("cp.async.commit_group;")
#define CP_WAIT0()  asm volatile("cp.async.wait_group 0;" ::: "memory")
#define CP_WAIT1()  asm volatile("cp.async.wait_group 1;" ::: "memory")
#define CP_WAIT2()  asm volatile("cp.async.wait_group 2;" ::: "memory")

// ---------------------------------------------------------------------------
// split kernels
// ---------------------------------------------------------------------------
__global__ __launch_bounds__(256) void split_x_b(const float* __restrict__ in)
{
    size_t i = (size_t)blockIdx.x * 256 + threadIdx.x;   // over float4
    float4 v = ((const float4*)in)[i];
    __nv_bfloat16 a0, a1, b0, b1, c0, c1, d0, d1;
    split_bf16(v.x, a0, a1); split_bf16(v.y, b0, b1);
    split_bf16(v.z, c0, c1); split_bf16(v.w, d0, d1);
    __nv_bfloat162 p;
    p.x = a0; p.y = b0; *(__nv_bfloat162*)(g_xb0 + i * 4)     = p;
    p.x = c0; p.y = d0; *(__nv_bfloat162*)(g_xb0 + i * 4 + 2) = p;
    p.x = a1; p.y = b1; *(__nv_bfloat162*)(g_xb1 + i * 4)     = p;
    p.x = c1; p.y = d1; *(__nv_bfloat162*)(g_xb1 + i * 4 + 2) = p;
}

// transpose + split via smem tile: Wt_p[n][k] = split(W[k][n]); coalesced both ways
__global__ __launch_bounds__(256) void split_wT_s(const float* __restrict__ W, int w)
{
    __shared__ float ts[64][68];
    const int tid = threadIdx.x;
    const int n0 = blockIdx.x * 64, k0 = blockIdx.y * 64;

#pragma unroll
    for (int i = 0; i < 4; i++) {
        int idx = i * 256 + tid;
        int kr = idx >> 4, c4 = idx & 15;
        float4 v = *(const float4*)(W + (size_t)(k0 + kr) * Dq + n0 + c4 * 4);
        ts[c4 * 4 + 0][kr] = v.x;
        ts[c4 * 4 + 1][kr] = v.y;
        ts[c4 * 4 + 2][kr] = v.z;
        ts[c4 * 4 + 3][kr] = v.w;
    }
    __syncthreads();

    const int n = tid >> 2, kc = (tid & 3) * 16;
    unsigned u0[8], u1[8];
#pragma unroll
    for (int j = 0; j < 8; j++) {
        float v0 = ts[n][kc + 2 * j], v1 = ts[n][kc + 2 * j + 1];
        float h0 = bf_round(v0), h1 = bf_round(v1);
        PK_BF2(u0[j], h0, h1);
        PK_BF2(u1[j], v0 - h0, v1 - h1);
    }
    __nv_bfloat16* d0 = g_wtb + (size_t)(w * 2 + 0) * PLW + (size_t)(n0 + n) * Dq + k0 + kc;
    __nv_bfloat16* d1 = g_wtb + (size_t)(w * 2 + 1) * PLW + (size_t)(n0 + n) * Dq + k0 + kc;
    *(uint4*)(d0)     = make_uint4(u0[0], u0[1], u0[2], u0[3]);
    *(uint4*)(d0 + 8) = make_uint4(u0[4], u0[5], u0[6], u0[7]);
    *(uint4*)(d1)     = make_uint4(u1[0], u1[1], u1[2], u1[3]);
    *(uint4*)(d1 + 8) = make_uint4(u1[4], u1[5], u1[6], u1[7]);
}

// ---------------------------------------------------------------------------
// bf16x3 m16n8k16 GEMM, BK=32, 2-stage cp.async (R10, proven).
// ---------------------------------------------------------------------------
#define TPL 10240
#define STAGE_B 40960
#define GEMMP_SMEM (2 * STAGE_B)   // 81920

__device__ __forceinline__ void gemm_pipe_bf(const __nv_bfloat16* __restrict__ Ab0,
                                             const __nv_bfloat16* __restrict__ Ab1,
                                             const __nv_bfloat16* __restrict__ Wb0,
                                             const __nv_bfloat16* __restrict__ Wb1,
                                             __nv_bfloat16* __restrict__ Cb0,
                                             __nv_bfloat16* __restrict__ Cb1,
                                             float* __restrict__ Cf,
                                             const float* __restrict__ bias,
                                             int rowBlk, int colBlk)
{
    extern __shared__ float sm[];
    const unsigned smb = (unsigned)__cvta_generic_to_shared(sm);
    const int tid = threadIdx.x;
    const int wid = tid >> 5, lane = tid & 31;
    const int g = lane >> 2, t = lane & 3;
    const int wm = (wid & 3) * 32, wn = (wid >> 2) * 64;

    const size_t arow = (size_t)rowBlk * 128;
    const int ccol = colBlk * 128;

    const int quad = lane >> 3, lrow = lane & 7;
    const unsigned lmoff = (unsigned)(((quad & 1) * 8 + lrow) * 80 + (quad >> 1) * 16);

    float acc[2][8][4] = {};

#define PREFB(st, k0)                                                          \
    {                                                                          \
        unsigned base = smb + (st) * STAGE_B;                                  \
        _Pragma("unroll")                                                      \
        for (int i_ = 0; i_ < 2; i_++) {                                       \
            int idx = tid * 2 + i_;                                            \
            int r = idx >> 2, c4 = idx & 3;                                    \
            unsigned so = (unsigned)(r * 80 + c4 * 16);                        \
            CP_A16(base + 0 * TPL + so, Ab0 + (arow + r) * Dq + (k0) + c4 * 8);\
            CP_A16(base + 1 * TPL + so, Ab1 + (arow + r) * Dq + (k0) + c4 * 8);\
            CP_A16(base + 2 * TPL + so, Wb0 + (size_t)(ccol + r) * Dq + (k0) + c4 * 8); \
            CP_A16(base + 3 * TPL + so, Wb1 + (size_t)(ccol + r) * Dq + (k0) + c4 * 8); \
        }                                                                      \
    }

    PREFB(0, 0);
    CP_COMMIT();

    const int nch = Dq / 32;   // 32
    for (int chn = 0; chn < nch; chn++) {
        if (chn + 1 < nch) {
            PREFB((chn + 1) & 1, (chn + 1) * 32);
            CP_COMMIT();
            CP_WAIT1();
        } else {
            CP_WAIT0();
        }
        __syncthreads();

        const unsigned stg = smb + (chn & 1) * STAGE_B;

#pragma unroll
        for (int half = 0; half < 2; half++) {
            const unsigned co = (unsigned)(half * 32);
            unsigned af0[2][4], af1[2][4];
#pragma unroll
            for (int mt = 0; mt < 2; mt++) {
                unsigned ao = stg + (unsigned)((wm + mt * 16) * 80) + lmoff + co;
                LDSM_X4(af0[mt][0], af0[mt][1], af0[mt][2], af0[mt][3], ao);
                LDSM_X4(af1[mt][0], af1[mt][1], af1[mt][2], af1[mt][3], ao + TPL);
            }
            unsigned bf0[4][4], bf1[4][4];
#pragma unroll
            for (int np = 0; np < 4; np++) {
                unsigned wo = stg + 2 * TPL + (unsigned)((wn + np * 16) * 80) + lmoff + co;
                LDSM_X4(bf0[np][0], bf0[np][1], bf0[np][2], bf0[np][3], wo);
                LDSM_X4(bf1[np][0], bf1[np][1], bf1[np][2], bf1[np][3], wo + TPL);
            }
#pragma unroll
            for (int mt = 0; mt < 2; mt++)
#pragma unroll
                for (int nt = 0; nt < 8; nt++)
                    MMA_BF16(acc[mt][nt], af0[mt], bf0[nt >> 1][nt & 1], bf0[nt >> 1][(nt & 1) + 2]);
#pragma unroll
            for (int mt = 0; mt < 2; mt++)
#pragma unroll
                for (int nt = 0; nt < 8; nt++)
                    MMA_BF16(acc[mt][nt], af1[mt], bf0[nt >> 1][nt & 1], bf0[nt >> 1][(nt & 1) + 2]);
#pragma unroll
            for (int mt = 0; mt < 2; mt++)
#pragma unroll
                for (int nt = 0; nt < 8; nt++)
                    MMA_BF16(acc[mt][nt], af0[mt], bf1[nt >> 1][nt & 1], bf1[nt >> 1][(nt & 1) + 2]);
        }
        __syncthreads();
    }

#pragma unroll
    for (int mt = 0; mt < 2; mt++) {
        size_t r0 = arow + wm + mt * 16 + g;
#pragma unroll
        for (int nt = 0; nt < 8; nt++) {
            int c = ccol + wn + nt * 8 + 2 * t;
            if (Cb0) {
                float v0 = acc[mt][nt][0], v1 = acc[mt][nt][1];
                float v2 = acc[mt][nt][2], v3 = acc[mt][nt][3];
                unsigned u;
                PK_BF2(u, v0, v1);                               *(unsigned*)(Cb0 + r0 * Dq + c) = u;
                PK_BF2(u, v0 - bf_round(v0), v1 - bf_round(v1)); *(unsigned*)(Cb1 + r0 * Dq + c) = u;
                PK_BF2(u, v2, v3);                               *(unsigned*)(Cb0 + (r0 + 8) * Dq + c) = u;
                PK_BF2(u, v2 - bf_round(v2), v3 - bf_round(v3)); *(unsigned*)(Cb1 + (r0 + 8) * Dq + c) = u;
            } else {
                float b0 = bias[c], b1 = bias[c + 1];
                *(float2*)(Cf + r0 * Dq + c) =
                    make_float2(acc[mt][nt][0] + b0, acc[mt][nt][1] + b1);
                *(float2*)(Cf + (r0 + 8) * Dq + c) =
                    make_float2(acc[mt][nt][2] + b0, acc[mt][nt][3] + b1);
            }
        }
    }
#undef PREFB
}

__global__ __launch_bounds__(256, 2) void qkv_gemm_p()
{
    int w = blockIdx.x >> 3, colBlk = blockIdx.x & 7;
    __nv_bfloat16* C0 = (w == 0) ? g_qb0 : (w == 1) ? g_kb0 : g_vb0;
    __nv_bfloat16* C1 = (w == 0) ? g_qb1 : (w == 1) ? g_kb1 : g_vb1;
    gemm_pipe_bf(g_xb0, g_xb1,
                 g_wtb + (size_t)(w * 2) * PLW, g_wtb + (size_t)(w * 2 + 1) * PLW,
                 C0, C1, nullptr, nullptr, blockIdx.y, colBlk);
}

__global__ __launch_bounds__(256, 2) void out_proj_p(const float* __restrict__ bo,
                                                     float* __restrict__ out)
{
    gemm_pipe_bf(g_ab0, g_ab1,
                 g_wtb + (size_t)6 * PLW, g_wtb + (size_t)7 * PLW,
                 nullptr, nullptr, out, bo, blockIdx.y, blockIdx.x);
}

// ---------------------------------------------------------------------------
// bf16x3 flash attention: Q fragments persistent in registers, 4-stage K/V
// ring with prefetch distance 2 and ONE barrier per tile.
// BR=128 (8 warps x 16 rows), BC=64. ALiBi + causal, log2-domain softmax.
// smem: 4 stages x {K0 K1 V0 V1}[64][64]bf16 (144 B rows) = 147456 B.
// Q staged through stage 0 region once at kernel start.
// ---------------------------------------------------------------------------
#define VRB 144
#define FL_PL 9216            // one 64x64 plane (144 B rows)
#define FL_STG_SZ (4 * FL_PL) // 36864
#define FL_SMEM (4 * FL_STG_SZ)   // 147456

__global__ __launch_bounds__(256) void flash_bf()
{
    extern __shared__ char smc[];
    const unsigned smb = (unsigned)__cvta_generic_to_shared(smc);
    const int tid = threadIdx.x, wid = tid >> 5, lane = tid & 31;
    const int g = lane >> 2, t = lane & 3;
    const int quad = lane >> 3, lrow = lane & 7;
    const int it = (int)gridDim.x - 1 - (int)blockIdx.x;   // heavy tiles first
    const int i0 = it * 128;
    const int h = blockIdx.y, b = blockIdx.z;
    const float slope_l2 = exp2f(-0.5f * (float)(h + 1)) * 1.44269504f;
    const float sscale   = 0.125f * 1.44269504f;

    const unsigned lmoff = (unsigned)(((quad & 1) * 8 + lrow) * VRB + (quad >> 1) * 16);
    const unsigned vrow  = (unsigned)(lane & 15);
    const unsigned vc16  = (unsigned)(lane >> 4) * 16;

#define FL_LOAD_TILE(j0_, sbase_)                                              \
    {                                                                          \
        size_t kb_ = ((size_t)(b * Nq + (j0_)) * Hq + h) * DHq;                \
        _Pragma("unroll")                                                      \
        for (int itr_ = 0; itr_ < 2; itr_++) {                                 \
            int idx_ = itr_ * 256 + tid;                                       \
            int row_ = idx_ >> 3, ch_ = idx_ & 7;                              \
            size_t src_ = kb_ + (size_t)row_ * HDq + ch_ * 8;                  \
            unsigned so_ = (unsigned)(row_ * VRB + ch_ * 16);                  \
            CP_A16((sbase_) + 0 * FL_PL + so_, g_kb0 + src_);                  \
            CP_A16((sbase_) + 1 * FL_PL + so_, g_kb1 + src_);                  \
            CP_A16((sbase_) + 2 * FL_PL + so_, g_vb0 + src_);                  \
            CP_A16((sbase_) + 3 * FL_PL + so_, g_vb1 + src_);                  \
        }                                                                      \
    }

    // ---- prologue: stage Q through smem, extract fragments to registers ----
    unsigned qf0[4][4], qf1[4][4];
    {
        size_t qb = ((size_t)(b * Nq + i0) * Hq + h) * DHq;
#pragma unroll
        for (int itr = 0; itr < 4; itr++) {
            int idx = itr * 256 + tid;
            int row = idx >> 3, ch = idx & 7;
            size_t src = qb + (size_t)row * HDq + ch * 8;
            CP_A16(smb + (unsigned)(row * VRB + ch * 16), g_qb0 + src);
            CP_A16(smb + 18432u + (unsigned)(row * VRB + ch * 16), g_qb1 + src);
        }
        CP_COMMIT();
        CP_WAIT0();
        __syncthreads();
#pragma unroll
        for (int kt = 0; kt < 4; kt++) {
            unsigned qo = smb + (unsigned)(wid * 16) * VRB + lmoff + kt * 32;
            LDSM_X4(qf0[kt][0], qf0[kt][1], qf0[kt][2], qf0[kt][3], qo);
            LDSM_X4(qf1[kt][0], qf1[kt][1], qf1[kt][2], qf1[kt][3], qo + 18432u);
        }
        __syncthreads();   // all Q reads done before K/V pipeline reuses smem
    }

    float o[8][4] = {};
    float m0 = -1e30f, m1 = -1e30f, l0 = 0.f, l1 = 0.f;

    const int njt = 2 * (it + 1);   // >= 2 always

    // preload tiles 0 and 1
    FL_LOAD_TILE(0, smb);
    CP_COMMIT();
    FL_LOAD_TILE(64, smb + FL_STG_SZ);
    CP_COMMIT();

    for (int jt = 0; jt < njt; jt++) {
        const int j0 = jt * 64;

        if (jt + 2 < njt)
            FL_LOAD_TILE(j0 + 128, smb + (unsigned)(((jt + 2) & 3) * FL_STG_SZ));
        CP_COMMIT();   // possibly-empty group keeps accounting uniform
        CP_WAIT2();    // <=2 groups in flight -> tile jt resident
        __syncthreads();

        const unsigned kstg = smb + (unsigned)((jt & 3) * FL_STG_SZ);

        // ---- S = Q @ K^T : warp tile m16 x n64, 4 k16 chunks ----
        float s[8][4] = {};
#pragma unroll
        for (int kt = 0; kt < 4; kt++) {
            unsigned kb0[4][4], kb1[4][4];
#pragma unroll
            for (int grp = 0; grp < 4; grp++) {
                unsigned ko = kstg + (unsigned)(grp * 16) * VRB + lmoff + kt * 32;
                LDSM_X4(kb0[grp][0], kb0[grp][1], kb0[grp][2], kb0[grp][3], ko);
                LDSM_X4(kb1[grp][0], kb1[grp][1], kb1[grp][2], kb1[grp][3], ko + FL_PL);
            }
#pragma unroll
            for (int nt = 0; nt < 8; nt++)
                MMA_BF16(s[nt], qf0[kt], kb0[nt >> 1][nt & 1], kb0[nt >> 1][(nt & 1) + 2]);
#pragma unroll
            for (int nt = 0; nt < 8; nt++)
                MMA_BF16(s[nt], qf1[kt], kb0[nt >> 1][nt & 1], kb0[nt >> 1][(nt & 1) + 2]);
#pragma unroll
            for (int nt = 0; nt < 8; nt++)
                MMA_BF16(s[nt], qf0[kt], kb1[nt >> 1][nt & 1], kb1[nt >> 1][(nt & 1) + 2]);
        }

        // ---- scale + ALiBi + causal, row stats ----
        float rmax0 = -1e30f, rmax1 = -1e30f;
        const int ig0 = i0 + wid * 16 + g;
#pragma unroll
        for (int nt = 0; nt < 8; nt++)
#pragma unroll
            for (int e = 0; e < 4; e++) {
                int jg = j0 + nt * 8 + 2 * t + (e & 1);
                int ig = ig0 + ((e & 2) ? 8 : 0);
                float v = s[nt][e] * sscale + slope_l2 * (float)(ig - jg);
                if (jg > ig) v = -1e30f;
                s[nt][e] = v;
                if (e & 2) rmax1 = fmaxf(rmax1, v); else rmax0 = fmaxf(rmax0, v);
            }
        rmax0 = fmaxf(rmax0, __shfl_xor_sync(0xffffffffu, rmax0, 1));
        rmax0 = fmaxf(rmax0, __shfl_xor_sync(0xffffffffu, rmax0, 2));
        rmax1 = fmaxf(rmax1, __shfl_xor_sync(0xffffffffu, rmax1, 1));
        rmax1 = fmaxf(rmax1, __shfl_xor_sync(0xffffffffu, rmax1, 2));
        float mn0 = fmaxf(m0, rmax0), mn1 = fmaxf(m1, rmax1);
        float f0 = ex2(m0 - mn0), f1 = ex2(m1 - mn1);
        m0 = mn0; m1 = mn1;

        float rs0 = 0.f, rs1 = 0.f;
#pragma unroll
        for (int nt = 0; nt < 8; nt++)
#pragma unroll
            for (int e = 0; e < 4; e++) {
                float p = ex2(s[nt][e] - ((e & 2) ? mn1 : mn0));
                s[nt][e] = p;
                if (e & 2) rs1 += p; else rs0 += p;
            }
        rs0 += __shfl_xor_sync(0xffffffffu, rs0, 1);
        rs0 += __shfl_xor_sync(0xffffffffu, rs0, 2);
        rs1 += __shfl_xor_sync(0xffffffffu, rs1, 1);
        rs1 += __shfl_xor_sync(0xffffffffu, rs1, 2);
        l0 = l0 * f0 + rs0;
        l1 = l1 * f1 + rs1;
#pragma unroll
        for (int nt = 0; nt < 8; nt++) {
            o[nt][0] *= f0; o[nt][1] *= f0;
            o[nt][2] *= f1; o[nt][3] *= f1;
        }

        // ---- O += P @ V : P in registers (bf16 split), V via ldmatrix.trans ----
#pragma unroll
        for (int kt = 0; kt < 4; kt++) {
            unsigned p0[4], p1[4];
            {
                float c0 = s[2 * kt][0],     c1 = s[2 * kt][1];
                float c2 = s[2 * kt][2],     c3 = s[2 * kt][3];
                float d0 = s[2 * kt + 1][0], d1 = s[2 * kt + 1][1];
                float d2 = s[2 * kt + 1][2], d3 = s[2 * kt + 1][3];
                PK_BF2(p0[0], c0, c1); PK_BF2(p0[1], c2, c3);
                PK_BF2(p0[2], d0, d1); PK_BF2(p0[3], d2, d3);
                PK_BF2(p1[0], c0 - bf_round(c0), c1 - bf_round(c1));
                PK_BF2(p1[1], c2 - bf_round(c2), c3 - bf_round(c3));
                PK_BF2(p1[2], d0 - bf_round(d0), d1 - bf_round(d1));
                PK_BF2(p1[3], d2 - bf_round(d2), d3 - bf_round(d3));
            }
            unsigned vb0[4][4], vb1[4][4];
#pragma unroll
            for (int dg = 0; dg < 4; dg++) {
                unsigned vo = kstg + 2 * FL_PL +
                              (unsigned)((kt * 16 + vrow) * VRB) + (unsigned)(dg * 32) + vc16;
                LDSM_T_X4(vb0[dg][0], vb0[dg][1], vb0[dg][2], vb0[dg][3], vo);
                LDSM_T_X4(vb1[dg][0], vb1[dg][1], vb1[dg][2], vb1[dg][3], vo + FL_PL);
            }
#pragma unroll
            for (int nt = 0; nt < 8; nt++)
                MMA_BF16(o[nt], p0, vb0[nt >> 1][(nt & 1) * 2], vb0[nt >> 1][(nt & 1) * 2 + 1]);
#pragma unroll
            for (int nt = 0; nt < 8; nt++)
                MMA_BF16(o[nt], p1, vb0[nt >> 1][(nt & 1) * 2], vb0[nt >> 1][(nt & 1) * 2 + 1]);
#pragma unroll
            for (int nt = 0; nt < 8; nt++)
                MMA_BF16(o[nt], p0, vb1[nt >> 1][(nt & 1) * 2], vb1[nt >> 1][(nt & 1) * 2 + 1]);
        }
        // no trailing barrier: stage (jt&3) is next written at iter jt+2,
        // whose cp.async issues only after sync(jt+1) -> all reads of jt done.
    }

    // ---- normalize + write bf16 split planes ----
    float inv0 = 1.f / l0, inv1 = 1.f / l1;
    const int ig0 = i0 + wid * 16 + g;
#pragma unroll
    for (int nt = 0; nt < 8; nt++) {
        int d = nt * 8 + 2 * t;
        size_t idx0 = ((size_t)(b * Nq + ig0) * Hq + h) * DHq + d;
        size_t idx1 = idx0 + (size_t)8 * HDq;
        float v0 = o[nt][0] * inv0, v1 = o[nt][1] * inv0;
        float v2 = o[nt][2] * inv1, v3 = o[nt][3] * inv1;
        unsigned u;
        PK_BF2(u, v0, v1);                               *(unsigned*)(g_ab0 + idx0) = u;
        PK_BF2(u, v0 - bf_round(v0), v1 - bf_round(v1)); *(unsigned*)(g_ab1 + idx0) = u;
        PK_BF2(u, v2, v3);                               *(unsigned*)(g_ab0 + idx1) = u;
        PK_BF2(u, v2 - bf_round(v2), v3 - bf_round(v3)); *(unsigned*)(g_ab1 + idx1) = u;
    }
#undef FL_LOAD_TILE
}

// ---------------------------------------------------------------------------
extern "C" void kernel_launch(void* const* d_in, const int* in_sizes, int n_in,
                              void* d_out, int out_size)
{
    (void)in_sizes; (void)n_in; (void)out_size;
    const float* x  = (const float*)d_in[0];
    const float* Wq = (const float*)d_in[1];
    const float* Wk = (const float*)d_in[2];
    const float* Wv = (const float*)d_in[3];
    const float* Wo = (const float*)d_in[4];
    const float* bo = (const float*)d_in[5];
    float* out = (float*)d_out;

    cudaFuncSetAttribute(qkv_gemm_p, cudaFuncAttributeMaxDynamicSharedMemorySize, GEMMP_SMEM);
    cudaFuncSetAttribute(out_proj_p, cudaFuncAttributeMaxDynamicSharedMemorySize, GEMMP_SMEM);
    cudaFuncSetAttribute(flash_bf,   cudaFuncAttributeMaxDynamicSharedMemorySize, FL_SMEM);

    split_x_b<<<Mq * Dq / 4 / 256, 256>>>(x);
    split_wT_s<<<dim3(16, 16), 256>>>(Wq, 0);
    split_wT_s<<<dim3(16, 16), 256>>>(Wk, 1);
    split_wT_s<<<dim3(16, 16), 256>>>(Wv, 2);
    split_wT_s<<<dim3(16, 16), 256>>>(Wo, 3);

    qkv_gemm_p<<<dim3(24, 32), 256, GEMMP_SMEM>>>();
    flash_bf<<<dim3(16, Hq, Bq), 256, FL_SMEM>>>();
    out_proj_p<<<dim3(8, 32), 256, GEMMP_SMEM>>>(bo, out);
}

// round 13
// speedup vs baseline: 1.8906x; 1.0614x over previous
#include <cuda_runtime.h>
#include <cuda_bf16.h>

#define Bq 2
#define Nq 2048
#define Hq 16
#define DHq 64
#define Dq 1024
#define HDq (Hq * DHq)   // 1024
#define Mq (Bq * Nq)     // 4096

#define PLX ((size_t)Mq * Dq)
#define PLW ((size_t)Dq * Dq)
#define PLA ((size_t)Mq * HDq)

// bf16 split planes
__device__ __nv_bfloat16 g_xb0[PLX], g_xb1[PLX];
__device__ __nv_bfloat16 g_wtb[8 * PLW];          // 4 weights x 2 planes, transposed [n][k]
__device__ __nv_bfloat16 g_qb0[PLA], g_qb1[PLA];
__device__ __nv_bfloat16 g_kb0[PLA], g_kb1[PLA];
__device__ __nv_bfloat16 g_vb0[PLA], g_vb1[PLA];
__device__ __nv_bfloat16 g_ab0[PLA], g_ab1[PLA];

// ---------------------------------------------------------------------------
// helpers
// ---------------------------------------------------------------------------
__device__ __forceinline__ void split_bf16(float x, __nv_bfloat16& b0, __nv_bfloat16& b1)
{
    b0 = __float2bfloat16(x);
    b1 = __float2bfloat16(x - __bfloat162float(b0));
}

__device__ __forceinline__ float bf_round(float x)
{
    return __bfloat162float(__float2bfloat16(x));
}

__device__ __forceinline__ float ex2(float x)
{
    float r;
    asm("ex2.approx.f32 %0, %1;" : "=f"(r) : "f"(x));
    return r;
}

#define PK_BF2(d, a, b) \
    asm("cvt.rn.bf16x2.f32 %0, %1, %2;" : "=r"(d) : "f"(b), "f"(a))

#define MMA_BF16(d, a, b0_, b1_)                                              \
    asm volatile("mma.sync.aligned.m16n8k16.row.col.f32.bf16.bf16.f32 "       \
                 "{%0,%1,%2,%3}, {%4,%5,%6,%7}, {%8,%9}, {%0,%1,%2,%3};"      \
                 : "+f"(d[0]), "+f"(d[1]), "+f"(d[2]), "+f"(d[3])             \
                 : "r"(a[0]), "r"(a[1]), "r"(a[2]), "r"(a[3]),                \
                   "r"(b0_), "r"(b1_))

#define LDSM_X4(r0, r1, r2, r3, addr)                                         \
    asm volatile("ldmatrix.sync.aligned.m8n8.x4.shared.b16 {%0,%1,%2,%3}, [%4];" \
                 : "=r"(r0), "=r"(r1), "=r"(r2), "=r"(r3) : "r"(addr))

#define LDSM_T_X4(r0, r1, r2, r3, addr)                                       \
    asm volatile("ldmatrix.sync.aligned.m8n8.x4.trans.shared.b16 {%0,%1,%2,%3}, [%4];" \
                 : "=r"(r0), "=r"(r1), "=r"(r2), "=r"(r3) : "r"(addr))

#define CP_A16(dst, src) \
    asm volatile("cp.async.cg.shared.global [%0], [%1], 16;" :: "r"(dst), "l"(src))
#define CP_COMMIT() asm volatile("cp.async.commit_group;")
#define CP_WAIT0()  asm volatile("cp.async.wait_group 0;" ::: "memory")
#define CP_WAIT1()  asm volatile("cp.async.wait_group 1;" ::: "memory")

// ---------------------------------------------------------------------------
// split kernels
// ---------------------------------------------------------------------------
__global__ __launch_bounds__(256) void split_x_b(const float* __restrict__ in)
{
    size_t i = (size_t)blockIdx.x * 256 + threadIdx.x;   // over float4
    float4 v = ((const float4*)in)[i];
    __nv_bfloat16 a0, a1, b0, b1, c0, c1, d0, d1;
    split_bf16(v.x, a0, a1); split_bf16(v.y, b0, b1);
    split_bf16(v.z, c0, c1); split_bf16(v.w, d0, d1);
    __nv_bfloat162 p;
    p.x = a0; p.y = b0; *(__nv_bfloat162*)(g_xb0 + i * 4)     = p;
    p.x = c0; p.y = d0; *(__nv_bfloat162*)(g_xb0 + i * 4 + 2) = p;
    p.x = a1; p.y = b1; *(__nv_bfloat162*)(g_xb1 + i * 4)     = p;
    p.x = c1; p.y = d1; *(__nv_bfloat162*)(g_xb1 + i * 4 + 2) = p;
}

// all 4 weights in one launch: transpose + split via smem tile
__global__ __launch_bounds__(256) void split_wT_all(const float* __restrict__ Wq,
                                                    const float* __restrict__ Wk,
                                                    const float* __restrict__ Wv,
                                                    const float* __restrict__ Wo)
{
    __shared__ float ts[64][68];
    const int w = blockIdx.z;
    const float* W = (w == 0) ? Wq : (w == 1) ? Wk : (w == 2) ? Wv : Wo;
    const int tid = threadIdx.x;
    const int n0 = blockIdx.x * 64, k0 = blockIdx.y * 64;

#pragma unroll
    for (int i = 0; i < 4; i++) {
        int idx = i * 256 + tid;
        int kr = idx >> 4, c4 = idx & 15;
        float4 v = *(const float4*)(W + (size_t)(k0 + kr) * Dq + n0 + c4 * 4);
        ts[c4 * 4 + 0][kr] = v.x;
        ts[c4 * 4 + 1][kr] = v.y;
        ts[c4 * 4 + 2][kr] = v.z;
        ts[c4 * 4 + 3][kr] = v.w;
    }
    __syncthreads();

    const int n = tid >> 2, kc = (tid & 3) * 16;
    unsigned u0[8], u1[8];
#pragma unroll
    for (int j = 0; j < 8; j++) {
        float v0 = ts[n][kc + 2 * j], v1 = ts[n][kc + 2 * j + 1];
        float h0 = bf_round(v0), h1 = bf_round(v1);
        PK_BF2(u0[j], h0, h1);
        PK_BF2(u1[j], v0 - h0, v1 - h1);
    }
    __nv_bfloat16* d0 = g_wtb + (size_t)(w * 2 + 0) * PLW + (size_t)(n0 + n) * Dq + k0 + kc;
    __nv_bfloat16* d1 = g_wtb + (size_t)(w * 2 + 1) * PLW + (size_t)(n0 + n) * Dq + k0 + kc;
    *(uint4*)(d0)     = make_uint4(u0[0], u0[1], u0[2], u0[3]);
    *(uint4*)(d0 + 8) = make_uint4(u0[4], u0[5], u0[6], u0[7]);
    *(uint4*)(d1)     = make_uint4(u1[0], u1[1], u1[2], u1[3]);
    *(uint4*)(d1 + 8) = make_uint4(u1[4], u1[5], u1[6], u1[7]);
}

// ---------------------------------------------------------------------------
// bf16x3 m16n8k16 GEMM, BK=32, 2-stage cp.async (R10, proven).
// ---------------------------------------------------------------------------
#define TPL 10240
#define STAGE_B 40960
#define GEMMP_SMEM (2 * STAGE_B)   // 81920

__device__ __forceinline__ void gemm_pipe_bf(const __nv_bfloat16* __restrict__ Ab0,
                                             const __nv_bfloat16* __restrict__ Ab1,
                                             const __nv_bfloat16* __restrict__ Wb0,
                                             const __nv_bfloat16* __restrict__ Wb1,
                                             __nv_bfloat16* __restrict__ Cb0,
                                             __nv_bfloat16* __restrict__ Cb1,
                                             float* __restrict__ Cf,
                                             const float* __restrict__ bias,
                                             int rowBlk, int colBlk)
{
    extern __shared__ float sm[];
    const unsigned smb = (unsigned)__cvta_generic_to_shared(sm);
    const int tid = threadIdx.x;
    const int wid = tid >> 5, lane = tid & 31;
    const int g = lane >> 2, t = lane & 3;
    const int wm = (wid & 3) * 32, wn = (wid >> 2) * 64;

    const size_t arow = (size_t)rowBlk * 128;
    const int ccol = colBlk * 128;

    const int quad = lane >> 3, lrow = lane & 7;
    const unsigned lmoff = (unsigned)(((quad & 1) * 8 + lrow) * 80 + (quad >> 1) * 16);

    float acc[2][8][4] = {};

#define PREFB(st, k0)                                                          \
    {                                                                          \
        unsigned base = smb + (st) * STAGE_B;                                  \
        _Pragma("unroll")                                                      \
        for (int i_ = 0; i_ < 2; i_++) {                                       \
            int idx = tid * 2 + i_;                                            \
            int r = idx >> 2, c4 = idx & 3;                                    \
            unsigned so = (unsigned)(r * 80 + c4 * 16);                        \
            CP_A16(base + 0 * TPL + so, Ab0 + (arow + r) * Dq + (k0) + c4 * 8);\
            CP_A16(base + 1 * TPL + so, Ab1 + (arow + r) * Dq + (k0) + c4 * 8);\
            CP_A16(base + 2 * TPL + so, Wb0 + (size_t)(ccol + r) * Dq + (k0) + c4 * 8); \
            CP_A16(base + 3 * TPL + so, Wb1 + (size_t)(ccol + r) * Dq + (k0) + c4 * 8); \
        }                                                                      \
    }

    PREFB(0, 0);
    CP_COMMIT();

    const int nch = Dq / 32;   // 32
    for (int chn = 0; chn < nch; chn++) {
        if (chn + 1 < nch) {
            PREFB((chn + 1) & 1, (chn + 1) * 32);
            CP_COMMIT();
            CP_WAIT1();
        } else {
            CP_WAIT0();
        }
        __syncthreads();

        const unsigned stg = smb + (chn & 1) * STAGE_B;

#pragma unroll
        for (int half = 0; half < 2; half++) {
            const unsigned co = (unsigned)(half * 32);
            unsigned af0[2][4], af1[2][4];
#pragma unroll
            for (int mt = 0; mt < 2; mt++) {
                unsigned ao = stg + (unsigned)((wm + mt * 16) * 80) + lmoff + co;
                LDSM_X4(af0[mt][0], af0[mt][1], af0[mt][2], af0[mt][3], ao);
                LDSM_X4(af1[mt][0], af1[mt][1], af1[mt][2], af1[mt][3], ao + TPL);
            }
            unsigned bf0[4][4], bf1[4][4];
#pragma unroll
            for (int np = 0; np < 4; np++) {
                unsigned wo = stg + 2 * TPL + (unsigned)((wn + np * 16) * 80) + lmoff + co;
                LDSM_X4(bf0[np][0], bf0[np][1], bf0[np][2], bf0[np][3], wo);
                LDSM_X4(bf1[np][0], bf1[np][1], bf1[np][2], bf1[np][3], wo + TPL);
            }
#pragma unroll
            for (int mt = 0; mt < 2; mt++)
#pragma unroll
                for (int nt = 0; nt < 8; nt++)
                    MMA_BF16(acc[mt][nt], af0[mt], bf0[nt >> 1][nt & 1], bf0[nt >> 1][(nt & 1) + 2]);
#pragma unroll
            for (int mt = 0; mt < 2; mt++)
#pragma unroll
                for (int nt = 0; nt < 8; nt++)
                    MMA_BF16(acc[mt][nt], af1[mt], bf0[nt >> 1][nt & 1], bf0[nt >> 1][(nt & 1) + 2]);
#pragma unroll
            for (int mt = 0; mt < 2; mt++)
#pragma unroll
                for (int nt = 0; nt < 8; nt++)
                    MMA_BF16(acc[mt][nt], af0[mt], bf1[nt >> 1][nt & 1], bf1[nt >> 1][(nt & 1) + 2]);
        }
        __syncthreads();
    }

#pragma unroll
    for (int mt = 0; mt < 2; mt++) {
        size_t r0 = arow + wm + mt * 16 + g;
#pragma unroll
        for (int nt = 0; nt < 8; nt++) {
            int c = ccol + wn + nt * 8 + 2 * t;
            if (Cb0) {
                float v0 = acc[mt][nt][0], v1 = acc[mt][nt][1];
                float v2 = acc[mt][nt][2], v3 = acc[mt][nt][3];
                unsigned u;
                PK_BF2(u, v0, v1);                               *(unsigned*)(Cb0 + r0 * Dq + c) = u;
                PK_BF2(u, v0 - bf_round(v0), v1 - bf_round(v1)); *(unsigned*)(Cb1 + r0 * Dq + c) = u;
                PK_BF2(u, v2, v3);                               *(unsigned*)(Cb0 + (r0 + 8) * Dq + c) = u;
                PK_BF2(u, v2 - bf_round(v2), v3 - bf_round(v3)); *(unsigned*)(Cb1 + (r0 + 8) * Dq + c) = u;
            } else {
                float b0 = bias[c], b1 = bias[c + 1];
                *(float2*)(Cf + r0 * Dq + c) =
                    make_float2(acc[mt][nt][0] + b0, acc[mt][nt][1] + b1);
                *(float2*)(Cf + (r0 + 8) * Dq + c) =
                    make_float2(acc[mt][nt][2] + b0, acc[mt][nt][3] + b1);
            }
        }
    }
#undef PREFB
}

__global__ __launch_bounds__(256, 2) void qkv_gemm_p()
{
    int w = blockIdx.x >> 3, colBlk = blockIdx.x & 7;
    __nv_bfloat16* C0 = (w == 0) ? g_qb0 : (w == 1) ? g_kb0 : g_vb0;
    __nv_bfloat16* C1 = (w == 0) ? g_qb1 : (w == 1) ? g_kb1 : g_vb1;
    gemm_pipe_bf(g_xb0, g_xb1,
                 g_wtb + (size_t)(w * 2) * PLW, g_wtb + (size_t)(w * 2 + 1) * PLW,
                 C0, C1, nullptr, nullptr, blockIdx.y, colBlk);
}

__global__ __launch_bounds__(256, 2) void out_proj_p(const float* __restrict__ bo,
                                                     float* __restrict__ out)
{
    gemm_pipe_bf(g_ab0, g_ab1,
                 g_wtb + (size_t)6 * PLW, g_wtb + (size_t)7 * PLW,
                 nullptr, nullptr, out, bo, blockIdx.y, blockIdx.x);
}

// ---------------------------------------------------------------------------
// bf16x3 flash attention, BR=64 / 4 warps / 128 threads for 2+ CTAs per SM.
// Q fragments persistent in registers; 2-stage K/V ring (double-buffered).
// smem: 2 stages x {K0 K1 V0 V1}[64][64]bf16 (144 B rows) = 73728 B.
// ---------------------------------------------------------------------------
#define VRB 144
#define FL_PL 9216            // one 64x64 plane (144 B rows)
#define FL_STG_SZ (4 * FL_PL) // 36864
#define FL_SMEM (2 * FL_STG_SZ)   // 73728

__global__ __launch_bounds__(128, 2) void flash_bf()
{
    extern __shared__ char smc[];
    const unsigned smb = (unsigned)__cvta_generic_to_shared(smc);
    const int tid = threadIdx.x, wid = tid >> 5, lane = tid & 31;
    const int g = lane >> 2, t = lane & 3;
    const int quad = lane >> 3, lrow = lane & 7;
    const int it = (int)gridDim.x - 1 - (int)blockIdx.x;   // heavy tiles first
    const int i0 = it * 64;
    const int h = blockIdx.y, b = blockIdx.z;
    const float slope_l2 = exp2f(-0.5f * (float)(h + 1)) * 1.44269504f;
    const float sscale   = 0.125f * 1.44269504f;

    const unsigned lmoff = (unsigned)(((quad & 1) * 8 + lrow) * VRB + (quad >> 1) * 16);
    const unsigned vrow  = (unsigned)(lane & 15);
    const unsigned vc16  = (unsigned)(lane >> 4) * 16;

#define FL_LOAD_TILE(j0_, sbase_)                                              \
    {                                                                          \
        size_t kb_ = ((size_t)(b * Nq + (j0_)) * Hq + h) * DHq;                \
        _Pragma("unroll")                                                      \
        for (int itr_ = 0; itr_ < 4; itr_++) {                                 \
            int idx_ = itr_ * 128 + tid;                                       \
            int row_ = idx_ >> 3, ch_ = idx_ & 7;                              \
            size_t src_ = kb_ + (size_t)row_ * HDq + ch_ * 8;                  \
            unsigned so_ = (unsigned)(row_ * VRB + ch_ * 16);                  \
            CP_A16((sbase_) + 0 * FL_PL + so_, g_kb0 + src_);                  \
            CP_A16((sbase_) + 1 * FL_PL + so_, g_kb1 + src_);                  \
            CP_A16((sbase_) + 2 * FL_PL + so_, g_vb0 + src_);                  \
            CP_A16((sbase_) + 3 * FL_PL + so_, g_vb1 + src_);                  \
        }                                                                      \
    }

    // ---- prologue: stage Q[64][64] through stage-0 smem, extract fragments ----
    unsigned qf0[4][4], qf1[4][4];
    {
        size_t qb = ((size_t)(b * Nq + i0) * Hq + h) * DHq;
#pragma unroll
        for (int itr = 0; itr < 4; itr++) {
            int idx = itr * 128 + tid;
            int row = idx >> 3, ch = idx & 7;
            size_t src = qb + (size_t)row * HDq + ch * 8;
            CP_A16(smb + (unsigned)(row * VRB + ch * 16), g_qb0 + src);
            CP_A16(smb + (unsigned)FL_PL + (unsigned)(row * VRB + ch * 16), g_qb1 + src);
        }
        CP_COMMIT();
        CP_WAIT0();
        __syncthreads();
#pragma unroll
        for (int kt = 0; kt < 4; kt++) {
            unsigned qo = smb + (unsigned)(wid * 16) * VRB + lmoff + kt * 32;
            LDSM_X4(qf0[kt][0], qf0[kt][1], qf0[kt][2], qf0[kt][3], qo);
            LDSM_X4(qf1[kt][0], qf1[kt][1], qf1[kt][2], qf1[kt][3], qo + FL_PL);
        }
        __syncthreads();   // Q reads done before K/V pipeline reuses stage 0
    }

    float o[8][4] = {};
    float m0 = -1e30f, m1 = -1e30f, l0 = 0.f, l1 = 0.f;

    const int njt = it + 1;

    FL_LOAD_TILE(0, smb);
    CP_COMMIT();

    for (int jt = 0; jt < njt; jt++) {
        const int j0 = jt * 64;

        if (jt + 1 < njt) {
            FL_LOAD_TILE(j0 + 64, smb + (unsigned)(((jt + 1) & 1) * FL_STG_SZ));
            CP_COMMIT();
            CP_WAIT1();
        } else {
            CP_WAIT0();
        }
        __syncthreads();

        const unsigned kstg = smb + (unsigned)((jt & 1) * FL_STG_SZ);

        // ---- S = Q @ K^T : warp tile m16 x n64, 4 k16 chunks ----
        float s[8][4] = {};
#pragma unroll
        for (int kt = 0; kt < 4; kt++) {
            unsigned kb0[4][4], kb1[4][4];
#pragma unroll
            for (int grp = 0; grp < 4; grp++) {
                unsigned ko = kstg + (unsigned)(grp * 16) * VRB + lmoff + kt * 32;
                LDSM_X4(kb0[grp][0], kb0[grp][1], kb0[grp][2], kb0[grp][3], ko);
                LDSM_X4(kb1[grp][0], kb1[grp][1], kb1[grp][2], kb1[grp][3], ko + FL_PL);
            }
#pragma unroll
            for (int nt = 0; nt < 8; nt++)
                MMA_BF16(s[nt], qf0[kt], kb0[nt >> 1][nt & 1], kb0[nt >> 1][(nt & 1) + 2]);
#pragma unroll
            for (int nt = 0; nt < 8; nt++)
                MMA_BF16(s[nt], qf1[kt], kb0[nt >> 1][nt & 1], kb0[nt >> 1][(nt & 1) + 2]);
#pragma unroll
            for (int nt = 0; nt < 8; nt++)
                MMA_BF16(s[nt], qf0[kt], kb1[nt >> 1][nt & 1], kb1[nt >> 1][(nt & 1) + 2]);
        }

        // ---- scale + ALiBi + causal, row stats ----
        float rmax0 = -1e30f, rmax1 = -1e30f;
        const int ig0 = i0 + wid * 16 + g;
#pragma unroll
        for (int nt = 0; nt < 8; nt++)
#pragma unroll
            for (int e = 0; e < 4; e++) {
                int jg = j0 + nt * 8 + 2 * t + (e & 1);
                int ig = ig0 + ((e & 2) ? 8 : 0);
                float v = s[nt][e] * sscale + slope_l2 * (float)(ig - jg);
                if (jg > ig) v = -1e30f;
                s[nt][e] = v;
                if (e & 2) rmax1 = fmaxf(rmax1, v); else rmax0 = fmaxf(rmax0, v);
            }
        rmax0 = fmaxf(rmax0, __shfl_xor_sync(0xffffffffu, rmax0, 1));
        rmax0 = fmaxf(rmax0, __shfl_xor_sync(0xffffffffu, rmax0, 2));
        rmax1 = fmaxf(rmax1, __shfl_xor_sync(0xffffffffu, rmax1, 1));
        rmax1 = fmaxf(rmax1, __shfl_xor_sync(0xffffffffu, rmax1, 2));
        float mn0 = fmaxf(m0, rmax0), mn1 = fmaxf(m1, rmax1);
        float f0 = ex2(m0 - mn0), f1 = ex2(m1 - mn1);
        m0 = mn0; m1 = mn1;

        float rs0 = 0.f, rs1 = 0.f;
#pragma unroll
        for (int nt = 0; nt < 8; nt++)
#pragma unroll
            for (int e = 0; e < 4; e++) {
                float p = ex2(s[nt][e] - ((e & 2) ? mn1 : mn0));
                s[nt][e] = p;
                if (e & 2) rs1 += p; else rs0 += p;
            }
        rs0 += __shfl_xor_sync(0xffffffffu, rs0, 1);
        rs0 += __shfl_xor_sync(0xffffffffu, rs0, 2);
        rs1 += __shfl_xor_sync(0xffffffffu, rs1, 1);
        rs1 += __shfl_xor_sync(0xffffffffu, rs1, 2);
        l0 = l0 * f0 + rs0;
        l1 = l1 * f1 + rs1;
#pragma unroll
        for (int nt = 0; nt < 8; nt++) {
            o[nt][0] *= f0; o[nt][1] *= f0;
            o[nt][2] *= f1; o[nt][3] *= f1;
        }

        // ---- O += P @ V : P in registers (bf16 split), V via ldmatrix.trans ----
#pragma unroll
        for (int kt = 0; kt < 4; kt++) {
            unsigned p0[4], p1[4];
            {
                float c0 = s[2 * kt][0],     c1 = s[2 * kt][1];
                float c2 = s[2 * kt][2],     c3 = s[2 * kt][3];
                float d0 = s[2 * kt + 1][0], d1 = s[2 * kt + 1][1];
                float d2 = s[2 * kt + 1][2], d3 = s[2 * kt + 1][3];
                PK_BF2(p0[0], c0, c1); PK_BF2(p0[1], c2, c3);
                PK_BF2(p0[2], d0, d1); PK_BF2(p0[3], d2, d3);
                PK_BF2(p1[0], c0 - bf_round(c0), c1 - bf_round(c1));
                PK_BF2(p1[1], c2 - bf_round(c2), c3 - bf_round(c3));
                PK_BF2(p1[2], d0 - bf_round(d0), d1 - bf_round(d1));
                PK_BF2(p1[3], d2 - bf_round(d2), d3 - bf_round(d3));
            }
            unsigned vb0[4][4], vb1[4][4];
#pragma unroll
            for (int dg = 0; dg < 4; dg++) {
                unsigned vo = kstg + 2 * FL_PL +
                              (unsigned)((kt * 16 + vrow) * VRB) + (unsigned)(dg * 32) + vc16;
                LDSM_T_X4(vb0[dg][0], vb0[dg][1], vb0[dg][2], vb0[dg][3], vo);
                LDSM_T_X4(vb1[dg][0], vb1[dg][1], vb1[dg][2], vb1[dg][3], vo + FL_PL);
            }
#pragma unroll
            for (int nt = 0; nt < 8; nt++)
                MMA_BF16(o[nt], p0, vb0[nt >> 1][(nt & 1) * 2], vb0[nt >> 1][(nt & 1) * 2 + 1]);
#pragma unroll
            for (int nt = 0; nt < 8; nt++)
                MMA_BF16(o[nt], p1, vb0[nt >> 1][(nt & 1) * 2], vb0[nt >> 1][(nt & 1) * 2 + 1]);
#pragma unroll
            for (int nt = 0; nt < 8; nt++)
                MMA_BF16(o[nt], p0, vb1[nt >> 1][(nt & 1) * 2], vb1[nt >> 1][(nt & 1) * 2 + 1]);
        }
        __syncthreads();   // all reads of stage (jt&1) done before it is refilled
    }

    // ---- normalize + write bf16 split planes ----
    float inv0 = 1.f / l0, inv1 = 1.f / l1;
    const int ig0 = i0 + wid * 16 + g;
#pragma unroll
    for (int nt = 0; nt < 8; nt++) {
        int d = nt * 8 + 2 * t;
        size_t idx0 = ((size_t)(b * Nq + ig0) * Hq + h) * DHq + d;
        size_t idx1 = idx0 + (size_t)8 * HDq;
        float v0 = o[nt][0] * inv0, v1 = o[nt][1] * inv0;
        float v2 = o[nt][2] * inv1, v3 = o[nt][3] * inv1;
        unsigned u;
        PK_BF2(u, v0, v1);                               *(unsigned*)(g_ab0 + idx0) = u;
        PK_BF2(u, v0 - bf_round(v0), v1 - bf_round(v1)); *(unsigned*)(g_ab1 + idx0) = u;
        PK_BF2(u, v2, v3);                               *(unsigned*)(g_ab0 + idx1) = u;
        PK_BF2(u, v2 - bf_round(v2), v3 - bf_round(v3)); *(unsigned*)(g_ab1 + idx1) = u;
    }
#undef FL_LOAD_TILE
}

// ---------------------------------------------------------------------------
extern "C" void kernel_launch(void* const* d_in, const int* in_sizes, int n_in,
                              void* d_out, int out_size)
{
    (void)in_sizes; (void)n_in; (void)out_size;
    const float* x  = (const float*)d_in[0];
    const float* Wq = (const float*)d_in[1];
    const float* Wk = (const float*)d_in[2];
    const float* Wv = (const float*)d_in[3];
    const float* Wo = (const float*)d_in[4];
    const float* bo = (const float*)d_in[5];
    float* out = (float*)d_out;

    cudaFuncSetAttribute(qkv_gemm_p, cudaFuncAttributeMaxDynamicSharedMemorySize, GEMMP_SMEM);
    cudaFuncSetAttribute(out_proj_p, cudaFuncAttributeMaxDynamicSharedMemorySize, GEMMP_SMEM);
    cudaFuncSetAttribute(flash_bf,   cudaFuncAttributeMaxDynamicSharedMemorySize, FL_SMEM);

    split_x_b<<<Mq * Dq / 4 / 256, 256>>>(x);
    split_wT_all<<<dim3(16, 16, 4), 256>>>(Wq, Wk, Wv, Wo);

    qkv_gemm_p<<<dim3(24, 32), 256, GEMMP_SMEM>>>();
    flash_bf<<<dim3(32, Hq, Bq), 128, FL_SMEM>>>();
    out_proj_p<<<dim3(8, 32), 256, GEMMP_SMEM>>>(bo, out);
}

// round 14
// speedup vs baseline: 1.8936x; 1.0016x over previous
#include <cuda_runtime.h>
#include <cuda_bf16.h>

#define Bq 2
#define Nq 2048
#define Hq 16
#define DHq 64
#define Dq 1024
#define HDq (Hq * DHq)   // 1024
#define Mq (Bq * Nq)     // 4096

#define PLX ((size_t)Mq * Dq)
#define PLW ((size_t)Dq * Dq)
#define PLA ((size_t)Mq * HDq)

// bf16 split planes
__device__ __nv_bfloat16 g_xb0[PLX], g_xb1[PLX];
__device__ __nv_bfloat16 g_wtb[8 * PLW];          // 4 weights x 2 planes, transposed [n][k]
__device__ __nv_bfloat16 g_qb0[PLA], g_qb1[PLA];
__device__ __nv_bfloat16 g_kb0[PLA], g_kb1[PLA];
__device__ __nv_bfloat16 g_vb0[PLA], g_vb1[PLA];
__device__ __nv_bfloat16 g_ab0[PLA], g_ab1[PLA];

// ---------------------------------------------------------------------------
// helpers
// ---------------------------------------------------------------------------
__device__ __forceinline__ void split_bf16(float x, __nv_bfloat16& b0, __nv_bfloat16& b1)
{
    b0 = __float2bfloat16(x);
    b1 = __float2bfloat16(x - __bfloat162float(b0));
}

__device__ __forceinline__ float bf_round(float x)
{
    return __bfloat162float(__float2bfloat16(x));
}

__device__ __forceinline__ float ex2(float x)
{
    float r;
    asm("ex2.approx.f32 %0, %1;" : "=f"(r) : "f"(x));
    return r;
}

#define PK_BF2(d, a, b) \
    asm("cvt.rn.bf16x2.f32 %0, %1, %2;" : "=r"(d) : "f"(b), "f"(a))

#define MMA_BF16(d, a, b0_, b1_)                                              \
    asm volatile("mma.sync.aligned.m16n8k16.row.col.f32.bf16.bf16.f32 "       \
                 "{%0,%1,%2,%3}, {%4,%5,%6,%7}, {%8,%9}, {%0,%1,%2,%3};"      \
                 : "+f"(d[0]), "+f"(d[1]), "+f"(d[2]), "+f"(d[3])             \
                 : "r"(a[0]), "r"(a[1]), "r"(a[2]), "r"(a[3]),                \
                   "r"(b0_), "r"(b1_))

#define LDSM_X4(r0, r1, r2, r3, addr)                                         \
    asm volatile("ldmatrix.sync.aligned.m8n8.x4.shared.b16 {%0,%1,%2,%3}, [%4];" \
                 : "=r"(r0), "=r"(r1), "=r"(r2), "=r"(r3) : "r"(addr))

#define LDSM_T_X4(r0, r1, r2, r3, addr)                                       \
    asm volatile("ldmatrix.sync.aligned.m8n8.x4.trans.shared.b16 {%0,%1,%2,%3}, [%4];" \
                 : "=r"(r0), "=r"(r1), "=r"(r2), "=r"(r3) : "r"(addr))

#define CP_A16(dst, src) \
    asm volatile("cp.async.cg.shared.global [%0], [%1], 16;" :: "r"(dst), "l"(src))
#define CP_COMMIT() asm volatile("cp.async.commit_group;")
#define CP_WAIT0()  asm volatile("cp.async.wait_group 0;" ::: "memory")
#define CP_WAIT1()  asm volatile("cp.async.wait_group 1;" ::: "memory")

// ---------------------------------------------------------------------------
// split kernels
// ---------------------------------------------------------------------------
__global__ __launch_bounds__(256) void split_x_b(const float* __restrict__ in)
{
    size_t i = (size_t)blockIdx.x * 256 + threadIdx.x;   // over float4
    float4 v = ((const float4*)in)[i];
    __nv_bfloat16 a0, a1, b0, b1, c0, c1, d0, d1;
    split_bf16(v.x, a0, a1); split_bf16(v.y, b0, b1);
    split_bf16(v.z, c0, c1); split_bf16(v.w, d0, d1);
    __nv_bfloat162 p;
    p.x = a0; p.y = b0; *(__nv_bfloat162*)(g_xb0 + i * 4)     = p;
    p.x = c0; p.y = d0; *(__nv_bfloat162*)(g_xb0 + i * 4 + 2) = p;
    p.x = a1; p.y = b1; *(__nv_bfloat162*)(g_xb1 + i * 4)     = p;
    p.x = c1; p.y = d1; *(__nv_bfloat162*)(g_xb1 + i * 4 + 2) = p;
}

// all 4 weights in one launch: transpose + split via smem tile
__global__ __launch_bounds__(256) void split_wT_all(const float* __restrict__ Wq,
                                                    const float* __restrict__ Wk,
                                                    const float* __restrict__ Wv,
                                                    const float* __restrict__ Wo)
{
    __shared__ float ts[64][68];
    const int w = blockIdx.z;
    const float* W = (w == 0) ? Wq : (w == 1) ? Wk : (w == 2) ? Wv : Wo;
    const int tid = threadIdx.x;
    const int n0 = blockIdx.x * 64, k0 = blockIdx.y * 64;

#pragma unroll
    for (int i = 0; i < 4; i++) {
        int idx = i * 256 + tid;
        int kr = idx >> 4, c4 = idx & 15;
        float4 v = *(const float4*)(W + (size_t)(k0 + kr) * Dq + n0 + c4 * 4);
        ts[c4 * 4 + 0][kr] = v.x;
        ts[c4 * 4 + 1][kr] = v.y;
        ts[c4 * 4 + 2][kr] = v.z;
        ts[c4 * 4 + 3][kr] = v.w;
    }
    __syncthreads();

    const int n = tid >> 2, kc = (tid & 3) * 16;
    unsigned u0[8], u1[8];
#pragma unroll
    for (int j = 0; j < 8; j++) {
        float v0 = ts[n][kc + 2 * j], v1 = ts[n][kc + 2 * j + 1];
        float h0 = bf_round(v0), h1 = bf_round(v1);
        PK_BF2(u0[j], h0, h1);
        PK_BF2(u1[j], v0 - h0, v1 - h1);
    }
    __nv_bfloat16* d0 = g_wtb + (size_t)(w * 2 + 0) * PLW + (size_t)(n0 + n) * Dq + k0 + kc;
    __nv_bfloat16* d1 = g_wtb + (size_t)(w * 2 + 1) * PLW + (size_t)(n0 + n) * Dq + k0 + kc;
    *(uint4*)(d0)     = make_uint4(u0[0], u0[1], u0[2], u0[3]);
    *(uint4*)(d0 + 8) = make_uint4(u0[4], u0[5], u0[6], u0[7]);
    *(uint4*)(d1)     = make_uint4(u1[0], u1[1], u1[2], u1[3]);
    *(uint4*)(d1 + 8) = make_uint4(u1[4], u1[5], u1[6], u1[7]);
}

// ---------------------------------------------------------------------------
// bf16x3 m16n8k16 GEMM, BK=32, 2-stage cp.async (R10, proven).
// ---------------------------------------------------------------------------
#define TPL 10240
#define STAGE_B 40960
#define GEMMP_SMEM (2 * STAGE_B)   // 81920

__device__ __forceinline__ void gemm_pipe_bf(const __nv_bfloat16* __restrict__ Ab0,
                                             const __nv_bfloat16* __restrict__ Ab1,
                                             const __nv_bfloat16* __restrict__ Wb0,
                                             const __nv_bfloat16* __restrict__ Wb1,
                                             __nv_bfloat16* __restrict__ Cb0,
                                             __nv_bfloat16* __restrict__ Cb1,
                                             float* __restrict__ Cf,
                                             const float* __restrict__ bias,
                                             int rowBlk, int colBlk)
{
    extern __shared__ float sm[];
    const unsigned smb = (unsigned)__cvta_generic_to_shared(sm);
    const int tid = threadIdx.x;
    const int wid = tid >> 5, lane = tid & 31;
    const int g = lane >> 2, t = lane & 3;
    const int wm = (wid & 3) * 32, wn = (wid >> 2) * 64;

    const size_t arow = (size_t)rowBlk * 128;
    const int ccol = colBlk * 128;

    const int quad = lane >> 3, lrow = lane & 7;
    const unsigned lmoff = (unsigned)(((quad & 1) * 8 + lrow) * 80 + (quad >> 1) * 16);

    float acc[2][8][4] = {};

#define PREFB(st, k0)                                                          \
    {                                                                          \
        unsigned base = smb + (st) * STAGE_B;                                  \
        _Pragma("unroll")                                                      \
        for (int i_ = 0; i_ < 2; i_++) {                                       \
            int idx = tid * 2 + i_;                                            \
            int r = idx >> 2, c4 = idx & 3;                                    \
            unsigned so = (unsigned)(r * 80 + c4 * 16);                        \
            CP_A16(base + 0 * TPL + so, Ab0 + (arow + r) * Dq + (k0) + c4 * 8);\
            CP_A16(base + 1 * TPL + so, Ab1 + (arow + r) * Dq + (k0) + c4 * 8);\
            CP_A16(base + 2 * TPL + so, Wb0 + (size_t)(ccol + r) * Dq + (k0) + c4 * 8); \
            CP_A16(base + 3 * TPL + so, Wb1 + (size_t)(ccol + r) * Dq + (k0) + c4 * 8); \
        }                                                                      \
    }

    PREFB(0, 0);
    CP_COMMIT();

    const int nch = Dq / 32;   // 32
    for (int chn = 0; chn < nch; chn++) {
        if (chn + 1 < nch) {
            PREFB((chn + 1) & 1, (chn + 1) * 32);
            CP_COMMIT();
            CP_WAIT1();
        } else {
            CP_WAIT0();
        }
        __syncthreads();

        const unsigned stg = smb + (chn & 1) * STAGE_B;

#pragma unroll
        for (int half = 0; half < 2; half++) {
            const unsigned co = (unsigned)(half * 32);
            unsigned af0[2][4], af1[2][4];
#pragma unroll
            for (int mt = 0; mt < 2; mt++) {
                unsigned ao = stg + (unsigned)((wm + mt * 16) * 80) + lmoff + co;
                LDSM_X4(af0[mt][0], af0[mt][1], af0[mt][2], af0[mt][3], ao);
                LDSM_X4(af1[mt][0], af1[mt][1], af1[mt][2], af1[mt][3], ao + TPL);
            }
            unsigned bf0[4][4], bf1[4][4];
#pragma unroll
            for (int np = 0; np < 4; np++) {
                unsigned wo = stg + 2 * TPL + (unsigned)((wn + np * 16) * 80) + lmoff + co;
                LDSM_X4(bf0[np][0], bf0[np][1], bf0[np][2], bf0[np][3], wo);
                LDSM_X4(bf1[np][0], bf1[np][1], bf1[np][2], bf1[np][3], wo + TPL);
            }
#pragma unroll
            for (int mt = 0; mt < 2; mt++)
#pragma unroll
                for (int nt = 0; nt < 8; nt++)
                    MMA_BF16(acc[mt][nt], af0[mt], bf0[nt >> 1][nt & 1], bf0[nt >> 1][(nt & 1) + 2]);
#pragma unroll
            for (int mt = 0; mt < 2; mt++)
#pragma unroll
                for (int nt = 0; nt < 8; nt++)
                    MMA_BF16(acc[mt][nt], af1[mt], bf0[nt >> 1][nt & 1], bf0[nt >> 1][(nt & 1) + 2]);
#pragma unroll
            for (int mt = 0; mt < 2; mt++)
#pragma unroll
                for (int nt = 0; nt < 8; nt++)
                    MMA_BF16(acc[mt][nt], af0[mt], bf1[nt >> 1][nt & 1], bf1[nt >> 1][(nt & 1) + 2]);
        }
        __syncthreads();
    }

#pragma unroll
    for (int mt = 0; mt < 2; mt++) {
        size_t r0 = arow + wm + mt * 16 + g;
#pragma unroll
        for (int nt = 0; nt < 8; nt++) {
            int c = ccol + wn + nt * 8 + 2 * t;
            if (Cb0) {
                float v0 = acc[mt][nt][0], v1 = acc[mt][nt][1];
                float v2 = acc[mt][nt][2], v3 = acc[mt][nt][3];
                unsigned u;
                PK_BF2(u, v0, v1);                               *(unsigned*)(Cb0 + r0 * Dq + c) = u;
                PK_BF2(u, v0 - bf_round(v0), v1 - bf_round(v1)); *(unsigned*)(Cb1 + r0 * Dq + c) = u;
                PK_BF2(u, v2, v3);                               *(unsigned*)(Cb0 + (r0 + 8) * Dq + c) = u;
                PK_BF2(u, v2 - bf_round(v2), v3 - bf_round(v3)); *(unsigned*)(Cb1 + (r0 + 8) * Dq + c) = u;
            } else {
                float b0 = bias[c], b1 = bias[c + 1];
                *(float2*)(Cf + r0 * Dq + c) =
                    make_float2(acc[mt][nt][0] + b0, acc[mt][nt][1] + b1);
                *(float2*)(Cf + (r0 + 8) * Dq + c) =
                    make_float2(acc[mt][nt][2] + b0, acc[mt][nt][3] + b1);
            }
        }
    }
#undef PREFB
}

__global__ __launch_bounds__(256, 2) void qkv_gemm_p()
{
    int w = blockIdx.x >> 3, colBlk = blockIdx.x & 7;
    __nv_bfloat16* C0 = (w == 0) ? g_qb0 : (w == 1) ? g_kb0 : g_vb0;
    __nv_bfloat16* C1 = (w == 0) ? g_qb1 : (w == 1) ? g_kb1 : g_vb1;
    gemm_pipe_bf(g_xb0, g_xb1,
                 g_wtb + (size_t)(w * 2) * PLW, g_wtb + (size_t)(w * 2 + 1) * PLW,
                 C0, C1, nullptr, nullptr, blockIdx.y, colBlk);
}

__global__ __launch_bounds__(256, 2) void out_proj_p(const float* __restrict__ bo,
                                                     float* __restrict__ out)
{
    gemm_pipe_bf(g_ab0, g_ab1,
                 g_wtb + (size_t)6 * PLW, g_wtb + (size_t)7 * PLW,
                 nullptr, nullptr, out, bo, blockIdx.y, blockIdx.x);
}

// ---------------------------------------------------------------------------
// bf16x3 flash attention, BR=64 / 4 warps, target 3 CTAs/SM.
// ALiBi row-term dropped (softmax shift-invariant); causal mask only on the
// diagonal tile. Q fragments persistent; 2-stage K/V ring.
// ---------------------------------------------------------------------------
#define VRB 144
#define FL_PL 9216
#define FL_STG_SZ (4 * FL_PL) // 36864
#define FL_SMEM (2 * FL_STG_SZ)   // 73728

__global__ __launch_bounds__(128, 3) void flash_bf()
{
    extern __shared__ char smc[];
    const unsigned smb = (unsigned)__cvta_generic_to_shared(smc);
    const int tid = threadIdx.x, wid = tid >> 5, lane = tid & 31;
    const int g = lane >> 2, t = lane & 3;
    const int quad = lane >> 3, lrow = lane & 7;
    const int it = (int)gridDim.x - 1 - (int)blockIdx.x;   // heavy tiles first
    const int i0 = it * 64;
    const int h = blockIdx.y, b = blockIdx.z;
    const float slope_l2 = exp2f(-0.5f * (float)(h + 1)) * 1.44269504f;
    const float sscale   = 0.125f * 1.44269504f;

    const unsigned lmoff = (unsigned)(((quad & 1) * 8 + lrow) * VRB + (quad >> 1) * 16);
    const unsigned vrow  = (unsigned)(lane & 15);
    const unsigned vc16  = (unsigned)(lane >> 4) * 16;

#define FL_LOAD_TILE(j0_, sbase_)                                              \
    {                                                                          \
        size_t kb_ = ((size_t)(b * Nq + (j0_)) * Hq + h) * DHq;                \
        _Pragma("unroll")                                                      \
        for (int itr_ = 0; itr_ < 4; itr_++) {                                 \
            int idx_ = itr_ * 128 + tid;                                       \
            int row_ = idx_ >> 3, ch_ = idx_ & 7;                              \
            size_t src_ = kb_ + (size_t)row_ * HDq + ch_ * 8;                  \
            unsigned so_ = (unsigned)(row_ * VRB + ch_ * 16);                  \
            CP_A16((sbase_) + 0 * FL_PL + so_, g_kb0 + src_);                  \
            CP_A16((sbase_) + 1 * FL_PL + so_, g_kb1 + src_);                  \
            CP_A16((sbase_) + 2 * FL_PL + so_, g_vb0 + src_);                  \
            CP_A16((sbase_) + 3 * FL_PL + so_, g_vb1 + src_);                  \
        }                                                                      \
    }

    // ---- prologue: stage Q[64][64] through stage-0 smem, extract fragments ----
    unsigned qf0[4][4], qf1[4][4];
    {
        size_t qb = ((size_t)(b * Nq + i0) * Hq + h) * DHq;
#pragma unroll
        for (int itr = 0; itr < 4; itr++) {
            int idx = itr * 128 + tid;
            int row = idx >> 3, ch = idx & 7;
            size_t src = qb + (size_t)row * HDq + ch * 8;
            CP_A16(smb + (unsigned)(row * VRB + ch * 16), g_qb0 + src);
            CP_A16(smb + (unsigned)FL_PL + (unsigned)(row * VRB + ch * 16), g_qb1 + src);
        }
        CP_COMMIT();
        CP_WAIT0();
        __syncthreads();
#pragma unroll
        for (int kt = 0; kt < 4; kt++) {
            unsigned qo = smb + (unsigned)(wid * 16) * VRB + lmoff + kt * 32;
            LDSM_X4(qf0[kt][0], qf0[kt][1], qf0[kt][2], qf0[kt][3], qo);
            LDSM_X4(qf1[kt][0], qf1[kt][1], qf1[kt][2], qf1[kt][3], qo + FL_PL);
        }
        __syncthreads();   // Q reads done before K/V pipeline reuses stage 0
    }

    float o[8][4] = {};
    float m0 = -1e30f, m1 = -1e30f, l0 = 0.f, l1 = 0.f;

    const int njt = it + 1;

    FL_LOAD_TILE(0, smb);
    CP_COMMIT();

    for (int jt = 0; jt < njt; jt++) {
        const int j0 = jt * 64;

        if (jt + 1 < njt) {
            FL_LOAD_TILE(j0 + 64, smb + (unsigned)(((jt + 1) & 1) * FL_STG_SZ));
            CP_COMMIT();
            CP_WAIT1();
        } else {
            CP_WAIT0();
        }
        __syncthreads();

        const unsigned kstg = smb + (unsigned)((jt & 1) * FL_STG_SZ);

        // ---- S = Q @ K^T ----
        float s[8][4] = {};
#pragma unroll
        for (int kt = 0; kt < 4; kt++) {
            unsigned kb0[4][4], kb1[4][4];
#pragma unroll
            for (int grp = 0; grp < 4; grp++) {
                unsigned ko = kstg + (unsigned)(grp * 16) * VRB + lmoff + kt * 32;
                LDSM_X4(kb0[grp][0], kb0[grp][1], kb0[grp][2], kb0[grp][3], ko);
                LDSM_X4(kb1[grp][0], kb1[grp][1], kb1[grp][2], kb1[grp][3], ko + FL_PL);
            }
#pragma unroll
            for (int nt = 0; nt < 8; nt++)
                MMA_BF16(s[nt], qf0[kt], kb0[nt >> 1][nt & 1], kb0[nt >> 1][(nt & 1) + 2]);
#pragma unroll
            for (int nt = 0; nt < 8; nt++)
                MMA_BF16(s[nt], qf1[kt], kb0[nt >> 1][nt & 1], kb0[nt >> 1][(nt & 1) + 2]);
#pragma unroll
            for (int nt = 0; nt < 8; nt++)
                MMA_BF16(s[nt], qf0[kt], kb1[nt >> 1][nt & 1], kb1[nt >> 1][(nt & 1) + 2]);
        }

        // ---- scale + ALiBi(-slope*j only; row term cancels in softmax) ----
        float bj[16];
#pragma unroll
        for (int c8 = 0; c8 < 16; c8++)
            bj[c8] = -slope_l2 * (float)(j0 + (c8 >> 1) * 8 + 2 * t + (c8 & 1));
#pragma unroll
        for (int nt = 0; nt < 8; nt++)
#pragma unroll
            for (int e = 0; e < 4; e++)
                s[nt][e] = fmaf(s[nt][e], sscale, bj[nt * 2 + (e & 1)]);

        // causal mask: only the diagonal tile (jt == njt-1) has jg > ig cases
        if (jt == njt - 1) {
            const int ig0 = i0 + wid * 16 + g;
#pragma unroll
            for (int nt = 0; nt < 8; nt++)
#pragma unroll
                for (int e = 0; e < 4; e++) {
                    int jg = j0 + nt * 8 + 2 * t + (e & 1);
                    int ig = ig0 + ((e & 2) ? 8 : 0);
                    if (jg > ig) s[nt][e] = -1e30f;
                }
        }

        // ---- row stats ----
        float rmax0 = -1e30f, rmax1 = -1e30f;
#pragma unroll
        for (int nt = 0; nt < 8; nt++) {
            rmax0 = fmaxf(rmax0, fmaxf(s[nt][0], s[nt][1]));
            rmax1 = fmaxf(rmax1, fmaxf(s[nt][2], s[nt][3]));
        }
        rmax0 = fmaxf(rmax0, __shfl_xor_sync(0xffffffffu, rmax0, 1));
        rmax0 = fmaxf(rmax0, __shfl_xor_sync(0xffffffffu, rmax0, 2));
        rmax1 = fmaxf(rmax1, __shfl_xor_sync(0xffffffffu, rmax1, 1));
        rmax1 = fmaxf(rmax1, __shfl_xor_sync(0xffffffffu, rmax1, 2));
        float mn0 = fmaxf(m0, rmax0), mn1 = fmaxf(m1, rmax1);
        float f0 = ex2(m0 - mn0), f1 = ex2(m1 - mn1);
        m0 = mn0; m1 = mn1;

        float rs0 = 0.f, rs1 = 0.f;
#pragma unroll
        for (int nt = 0; nt < 8; nt++) {
            float p0_ = ex2(s[nt][0] - mn0), p1_ = ex2(s[nt][1] - mn0);
            float p2_ = ex2(s[nt][2] - mn1), p3_ = ex2(s[nt][3] - mn1);
            s[nt][0] = p0_; s[nt][1] = p1_; s[nt][2] = p2_; s[nt][3] = p3_;
            rs0 += p0_ + p1_; rs1 += p2_ + p3_;
        }
        rs0 += __shfl_xor_sync(0xffffffffu, rs0, 1);
        rs0 += __shfl_xor_sync(0xffffffffu, rs0, 2);
        rs1 += __shfl_xor_sync(0xffffffffu, rs1, 1);
        rs1 += __shfl_xor_sync(0xffffffffu, rs1, 2);
        l0 = l0 * f0 + rs0;
        l1 = l1 * f1 + rs1;
#pragma unroll
        for (int nt = 0; nt < 8; nt++) {
            o[nt][0] *= f0; o[nt][1] *= f0;
            o[nt][2] *= f1; o[nt][3] *= f1;
        }

        // ---- O += P @ V ----
#pragma unroll
        for (int kt = 0; kt < 4; kt++) {
            unsigned p0[4], p1[4];
            {
                float c0 = s[2 * kt][0],     c1 = s[2 * kt][1];
                float c2 = s[2 * kt][2],     c3 = s[2 * kt][3];
                float d0 = s[2 * kt + 1][0], d1 = s[2 * kt + 1][1];
                float d2 = s[2 * kt + 1][2], d3 = s[2 * kt + 1][3];
                PK_BF2(p0[0], c0, c1); PK_BF2(p0[1], c2, c3);
                PK_BF2(p0[2], d0, d1); PK_BF2(p0[3], d2, d3);
                PK_BF2(p1[0], c0 - bf_round(c0), c1 - bf_round(c1));
                PK_BF2(p1[1], c2 - bf_round(c2), c3 - bf_round(c3));
                PK_BF2(p1[2], d0 - bf_round(d0), d1 - bf_round(d1));
                PK_BF2(p1[3], d2 - bf_round(d2), d3 - bf_round(d3));
            }
            unsigned vb0[4][4], vb1[4][4];
#pragma unroll
            for (int dg = 0; dg < 4; dg++) {
                unsigned vo = kstg + 2 * FL_PL +
                              (unsigned)((kt * 16 + vrow) * VRB) + (unsigned)(dg * 32) + vc16;
                LDSM_T_X4(vb0[dg][0], vb0[dg][1], vb0[dg][2], vb0[dg][3], vo);
                LDSM_T_X4(vb1[dg][0], vb1[dg][1], vb1[dg][2], vb1[dg][3], vo + FL_PL);
            }
#pragma unroll
            for (int nt = 0; nt < 8; nt++)
                MMA_BF16(o[nt], p0, vb0[nt >> 1][(nt & 1) * 2], vb0[nt >> 1][(nt & 1) * 2 + 1]);
#pragma unroll
            for (int nt = 0; nt < 8; nt++)
                MMA_BF16(o[nt], p1, vb0[nt >> 1][(nt & 1) * 2], vb0[nt >> 1][(nt & 1) * 2 + 1]);
#pragma unroll
            for (int nt = 0; nt < 8; nt++)
                MMA_BF16(o[nt], p0, vb1[nt >> 1][(nt & 1) * 2], vb1[nt >> 1][(nt & 1) * 2 + 1]);
        }
        __syncthreads();   // all reads of stage (jt&1) done before it is refilled
    }

    // ---- normalize + write bf16 split planes ----
    float inv0 = 1.f / l0, inv1 = 1.f / l1;
    const int ig0 = i0 + wid * 16 + g;
#pragma unroll
    for (int nt = 0; nt < 8; nt++) {
        int d = nt * 8 + 2 * t;
        size_t idx0 = ((size_t)(b * Nq + ig0) * Hq + h) * DHq + d;
        size_t idx1 = idx0 + (size_t)8 * HDq;
        float v0 = o[nt][0] * inv0, v1 = o[nt][1] * inv0;
        float v2 = o[nt][2] * inv1, v3 = o[nt][3] * inv1;
        unsigned u;
        PK_BF2(u, v0, v1);                               *(unsigned*)(g_ab0 + idx0) = u;
        PK_BF2(u, v0 - bf_round(v0), v1 - bf_round(v1)); *(unsigned*)(g_ab1 + idx0) = u;
        PK_BF2(u, v2, v3);                               *(unsigned*)(g_ab0 + idx1) = u;
        PK_BF2(u, v2 - bf_round(v2), v3 - bf_round(v3)); *(unsigned*)(g_ab1 + idx1) = u;
    }
#undef FL_LOAD_TILE
}

// ---------------------------------------------------------------------------
extern "C" void kernel_launch(void* const* d_in, const int* in_sizes, int n_in,
                              void* d_out, int out_size)
{
    (void)in_sizes; (void)n_in; (void)out_size;
    const float* x  = (const float*)d_in[0];
    const float* Wq = (const float*)d_in[1];
    const float* Wk = (const float*)d_in[2];
    const float* Wv = (const float*)d_in[3];
    const float* Wo = (const float*)d_in[4];
    const float* bo = (const float*)d_in[5];
    float* out = (float*)d_out;

    cudaFuncSetAttribute(qkv_gemm_p, cudaFuncAttributeMaxDynamicSharedMemorySize, GEMMP_SMEM);
    cudaFuncSetAttribute(out_proj_p, cudaFuncAttributeMaxDynamicSharedMemorySize, GEMMP_SMEM);
    cudaFuncSetAttribute(flash_bf,   cudaFuncAttributeMaxDynamicSharedMemorySize, FL_SMEM);

    split_x_b<<<Mq * Dq / 4 / 256, 256>>>(x);
    split_wT_all<<<dim3(16, 16, 4), 256>>>(Wq, Wk, Wv, Wo);

    qkv_gemm_p<<<dim3(24, 32), 256, GEMMP_SMEM>>>();
    flash_bf<<<dim3(32, Hq, Bq), 128, FL_SMEM>>>();
    out_proj_p<<<dim3(8, 32), 256, GEMMP_SMEM>>>(bo, out);
}

// round 15
// speedup vs baseline: 1.9789x; 1.0451x over previous
#include <cuda_runtime.h>
#include <cuda_bf16.h>
#include <cuda_fp16.h>

#define Bq 2
#define Nq 2048
#define Hq 16
#define DHq 64
#define Dq 1024
#define HDq (Hq * DHq)   // 1024
#define Mq (Bq * Nq)     // 4096

#define PLX ((size_t)Mq * Dq)
#define PLW ((size_t)Dq * Dq)
#define PLA ((size_t)Mq * HDq)

// bf16 split planes
__device__ __nv_bfloat16 g_xb0[PLX], g_xb1[PLX];
__device__ __nv_bfloat16 g_wtb[8 * PLW];          // 4 weights x 2 planes, transposed [n][k]
__device__ __nv_bfloat16 g_qb0[PLA], g_qb1[PLA];
__device__ __nv_bfloat16 g_kb0[PLA], g_kb1[PLA];
__device__ __half        g_vh0[PLA], g_vh1[PLA];  // V planes in fp16 (for fp16 PV path)
__device__ __nv_bfloat16 g_ab0[PLA], g_ab1[PLA];

// ---------------------------------------------------------------------------
// helpers
// ---------------------------------------------------------------------------
__device__ __forceinline__ float bf_round(float x)
{
    return __bfloat162float(__float2bfloat16(x));
}

__device__ __forceinline__ float hf_round(float x)
{
    return __half2float(__float2half_rn(x));
}

__device__ __forceinline__ float ex2(float x)
{
    float r;
    asm("ex2.approx.f32 %0, %1;" : "=f"(r) : "f"(x));
    return r;
}

#define PK_BF2(d, a, b) \
    asm("cvt.rn.bf16x2.f32 %0, %1, %2;" : "=r"(d) : "f"(b), "f"(a))
#define PK_HF2(d, a, b) \
    asm("cvt.rn.f16x2.f32 %0, %1, %2;" : "=r"(d) : "f"(b), "f"(a))

#define MMA_BF16(d, a, b0_, b1_)                                              \
    asm volatile("mma.sync.aligned.m16n8k16.row.col.f32.bf16.bf16.f32 "       \
                 "{%0,%1,%2,%3}, {%4,%5,%6,%7}, {%8,%9}, {%0,%1,%2,%3};"      \
                 : "+f"(d[0]), "+f"(d[1]), "+f"(d[2]), "+f"(d[3])             \
                 : "r"(a[0]), "r"(a[1]), "r"(a[2]), "r"(a[3]),                \
                   "r"(b0_), "r"(b1_))

#define MMA_F16(d, a, b0_, b1_)                                               \
    asm volatile("mma.sync.aligned.m16n8k16.row.col.f32.f16.f16.f32 "         \
                 "{%0,%1,%2,%3}, {%4,%5,%6,%7}, {%8,%9}, {%0,%1,%2,%3};"      \
                 : "+f"(d[0]), "+f"(d[1]), "+f"(d[2]), "+f"(d[3])             \
                 : "r"(a[0]), "r"(a[1]), "r"(a[2]), "r"(a[3]),                \
                   "r"(b0_), "r"(b1_))

#define LDSM_X4(r0, r1, r2, r3, addr)                                         \
    asm volatile("ldmatrix.sync.aligned.m8n8.x4.shared.b16 {%0,%1,%2,%3}, [%4];" \
                 : "=r"(r0), "=r"(r1), "=r"(r2), "=r"(r3) : "r"(addr))

#define LDSM_T_X4(r0, r1, r2, r3, addr)                                       \
    asm volatile("ldmatrix.sync.aligned.m8n8.x4.trans.shared.b16 {%0,%1,%2,%3}, [%4];" \
                 : "=r"(r0), "=r"(r1), "=r"(r2), "=r"(r3) : "r"(addr))

#define CP_A16(dst, src) \
    asm volatile("cp.async.cg.shared.global [%0], [%1], 16;" :: "r"(dst), "l"(src))
#define CP_COMMIT() asm volatile("cp.async.commit_group;")
#define CP_WAIT0()  asm volatile("cp.async.wait_group 0;" ::: "memory")
#define CP_WAIT1()  asm volatile("cp.async.wait_group 1;" ::: "memory")

// ---------------------------------------------------------------------------
// split kernels
// ---------------------------------------------------------------------------
__global__ __launch_bounds__(256) void split_x_b(const float* __restrict__ in)
{
    size_t i = (size_t)blockIdx.x * 256 + threadIdx.x;   // over float4
    float4 v = ((const float4*)in)[i];
    float h0 = bf_round(v.x), h1 = bf_round(v.y), h2 = bf_round(v.z), h3 = bf_round(v.w);
    unsigned u;
    PK_BF2(u, h0, h1);                 *(unsigned*)(g_xb0 + i * 4)     = u;
    PK_BF2(u, h2, h3);                 *(unsigned*)(g_xb0 + i * 4 + 2) = u;
    PK_BF2(u, v.x - h0, v.y - h1);     *(unsigned*)(g_xb1 + i * 4)     = u;
    PK_BF2(u, v.z - h2, v.w - h3);     *(unsigned*)(g_xb1 + i * 4 + 2) = u;
}

// all 4 weights in one launch: transpose + split via smem tile
__global__ __launch_bounds__(256) void split_wT_all(const float* __restrict__ Wq,
                                                    const float* __restrict__ Wk,
                                                    const float* __restrict__ Wv,
                                                    const float* __restrict__ Wo)
{
    __shared__ float ts[64][68];
    const int w = blockIdx.z;
    const float* W = (w == 0) ? Wq : (w == 1) ? Wk : (w == 2) ? Wv : Wo;
    const int tid = threadIdx.x;
    const int n0 = blockIdx.x * 64, k0 = blockIdx.y * 64;

#pragma unroll
    for (int i = 0; i < 4; i++) {
        int idx = i * 256 + tid;
        int kr = idx >> 4, c4 = idx & 15;
        float4 v = *(const float4*)(W + (size_t)(k0 + kr) * Dq + n0 + c4 * 4);
        ts[c4 * 4 + 0][kr] = v.x;
        ts[c4 * 4 + 1][kr] = v.y;
        ts[c4 * 4 + 2][kr] = v.z;
        ts[c4 * 4 + 3][kr] = v.w;
    }
    __syncthreads();

    const int n = tid >> 2, kc = (tid & 3) * 16;
    unsigned u0[8], u1[8];
#pragma unroll
    for (int j = 0; j < 8; j++) {
        float v0 = ts[n][kc + 2 * j], v1 = ts[n][kc + 2 * j + 1];
        float h0 = bf_round(v0), h1 = bf_round(v1);
        PK_BF2(u0[j], h0, h1);
        PK_BF2(u1[j], v0 - h0, v1 - h1);
    }
    __nv_bfloat16* d0 = g_wtb + (size_t)(w * 2 + 0) * PLW + (size_t)(n0 + n) * Dq + k0 + kc;
    __nv_bfloat16* d1 = g_wtb + (size_t)(w * 2 + 1) * PLW + (size_t)(n0 + n) * Dq + k0 + kc;
    *(uint4*)(d0)     = make_uint4(u0[0], u0[1], u0[2], u0[3]);
    *(uint4*)(d0 + 8) = make_uint4(u0[4], u0[5], u0[6], u0[7]);
    *(uint4*)(d1)     = make_uint4(u1[0], u1[1], u1[2], u1[3]);
    *(uint4*)(d1 + 8) = make_uint4(u1[4], u1[5], u1[6], u1[7]);
}

// ---------------------------------------------------------------------------
// bf16x3 m16n8k16 GEMM, BK=32, 2-stage cp.async (R10, proven).
// Epilogues: bf16 planes (Cb0) / fp16 planes (Ch0) / fp32 + bias (Cf).
// ---------------------------------------------------------------------------
#define TPL 10240
#define STAGE_B 40960
#define GEMMP_SMEM (2 * STAGE_B)   // 81920

__device__ __forceinline__ void gemm_pipe_bf(const __nv_bfloat16* __restrict__ Ab0,
                                             const __nv_bfloat16* __restrict__ Ab1,
                                             const __nv_bfloat16* __restrict__ Wb0,
                                             const __nv_bfloat16* __restrict__ Wb1,
                                             __nv_bfloat16* __restrict__ Cb0,
                                             __nv_bfloat16* __restrict__ Cb1,
                                             __half* __restrict__ Ch0,
                                             __half* __restrict__ Ch1,
                                             float* __restrict__ Cf,
                                             const float* __restrict__ bias,
                                             int rowBlk, int colBlk)
{
    extern __shared__ float sm[];
    const unsigned smb = (unsigned)__cvta_generic_to_shared(sm);
    const int tid = threadIdx.x;
    const int wid = tid >> 5, lane = tid & 31;
    const int g = lane >> 2, t = lane & 3;
    const int wm = (wid & 3) * 32, wn = (wid >> 2) * 64;

    const size_t arow = (size_t)rowBlk * 128;
    const int ccol = colBlk * 128;

    const int quad = lane >> 3, lrow = lane & 7;
    const unsigned lmoff = (unsigned)(((quad & 1) * 8 + lrow) * 80 + (quad >> 1) * 16);

    float acc[2][8][4] = {};

#define PREFB(st, k0)                                                          \
    {                                                                          \
        unsigned base = smb + (st) * STAGE_B;                                  \
        _Pragma("unroll")                                                      \
        for (int i_ = 0; i_ < 2; i_++) {                                       \
            int idx = tid * 2 + i_;                                            \
            int r = idx >> 2, c4 = idx & 3;                                    \
            unsigned so = (unsigned)(r * 80 + c4 * 16);                        \
            CP_A16(base + 0 * TPL + so, Ab0 + (arow + r) * Dq + (k0) + c4 * 8);\
            CP_A16(base + 1 * TPL + so, Ab1 + (arow + r) * Dq + (k0) + c4 * 8);\
            CP_A16(base + 2 * TPL + so, Wb0 + (size_t)(ccol + r) * Dq + (k0) + c4 * 8); \
            CP_A16(base + 3 * TPL + so, Wb1 + (size_t)(ccol + r) * Dq + (k0) + c4 * 8); \
        }                                                                      \
    }

    PREFB(0, 0);
    CP_COMMIT();

    const int nch = Dq / 32;   // 32
    for (int chn = 0; chn < nch; chn++) {
        if (chn + 1 < nch) {
            PREFB((chn + 1) & 1, (chn + 1) * 32);
            CP_COMMIT();
            CP_WAIT1();
        } else {
            CP_WAIT0();
        }
        __syncthreads();

        const unsigned stg = smb + (chn & 1) * STAGE_B;

#pragma unroll
        for (int half = 0; half < 2; half++) {
            const unsigned co = (unsigned)(half * 32);
            unsigned af0[2][4], af1[2][4];
#pragma unroll
            for (int mt = 0; mt < 2; mt++) {
                unsigned ao = stg + (unsigned)((wm + mt * 16) * 80) + lmoff + co;
                LDSM_X4(af0[mt][0], af0[mt][1], af0[mt][2], af0[mt][3], ao);
                LDSM_X4(af1[mt][0], af1[mt][1], af1[mt][2], af1[mt][3], ao + TPL);
            }
            unsigned bf0[4][4], bf1[4][4];
#pragma unroll
            for (int np = 0; np < 4; np++) {
                unsigned wo = stg + 2 * TPL + (unsigned)((wn + np * 16) * 80) + lmoff + co;
                LDSM_X4(bf0[np][0], bf0[np][1], bf0[np][2], bf0[np][3], wo);
                LDSM_X4(bf1[np][0], bf1[np][1], bf1[np][2], bf1[np][3], wo + TPL);
            }
#pragma unroll
            for (int mt = 0; mt < 2; mt++)
#pragma unroll
                for (int nt = 0; nt < 8; nt++)
                    MMA_BF16(acc[mt][nt], af0[mt], bf0[nt >> 1][nt & 1], bf0[nt >> 1][(nt & 1) + 2]);
#pragma unroll
            for (int mt = 0; mt < 2; mt++)
#pragma unroll
                for (int nt = 0; nt < 8; nt++)
                    MMA_BF16(acc[mt][nt], af1[mt], bf0[nt >> 1][nt & 1], bf0[nt >> 1][(nt & 1) + 2]);
#pragma unroll
            for (int mt = 0; mt < 2; mt++)
#pragma unroll
                for (int nt = 0; nt < 8; nt++)
                    MMA_BF16(acc[mt][nt], af0[mt], bf1[nt >> 1][nt & 1], bf1[nt >> 1][(nt & 1) + 2]);
        }
        __syncthreads();
    }

#pragma unroll
    for (int mt = 0; mt < 2; mt++) {
        size_t r0 = arow + wm + mt * 16 + g;
#pragma unroll
        for (int nt = 0; nt < 8; nt++) {
            int c = ccol + wn + nt * 8 + 2 * t;
            float v0 = acc[mt][nt][0], v1 = acc[mt][nt][1];
            float v2 = acc[mt][nt][2], v3 = acc[mt][nt][3];
            if (Ch0) {
                float h0 = hf_round(v0), h1 = hf_round(v1);
                float h2 = hf_round(v2), h3 = hf_round(v3);
                unsigned u;
                PK_HF2(u, h0, h1);           *(unsigned*)(Ch0 + r0 * Dq + c) = u;
                PK_HF2(u, v0 - h0, v1 - h1); *(unsigned*)(Ch1 + r0 * Dq + c) = u;
                PK_HF2(u, h2, h3);           *(unsigned*)(Ch0 + (r0 + 8) * Dq + c) = u;
                PK_HF2(u, v2 - h2, v3 - h3); *(unsigned*)(Ch1 + (r0 + 8) * Dq + c) = u;
            } else if (Cb0) {
                float h0 = bf_round(v0), h1 = bf_round(v1);
                float h2 = bf_round(v2), h3 = bf_round(v3);
                unsigned u;
                PK_BF2(u, h0, h1);           *(unsigned*)(Cb0 + r0 * Dq + c) = u;
                PK_BF2(u, v0 - h0, v1 - h1); *(unsigned*)(Cb1 + r0 * Dq + c) = u;
                PK_BF2(u, h2, h3);           *(unsigned*)(Cb0 + (r0 + 8) * Dq + c) = u;
                PK_BF2(u, v2 - h2, v3 - h3); *(unsigned*)(Cb1 + (r0 + 8) * Dq + c) = u;
            } else {
                float b0 = bias[c], b1 = bias[c + 1];
                *(float2*)(Cf + r0 * Dq + c)       = make_float2(v0 + b0, v1 + b1);
                *(float2*)(Cf + (r0 + 8) * Dq + c) = make_float2(v2 + b0, v3 + b1);
            }
        }
    }
#undef PREFB
}

__global__ __launch_bounds__(256, 2) void qkv_gemm_p()
{
    int w = blockIdx.x >> 3, colBlk = blockIdx.x & 7;
    __nv_bfloat16* C0 = (w == 0) ? g_qb0 : (w == 1) ? g_kb0 : nullptr;
    __nv_bfloat16* C1 = (w == 0) ? g_qb1 : (w == 1) ? g_kb1 : nullptr;
    __half* H0 = (w == 2) ? g_vh0 : nullptr;
    __half* H1 = (w == 2) ? g_vh1 : nullptr;
    gemm_pipe_bf(g_xb0, g_xb1,
                 g_wtb + (size_t)(w * 2) * PLW, g_wtb + (size_t)(w * 2 + 1) * PLW,
                 C0, C1, H0, H1, nullptr, nullptr, blockIdx.y, colBlk);
}

__global__ __launch_bounds__(256, 2) void out_proj_p(const float* __restrict__ bo,
                                                     float* __restrict__ out)
{
    gemm_pipe_bf(g_ab0, g_ab1,
                 g_wtb + (size_t)6 * PLW, g_wtb + (size_t)7 * PLW,
                 nullptr, nullptr, nullptr, nullptr, out, bo, blockIdx.y, blockIdx.x);
}

// ---------------------------------------------------------------------------
// flash attention: S in bf16x3, P single fp16, V fp16 x2 (PV = 2 passes).
// BR=64 / 4 warps; Q frags persistent; 2-stage K/V ring; diag-only causal.
// ---------------------------------------------------------------------------
#define VRB 144
#define FL_PL 9216
#define FL_STG_SZ (4 * FL_PL) // 36864
#define FL_SMEM (2 * FL_STG_SZ)   // 73728

__global__ __launch_bounds__(128, 3) void flash_bf()
{
    extern __shared__ char smc[];
    const unsigned smb = (unsigned)__cvta_generic_to_shared(smc);
    const int tid = threadIdx.x, wid = tid >> 5, lane = tid & 31;
    const int g = lane >> 2, t = lane & 3;
    const int quad = lane >> 3, lrow = lane & 7;
    const int it = (int)gridDim.x - 1 - (int)blockIdx.x;   // heavy tiles first
    const int i0 = it * 64;
    const int h = blockIdx.y, b = blockIdx.z;
    const float slope_l2 = exp2f(-0.5f * (float)(h + 1)) * 1.44269504f;
    const float sscale   = 0.125f * 1.44269504f;

    const unsigned lmoff = (unsigned)(((quad & 1) * 8 + lrow) * VRB + (quad >> 1) * 16);
    const unsigned vrow  = (unsigned)(lane & 15);
    const unsigned vc16  = (unsigned)(lane >> 4) * 16;

#define FL_LOAD_TILE(j0_, sbase_)                                              \
    {                                                                          \
        size_t kb_ = ((size_t)(b * Nq + (j0_)) * Hq + h) * DHq;                \
        _Pragma("unroll")                                                      \
        for (int itr_ = 0; itr_ < 4; itr_++) {                                 \
            int idx_ = itr_ * 128 + tid;                                       \
            int row_ = idx_ >> 3, ch_ = idx_ & 7;                              \
            size_t src_ = kb_ + (size_t)row_ * HDq + ch_ * 8;                  \
            unsigned so_ = (unsigned)(row_ * VRB + ch_ * 16);                  \
            CP_A16((sbase_) + 0 * FL_PL + so_, g_kb0 + src_);                  \
            CP_A16((sbase_) + 1 * FL_PL + so_, g_kb1 + src_);                  \
            CP_A16((sbase_) + 2 * FL_PL + so_, g_vh0 + src_);                  \
            CP_A16((sbase_) + 3 * FL_PL + so_, g_vh1 + src_);                  \
        }                                                                      \
    }

    // ---- prologue: stage Q[64][64] through stage-0 smem, extract fragments ----
    unsigned qf0[4][4], qf1[4][4];
    {
        size_t qb = ((size_t)(b * Nq + i0) * Hq + h) * DHq;
#pragma unroll
        for (int itr = 0; itr < 4; itr++) {
            int idx = itr * 128 + tid;
            int row = idx >> 3, ch = idx & 7;
            size_t src = qb + (size_t)row * HDq + ch * 8;
            CP_A16(smb + (unsigned)(row * VRB + ch * 16), g_qb0 + src);
            CP_A16(smb + (unsigned)FL_PL + (unsigned)(row * VRB + ch * 16), g_qb1 + src);
        }
        CP_COMMIT();
        CP_WAIT0();
        __syncthreads();
#pragma unroll
        for (int kt = 0; kt < 4; kt++) {
            unsigned qo = smb + (unsigned)(wid * 16) * VRB + lmoff + kt * 32;
            LDSM_X4(qf0[kt][0], qf0[kt][1], qf0[kt][2], qf0[kt][3], qo);
            LDSM_X4(qf1[kt][0], qf1[kt][1], qf1[kt][2], qf1[kt][3], qo + FL_PL);
        }
        __syncthreads();   // Q reads done before K/V pipeline reuses stage 0
    }

    float o[8][4] = {};
    float m0 = -1e30f, m1 = -1e30f, l0 = 0.f, l1 = 0.f;

    const int njt = it + 1;

    FL_LOAD_TILE(0, smb);
    CP_COMMIT();

    for (int jt = 0; jt < njt; jt++) {
        const int j0 = jt * 64;

        if (jt + 1 < njt) {
            FL_LOAD_TILE(j0 + 64, smb + (unsigned)(((jt + 1) & 1) * FL_STG_SZ));
            CP_COMMIT();
            CP_WAIT1();
        } else {
            CP_WAIT0();
        }
        __syncthreads();

        const unsigned kstg = smb + (unsigned)((jt & 1) * FL_STG_SZ);

        // ---- S = Q @ K^T (bf16x3) ----
        float s[8][4] = {};
#pragma unroll
        for (int kt = 0; kt < 4; kt++) {
            unsigned kb0[4][4], kb1[4][4];
#pragma unroll
            for (int grp = 0; grp < 4; grp++) {
                unsigned ko = kstg + (unsigned)(grp * 16) * VRB + lmoff + kt * 32;
                LDSM_X4(kb0[grp][0], kb0[grp][1], kb0[grp][2], kb0[grp][3], ko);
                LDSM_X4(kb1[grp][0], kb1[grp][1], kb1[grp][2], kb1[grp][3], ko + FL_PL);
            }
#pragma unroll
            for (int nt = 0; nt < 8; nt++)
                MMA_BF16(s[nt], qf0[kt], kb0[nt >> 1][nt & 1], kb0[nt >> 1][(nt & 1) + 2]);
#pragma unroll
            for (int nt = 0; nt < 8; nt++)
                MMA_BF16(s[nt], qf1[kt], kb0[nt >> 1][nt & 1], kb0[nt >> 1][(nt & 1) + 2]);
#pragma unroll
            for (int nt = 0; nt < 8; nt++)
                MMA_BF16(s[nt], qf0[kt], kb1[nt >> 1][nt & 1], kb1[nt >> 1][(nt & 1) + 2]);
        }

        // ---- scale + ALiBi(-slope*j only; row term cancels in softmax) ----
        float bj[16];
#pragma unroll
        for (int c8 = 0; c8 < 16; c8++)
            bj[c8] = -slope_l2 * (float)(j0 + (c8 >> 1) * 8 + 2 * t + (c8 & 1));
#pragma unroll
        for (int nt = 0; nt < 8; nt++)
#pragma unroll
            for (int e = 0; e < 4; e++)
                s[nt][e] = fmaf(s[nt][e], sscale, bj[nt * 2 + (e & 1)]);

        if (jt == njt - 1) {   // causal: only the diagonal tile masks
            const int ig0 = i0 + wid * 16 + g;
#pragma unroll
            for (int nt = 0; nt < 8; nt++)
#pragma unroll
                for (int e = 0; e < 4; e++) {
                    int jg = j0 + nt * 8 + 2 * t + (e & 1);
                    int ig = ig0 + ((e & 2) ? 8 : 0);
                    if (jg > ig) s[nt][e] = -1e30f;
                }
        }

        // ---- row stats ----
        float rmax0 = -1e30f, rmax1 = -1e30f;
#pragma unroll
        for (int nt = 0; nt < 8; nt++) {
            rmax0 = fmaxf(rmax0, fmaxf(s[nt][0], s[nt][1]));
            rmax1 = fmaxf(rmax1, fmaxf(s[nt][2], s[nt][3]));
        }
        rmax0 = fmaxf(rmax0, __shfl_xor_sync(0xffffffffu, rmax0, 1));
        rmax0 = fmaxf(rmax0, __shfl_xor_sync(0xffffffffu, rmax0, 2));
        rmax1 = fmaxf(rmax1, __shfl_xor_sync(0xffffffffu, rmax1, 1));
        rmax1 = fmaxf(rmax1, __shfl_xor_sync(0xffffffffu, rmax1, 2));
        float mn0 = fmaxf(m0, rmax0), mn1 = fmaxf(m1, rmax1);
        float f0 = ex2(m0 - mn0), f1 = ex2(m1 - mn1);
        m0 = mn0; m1 = mn1;

        float rs0 = 0.f, rs1 = 0.f;
#pragma unroll
        for (int nt = 0; nt < 8; nt++) {
            float p0_ = ex2(s[nt][0] - mn0), p1_ = ex2(s[nt][1] - mn0);
            float p2_ = ex2(s[nt][2] - mn1), p3_ = ex2(s[nt][3] - mn1);
            s[nt][0] = p0_; s[nt][1] = p1_; s[nt][2] = p2_; s[nt][3] = p3_;
            rs0 += p0_ + p1_; rs1 += p2_ + p3_;
        }
        rs0 += __shfl_xor_sync(0xffffffffu, rs0, 1);
        rs0 += __shfl_xor_sync(0xffffffffu, rs0, 2);
        rs1 += __shfl_xor_sync(0xffffffffu, rs1, 1);
        rs1 += __shfl_xor_sync(0xffffffffu, rs1, 2);
        l0 = l0 * f0 + rs0;
        l1 = l1 * f1 + rs1;
#pragma unroll
        for (int nt = 0; nt < 8; nt++) {
            o[nt][0] *= f0; o[nt][1] *= f0;
            o[nt][2] *= f1; o[nt][3] *= f1;
        }

        // ---- O += P @ V : P single fp16 (in regs), V fp16 x2 planes ----
#pragma unroll
        for (int kt = 0; kt < 4; kt++) {
            unsigned p0[4];
            PK_HF2(p0[0], s[2 * kt][0],     s[2 * kt][1]);
            PK_HF2(p0[1], s[2 * kt][2],     s[2 * kt][3]);
            PK_HF2(p0[2], s[2 * kt + 1][0], s[2 * kt + 1][1]);
            PK_HF2(p0[3], s[2 * kt + 1][2], s[2 * kt + 1][3]);

            unsigned vb0[4][4], vb1[4][4];
#pragma unroll
            for (int dg = 0; dg < 4; dg++) {
                unsigned vo = kstg + 2 * FL_PL +
                              (unsigned)((kt * 16 + vrow) * VRB) + (unsigned)(dg * 32) + vc16;
                LDSM_T_X4(vb0[dg][0], vb0[dg][1], vb0[dg][2], vb0[dg][3], vo);
                LDSM_T_X4(vb1[dg][0], vb1[dg][1], vb1[dg][2], vb1[dg][3], vo + FL_PL);
            }
#pragma unroll
            for (int nt = 0; nt < 8; nt++)
                MMA_F16(o[nt], p0, vb0[nt >> 1][(nt & 1) * 2], vb0[nt >> 1][(nt & 1) * 2 + 1]);
#pragma unroll
            for (int nt = 0; nt < 8; nt++)
                MMA_F16(o[nt], p0, vb1[nt >> 1][(nt & 1) * 2], vb1[nt >> 1][(nt & 1) * 2 + 1]);
        }
        __syncthreads();   // all reads of stage (jt&1) done before it is refilled
    }

    // ---- normalize + write bf16 split planes ----
    float inv0 = 1.f / l0, inv1 = 1.f / l1;
    const int ig0 = i0 + wid * 16 + g;
#pragma unroll
    for (int nt = 0; nt < 8; nt++) {
        int d = nt * 8 + 2 * t;
        size_t idx0 = ((size_t)(b * Nq + ig0) * Hq + h) * DHq + d;
        size_t idx1 = idx0 + (size_t)8 * HDq;
        float v0 = o[nt][0] * inv0, v1 = o[nt][1] * inv0;
        float v2 = o[nt][2] * inv1, v3 = o[nt][3] * inv1;
        float h0 = bf_round(v0), h1 = bf_round(v1);
        float h2 = bf_round(v2), h3 = bf_round(v3);
        unsigned u;
        PK_BF2(u, h0, h1);           *(unsigned*)(g_ab0 + idx0) = u;
        PK_BF2(u, v0 - h0, v1 - h1); *(unsigned*)(g_ab1 + idx0) = u;
        PK_BF2(u, h2, h3);           *(unsigned*)(g_ab0 + idx1) = u;
        PK_BF2(u, v2 - h2, v3 - h3); *(unsigned*)(g_ab1 + idx1) = u;
    }
#undef FL_LOAD_TILE
}

// ---------------------------------------------------------------------------
extern "C" void kernel_launch(void* const* d_in, const int* in_sizes, int n_in,
                              void* d_out, int out_size)
{
    (void)in_sizes; (void)n_in; (void)out_size;
    const float* x  = (const float*)d_in[0];
    const float* Wq = (const float*)d_in[1];
    const float* Wk = (const float*)d_in[2];
    const float* Wv = (const float*)d_in[3];
    const float* Wo = (const float*)d_in[4];
    const float* bo = (const float*)d_in[5];
    float* out = (float*)d_out;

    cudaFuncSetAttribute(qkv_gemm_p, cudaFuncAttributeMaxDynamicSharedMemorySize, GEMMP_SMEM);
    cudaFuncSetAttribute(out_proj_p, cudaFuncAttributeMaxDynamicSharedMemorySize, GEMMP_SMEM);
    cudaFuncSetAttribute(flash_bf,   cudaFuncAttributeMaxDynamicSharedMemorySize, FL_SMEM);

    split_x_b<<<Mq * Dq / 4 / 256, 256>>>(x);
    split_wT_all<<<dim3(16, 16, 4), 256>>>(Wq, Wk, Wv, Wo);

    qkv_gemm_p<<<dim3(24, 32), 256, GEMMP_SMEM>>>();
    flash_bf<<<dim3(32, Hq, Bq), 128, FL_SMEM>>>();
    out_proj_p<<<dim3(8, 32), 256, GEMMP_SMEM>>>(bo, out);
}